// round 1
// baseline (speedup 1.0000x reference)
#include <cuda_runtime.h>
#include <cstdint>

// Fixed problem shapes
#define Bb 2
#define Nn 2048
#define Dd 1024
#define Hh 16
#define HD 64
#define BN_ROWS (Bb * Nn)          // 4096
#define QKV_COLS (3 * Dd)          // 3072

// Scratch (device globals: allocation-guard safe)
__device__ float g_qkv[BN_ROWS * QKV_COLS];   // [B*N, 3D]  ~50 MB
__device__ float g_ctx[BN_ROWS * Dd];         // [B*N, D]   ~17 MB

// ---------------------------------------------------------------------------
// NT GEMM: C[M,Nc] = A[M,K] * B[Nc,K]^T + bias[Nc]
// BM=BN=64, BK=16, 256 threads, 4x4 micro-tile.
// ---------------------------------------------------------------------------
template <int BM, int BN, int BK>
__global__ __launch_bounds__(256)
void gemm_nt(const float* __restrict__ A, const float* __restrict__ B,
             const float* __restrict__ bias, float* __restrict__ C,
             int M, int Nc, int K) {
    __shared__ float As[BK][BM];
    __shared__ float Bs[BK][BN];

    const int tid = threadIdx.x;
    const int tx = tid & 15;        // 0..15 -> col group
    const int ty = tid >> 4;        // 0..15 -> row group
    const int row0 = blockIdx.y * BM;
    const int col0 = blockIdx.x * BN;

    float acc[4][4] = {};

    const int lr = tid >> 2;        // 0..63: tile row this thread loads
    const int lk = (tid & 3) * 4;   // 0,4,8,12: k-offset (float4)

    for (int k0 = 0; k0 < K; k0 += BK) {
        // Load A tile (BM x BK) and B tile (BN x BK), store k-major in smem
        float4 va = *reinterpret_cast<const float4*>(&A[(size_t)(row0 + lr) * K + k0 + lk]);
        float4 vb = *reinterpret_cast<const float4*>(&B[(size_t)(col0 + lr) * K + k0 + lk]);
        As[lk + 0][lr] = va.x; As[lk + 1][lr] = va.y;
        As[lk + 2][lr] = va.z; As[lk + 3][lr] = va.w;
        Bs[lk + 0][lr] = vb.x; Bs[lk + 1][lr] = vb.y;
        Bs[lk + 2][lr] = vb.z; Bs[lk + 3][lr] = vb.w;
        __syncthreads();

#pragma unroll
        for (int kk = 0; kk < BK; kk++) {
            float4 a4 = *reinterpret_cast<const float4*>(&As[kk][ty * 4]);
            float4 b4 = *reinterpret_cast<const float4*>(&Bs[kk][tx * 4]);
            float a[4] = {a4.x, a4.y, a4.z, a4.w};
            float b[4] = {b4.x, b4.y, b4.z, b4.w};
#pragma unroll
            for (int i = 0; i < 4; i++)
#pragma unroll
                for (int j = 0; j < 4; j++)
                    acc[i][j] += a[i] * b[j];
        }
        __syncthreads();
    }

#pragma unroll
    for (int i = 0; i < 4; i++) {
        const int r = row0 + ty * 4 + i;
        float4 o;
        const int c = col0 + tx * 4;
        o.x = acc[i][0] + bias[c + 0];
        o.y = acc[i][1] + bias[c + 1];
        o.z = acc[i][2] + bias[c + 2];
        o.w = acc[i][3] + bias[c + 3];
        *reinterpret_cast<float4*>(&C[(size_t)r * Nc + c]) = o;
    }
}

// ---------------------------------------------------------------------------
// Flash-style attention with recency bias.
// grid: (N/64, H, B); block: 64 threads. Each thread owns one query row.
// ---------------------------------------------------------------------------
__global__ __launch_bounds__(64)
void attn_kernel(const float* __restrict__ qkv,
                 const int* __restrict__ t_idx,
                 const unsigned char* __restrict__ mask,
                 const float* __restrict__ alpha,
                 float* __restrict__ ctx) {
    const int qt = blockIdx.x, h = blockIdx.y, b = blockIdx.z;
    const int tid = threadIdx.x;
    const int qrow = qt * 64 + tid;

    __shared__ float Ks[64][68];   // padded: conflict-free STS.128
    __shared__ float Vs[64][68];
    __shared__ int   tks[64];

    const float a_h = alpha[h];
    const float scale = 0.125f;    // 1/sqrt(64)

    // Load and pre-scale this thread's query row
    float q[64];
    const float* qptr = qkv + ((size_t)(b * Nn + qrow)) * QKV_COLS + h * HD;
#pragma unroll
    for (int d4 = 0; d4 < 16; d4++) {
        float4 v = *reinterpret_cast<const float4*>(qptr + d4 * 4);
        q[d4 * 4 + 0] = v.x * scale;
        q[d4 * 4 + 1] = v.y * scale;
        q[d4 * 4 + 2] = v.z * scale;
        q[d4 * 4 + 3] = v.w * scale;
    }
    const int t_q = t_idx[b * Nn + qrow];
    const unsigned char* mrow_base = mask + ((size_t)(b * Nn + qrow)) * Nn;

    float acc[64];
#pragma unroll
    for (int d = 0; d < 64; d++) acc[d] = 0.0f;
    float m = -1e30f, l = 0.0f;

    const float* kbase = qkv + ((size_t)(b * Nn)) * QKV_COLS + Dd + h * HD;
    const float* vbase = kbase + Dd;

    for (int k0 = 0; k0 < Nn; k0 += 64) {
        // Stage K/V tile (each thread loads one row) + key time indices
        {
            const float* kr = kbase + (size_t)(k0 + tid) * QKV_COLS;
            const float* vr = vbase + (size_t)(k0 + tid) * QKV_COLS;
#pragma unroll
            for (int d4 = 0; d4 < 16; d4++) {
                *reinterpret_cast<float4*>(&Ks[tid][d4 * 4]) =
                    *reinterpret_cast<const float4*>(kr + d4 * 4);
                *reinterpret_cast<float4*>(&Vs[tid][d4 * 4]) =
                    *reinterpret_cast<const float4*>(vr + d4 * 4);
            }
            tks[tid] = t_idx[b * Nn + k0 + tid];
        }
        __syncthreads();

        // Check the 64-byte mask chunk for this (q, tile)
        const uint4* m16 = reinterpret_cast<const uint4*>(mrow_base + k0);
        uint4 ma = m16[0], mb = m16[1], mc = m16[2], md = m16[3];
        unsigned any = ma.x | ma.y | ma.z | ma.w | mb.x | mb.y | mb.z | mb.w |
                       mc.x | mc.y | mc.z | mc.w | md.x | md.y | md.z | md.w;

        if (any == 0) {
            // Fast path: no masked keys in this tile
            for (int j = 0; j < 64; j++) {
                float s = 0.0f;
#pragma unroll
                for (int d4 = 0; d4 < 16; d4++) {
                    float4 kv = *reinterpret_cast<const float4*>(&Ks[j][d4 * 4]);
                    s += q[d4 * 4 + 0] * kv.x;
                    s += q[d4 * 4 + 1] * kv.y;
                    s += q[d4 * 4 + 2] * kv.z;
                    s += q[d4 * 4 + 3] * kv.w;
                }
                const int dt = t_q - tks[j];
                if (dt > 0) s -= a_h * (float)dt;

                if (s <= m) {
                    const float p = __expf(s - m);
                    l += p;
#pragma unroll
                    for (int d4 = 0; d4 < 16; d4++) {
                        float4 vv = *reinterpret_cast<const float4*>(&Vs[j][d4 * 4]);
                        acc[d4 * 4 + 0] += p * vv.x;
                        acc[d4 * 4 + 1] += p * vv.y;
                        acc[d4 * 4 + 2] += p * vv.z;
                        acc[d4 * 4 + 3] += p * vv.w;
                    }
                } else {
                    const float corr = __expf(m - s);
                    m = s;
                    l = l * corr + 1.0f;
#pragma unroll
                    for (int d4 = 0; d4 < 16; d4++) {
                        float4 vv = *reinterpret_cast<const float4*>(&Vs[j][d4 * 4]);
                        acc[d4 * 4 + 0] = acc[d4 * 4 + 0] * corr + vv.x;
                        acc[d4 * 4 + 1] = acc[d4 * 4 + 1] * corr + vv.y;
                        acc[d4 * 4 + 2] = acc[d4 * 4 + 2] * corr + vv.z;
                        acc[d4 * 4 + 3] = acc[d4 * 4 + 3] * corr + vv.w;
                    }
                }
            }
        } else {
            // Slow path: per-key mask check
            const unsigned char* mrow = mrow_base + k0;
            for (int j = 0; j < 64; j++) {
                if (mrow[j]) continue;
                float s = 0.0f;
#pragma unroll
                for (int d4 = 0; d4 < 16; d4++) {
                    float4 kv = *reinterpret_cast<const float4*>(&Ks[j][d4 * 4]);
                    s += q[d4 * 4 + 0] * kv.x;
                    s += q[d4 * 4 + 1] * kv.y;
                    s += q[d4 * 4 + 2] * kv.z;
                    s += q[d4 * 4 + 3] * kv.w;
                }
                const int dt = t_q - tks[j];
                if (dt > 0) s -= a_h * (float)dt;

                if (s <= m) {
                    const float p = __expf(s - m);
                    l += p;
#pragma unroll
                    for (int d = 0; d < 64; d++) acc[d] += p * Vs[j][d];
                } else {
                    const float corr = __expf(m - s);
                    m = s;
                    l = l * corr + 1.0f;
#pragma unroll
                    for (int d = 0; d < 64; d++) acc[d] = acc[d] * corr + Vs[j][d];
                }
            }
        }
        __syncthreads();
    }

    // Normalize and write ctx[b, qrow, h*64 + d]
    const float inv = (l > 0.0f) ? (1.0f / l) : 0.0f;
    float* cptr = ctx + ((size_t)(b * Nn + qrow)) * Dd + h * HD;
#pragma unroll
    for (int d4 = 0; d4 < 16; d4++) {
        float4 o;
        o.x = acc[d4 * 4 + 0] * inv;
        o.y = acc[d4 * 4 + 1] * inv;
        o.z = acc[d4 * 4 + 2] * inv;
        o.w = acc[d4 * 4 + 3] * inv;
        *reinterpret_cast<float4*>(cptr + d4 * 4) = o;
    }
}

// ---------------------------------------------------------------------------
extern "C" void kernel_launch(void* const* d_in, const int* in_sizes, int n_in,
                              void* d_out, int out_size) {
    const float*         X     = (const float*)d_in[0];
    const int*           t_idx = (const int*)d_in[1];
    const unsigned char* mask  = (const unsigned char*)d_in[2];
    const float*         Wqkv  = (const float*)d_in[3];
    const float*         bqkv  = (const float*)d_in[4];
    const float*         Wo    = (const float*)d_in[5];
    const float*         bo    = (const float*)d_in[6];
    const float*         alpha = (const float*)d_in[7];
    float*               out   = (float*)d_out;

    void* qkv_p = nullptr;
    void* ctx_p = nullptr;
    cudaGetSymbolAddress(&qkv_p, g_qkv);
    cudaGetSymbolAddress(&ctx_p, g_ctx);
    float* qkv = (float*)qkv_p;
    float* ctx = (float*)ctx_p;

    // 1) QKV projection: [4096,1024] x [3072,1024]^T -> [4096,3072]
    {
        dim3 grid(QKV_COLS / 64, BN_ROWS / 64);
        gemm_nt<64, 64, 16><<<grid, 256>>>(X, Wqkv, bqkv, qkv,
                                           BN_ROWS, QKV_COLS, Dd);
    }

    // 2) Attention -> ctx [B,N,D]
    {
        dim3 grid(Nn / 64, Hh, Bb);
        attn_kernel<<<grid, 64>>>(qkv, t_idx, mask, alpha, ctx);
    }

    // 3) Output projection: [4096,1024] x [1024,1024]^T -> [4096,1024]
    {
        dim3 grid(Dd / 64, BN_ROWS / 64);
        gemm_nt<64, 64, 16><<<grid, 256>>>(ctx, Wo, bo, out,
                                           BN_ROWS, Dd, Dd);
    }
}

// round 2
// speedup vs baseline: 1.2877x; 1.2877x over previous
#include <cuda_runtime.h>
#include <cstdint>

// Fixed problem shapes
#define Bb 2
#define Nn 2048
#define Dd 1024
#define Hh 16
#define HD 64
#define BN_ROWS (Bb * Nn)          // 4096
#define QKV_COLS (3 * Dd)          // 3072

// Scratch (device globals: allocation-guard safe)
__device__ float g_qkv[BN_ROWS * QKV_COLS];   // [B*N, 3D]  ~50 MB
__device__ float g_ctx[BN_ROWS * Dd];         // [B*N, D]   ~17 MB

// ---------------------------------------------------------------------------
// NT GEMM: C[M,Nc] = A[M,K] * B[Nc,K]^T + bias[Nc]
// BM=BN=64, BK=16, 256 threads, 4x4 micro-tile. (~90% of fp32 FFMA ceiling)
// ---------------------------------------------------------------------------
template <int BM, int BN, int BK>
__global__ __launch_bounds__(256)
void gemm_nt(const float* __restrict__ A, const float* __restrict__ B,
             const float* __restrict__ bias, float* __restrict__ C,
             int M, int Nc, int K) {
    __shared__ float As[BK][BM];
    __shared__ float Bs[BK][BN];

    const int tid = threadIdx.x;
    const int tx = tid & 15;        // 0..15 -> col group
    const int ty = tid >> 4;        // 0..15 -> row group
    const int row0 = blockIdx.y * BM;
    const int col0 = blockIdx.x * BN;

    float acc[4][4] = {};

    const int lr = tid >> 2;        // 0..63: tile row this thread loads
    const int lk = (tid & 3) * 4;   // 0,4,8,12: k-offset (float4)

    for (int k0 = 0; k0 < K; k0 += BK) {
        float4 va = *reinterpret_cast<const float4*>(&A[(size_t)(row0 + lr) * K + k0 + lk]);
        float4 vb = *reinterpret_cast<const float4*>(&B[(size_t)(col0 + lr) * K + k0 + lk]);
        As[lk + 0][lr] = va.x; As[lk + 1][lr] = va.y;
        As[lk + 2][lr] = va.z; As[lk + 3][lr] = va.w;
        Bs[lk + 0][lr] = vb.x; Bs[lk + 1][lr] = vb.y;
        Bs[lk + 2][lr] = vb.z; Bs[lk + 3][lr] = vb.w;
        __syncthreads();

#pragma unroll
        for (int kk = 0; kk < BK; kk++) {
            float4 a4 = *reinterpret_cast<const float4*>(&As[kk][ty * 4]);
            float4 b4 = *reinterpret_cast<const float4*>(&Bs[kk][tx * 4]);
            float a[4] = {a4.x, a4.y, a4.z, a4.w};
            float b[4] = {b4.x, b4.y, b4.z, b4.w};
#pragma unroll
            for (int i = 0; i < 4; i++)
#pragma unroll
                for (int j = 0; j < 4; j++)
                    acc[i][j] += a[i] * b[j];
        }
        __syncthreads();
    }

#pragma unroll
    for (int i = 0; i < 4; i++) {
        const int r = row0 + ty * 4 + i;
        float4 o;
        const int c = col0 + tx * 4;
        o.x = acc[i][0] + bias[c + 0];
        o.y = acc[i][1] + bias[c + 1];
        o.z = acc[i][2] + bias[c + 2];
        o.w = acc[i][3] + bias[c + 3];
        *reinterpret_cast<float4*>(&C[(size_t)r * Nc + c]) = o;
    }
}

// ---------------------------------------------------------------------------
// Flash-style attention with recency bias. BRANCH-FREE softmax:
// scores are bounded (|q.k/8| << 20, bias <= 0), so exp() without a running
// max is safe in fp32, and softmax is shift-invariant -> identical result.
// grid: (N/64, H, B); block: 64 threads. Each thread owns one query row.
// ---------------------------------------------------------------------------
__global__ __launch_bounds__(64)
void attn_kernel(const float* __restrict__ qkv,
                 const int* __restrict__ t_idx,
                 const unsigned char* __restrict__ mask,
                 const float* __restrict__ alpha,
                 float* __restrict__ ctx) {
    const int qt = blockIdx.x, h = blockIdx.y, b = blockIdx.z;
    const int tid = threadIdx.x;
    const int qrow = qt * 64 + tid;

    __shared__ float Ks[64][68];   // padded: conflict-free STS.128
    __shared__ float Vs[64][68];
    __shared__ int   tks[64];

    const float a_h = alpha[h];
    const float scale = 0.125f;    // 1/sqrt(64)

    // Load and pre-scale this thread's query row
    float q[64];
    const float* qptr = qkv + ((size_t)(b * Nn + qrow)) * QKV_COLS + h * HD;
#pragma unroll
    for (int d4 = 0; d4 < 16; d4++) {
        float4 v = *reinterpret_cast<const float4*>(qptr + d4 * 4);
        q[d4 * 4 + 0] = v.x * scale;
        q[d4 * 4 + 1] = v.y * scale;
        q[d4 * 4 + 2] = v.z * scale;
        q[d4 * 4 + 3] = v.w * scale;
    }
    const float t_qf = (float)t_idx[b * Nn + qrow];
    const unsigned char* mrow_base = mask + ((size_t)(b * Nn + qrow)) * Nn;

    float acc[64];
#pragma unroll
    for (int d = 0; d < 64; d++) acc[d] = 0.0f;
    float l = 0.0f;

    const float* kbase = qkv + ((size_t)(b * Nn)) * QKV_COLS + Dd + h * HD;
    const float* vbase = kbase + Dd;

    for (int k0 = 0; k0 < Nn; k0 += 64) {
        // Stage K/V tile (each thread loads one row) + key time indices
        {
            const float* kr = kbase + (size_t)(k0 + tid) * QKV_COLS;
            const float* vr = vbase + (size_t)(k0 + tid) * QKV_COLS;
#pragma unroll
            for (int d4 = 0; d4 < 16; d4++) {
                *reinterpret_cast<float4*>(&Ks[tid][d4 * 4]) =
                    *reinterpret_cast<const float4*>(kr + d4 * 4);
                *reinterpret_cast<float4*>(&Vs[tid][d4 * 4]) =
                    *reinterpret_cast<const float4*>(vr + d4 * 4);
            }
            tks[tid] = t_idx[b * Nn + k0 + tid];
        }
        __syncthreads();

        // Check the 64-byte mask chunk for this (q, tile)
        const uint4* m16 = reinterpret_cast<const uint4*>(mrow_base + k0);
        uint4 ma = m16[0], mb = m16[1], mc = m16[2], md = m16[3];
        unsigned any = ma.x | ma.y | ma.z | ma.w | mb.x | mb.y | mb.z | mb.w |
                       mc.x | mc.y | mc.z | mc.w | md.x | md.y | md.z | md.w;

        if (any == 0) {
            // Fast path: no masked keys; fully branch-free inner loop
#pragma unroll 2
            for (int j = 0; j < 64; j++) {
                float s0 = 0.f, s1 = 0.f, s2 = 0.f, s3 = 0.f;
#pragma unroll
                for (int d4 = 0; d4 < 16; d4 += 4) {
                    float4 k0v = *reinterpret_cast<const float4*>(&Ks[j][(d4 + 0) * 4]);
                    float4 k1v = *reinterpret_cast<const float4*>(&Ks[j][(d4 + 1) * 4]);
                    float4 k2v = *reinterpret_cast<const float4*>(&Ks[j][(d4 + 2) * 4]);
                    float4 k3v = *reinterpret_cast<const float4*>(&Ks[j][(d4 + 3) * 4]);
                    s0 += q[(d4 + 0) * 4 + 0] * k0v.x + q[(d4 + 0) * 4 + 1] * k0v.y
                        + q[(d4 + 0) * 4 + 2] * k0v.z + q[(d4 + 0) * 4 + 3] * k0v.w;
                    s1 += q[(d4 + 1) * 4 + 0] * k1v.x + q[(d4 + 1) * 4 + 1] * k1v.y
                        + q[(d4 + 1) * 4 + 2] * k1v.z + q[(d4 + 1) * 4 + 3] * k1v.w;
                    s2 += q[(d4 + 2) * 4 + 0] * k2v.x + q[(d4 + 2) * 4 + 1] * k2v.y
                        + q[(d4 + 2) * 4 + 2] * k2v.z + q[(d4 + 2) * 4 + 3] * k2v.w;
                    s3 += q[(d4 + 3) * 4 + 0] * k3v.x + q[(d4 + 3) * 4 + 1] * k3v.y
                        + q[(d4 + 3) * 4 + 2] * k3v.z + q[(d4 + 3) * 4 + 3] * k3v.w;
                }
                float s = (s0 + s1) + (s2 + s3);
                // recency bias: -a_h * max(t_q - t_k, 0)
                s -= a_h * fmaxf(t_qf - (float)tks[j], 0.0f);
                const float p = __expf(s);
                l += p;
#pragma unroll
                for (int d4 = 0; d4 < 16; d4++) {
                    float4 vv = *reinterpret_cast<const float4*>(&Vs[j][d4 * 4]);
                    acc[d4 * 4 + 0] += p * vv.x;
                    acc[d4 * 4 + 1] += p * vv.y;
                    acc[d4 * 4 + 2] += p * vv.z;
                    acc[d4 * 4 + 3] += p * vv.w;
                }
            }
        } else {
            // Slow path: per-key mask; masked keys contribute exactly 0 (p=0)
            const unsigned char* mrow = mrow_base + k0;
            for (int j = 0; j < 64; j++) {
                float s0 = 0.f, s1 = 0.f, s2 = 0.f, s3 = 0.f;
#pragma unroll
                for (int d4 = 0; d4 < 16; d4 += 4) {
                    float4 k0v = *reinterpret_cast<const float4*>(&Ks[j][(d4 + 0) * 4]);
                    float4 k1v = *reinterpret_cast<const float4*>(&Ks[j][(d4 + 1) * 4]);
                    float4 k2v = *reinterpret_cast<const float4*>(&Ks[j][(d4 + 2) * 4]);
                    float4 k3v = *reinterpret_cast<const float4*>(&Ks[j][(d4 + 3) * 4]);
                    s0 += q[(d4 + 0) * 4 + 0] * k0v.x + q[(d4 + 0) * 4 + 1] * k0v.y
                        + q[(d4 + 0) * 4 + 2] * k0v.z + q[(d4 + 0) * 4 + 3] * k0v.w;
                    s1 += q[(d4 + 1) * 4 + 0] * k1v.x + q[(d4 + 1) * 4 + 1] * k1v.y
                        + q[(d4 + 1) * 4 + 2] * k1v.z + q[(d4 + 1) * 4 + 3] * k1v.w;
                    s2 += q[(d4 + 2) * 4 + 0] * k2v.x + q[(d4 + 2) * 4 + 1] * k2v.y
                        + q[(d4 + 2) * 4 + 2] * k2v.z + q[(d4 + 2) * 4 + 3] * k2v.w;
                    s3 += q[(d4 + 3) * 4 + 0] * k3v.x + q[(d4 + 3) * 4 + 1] * k3v.y
                        + q[(d4 + 3) * 4 + 2] * k3v.z + q[(d4 + 3) * 4 + 3] * k3v.w;
                }
                float s = (s0 + s1) + (s2 + s3);
                s -= a_h * fmaxf(t_qf - (float)tks[j], 0.0f);
                float p = __expf(s);
                p = mrow[j] ? 0.0f : p;   // masked -> zero weight (selp, no branch)
                l += p;
#pragma unroll
                for (int d4 = 0; d4 < 16; d4++) {
                    float4 vv = *reinterpret_cast<const float4*>(&Vs[j][d4 * 4]);
                    acc[d4 * 4 + 0] += p * vv.x;
                    acc[d4 * 4 + 1] += p * vv.y;
                    acc[d4 * 4 + 2] += p * vv.z;
                    acc[d4 * 4 + 3] += p * vv.w;
                }
            }
        }
        __syncthreads();
    }

    // Normalize and write ctx[b, qrow, h*64 + d]
    const float inv = (l > 0.0f) ? (1.0f / l) : 0.0f;
    float* cptr = ctx + ((size_t)(b * Nn + qrow)) * Dd + h * HD;
#pragma unroll
    for (int d4 = 0; d4 < 16; d4++) {
        float4 o;
        o.x = acc[d4 * 4 + 0] * inv;
        o.y = acc[d4 * 4 + 1] * inv;
        o.z = acc[d4 * 4 + 2] * inv;
        o.w = acc[d4 * 4 + 3] * inv;
        *reinterpret_cast<float4*>(cptr + d4 * 4) = o;
    }
}

// ---------------------------------------------------------------------------
extern "C" void kernel_launch(void* const* d_in, const int* in_sizes, int n_in,
                              void* d_out, int out_size) {
    const float*         X     = (const float*)d_in[0];
    const int*           t_idx = (const int*)d_in[1];
    const unsigned char* mask  = (const unsigned char*)d_in[2];
    const float*         Wqkv  = (const float*)d_in[3];
    const float*         bqkv  = (const float*)d_in[4];
    const float*         Wo    = (const float*)d_in[5];
    const float*         bo    = (const float*)d_in[6];
    const float*         alpha = (const float*)d_in[7];
    float*               out   = (float*)d_out;

    void* qkv_p = nullptr;
    void* ctx_p = nullptr;
    cudaGetSymbolAddress(&qkv_p, g_qkv);
    cudaGetSymbolAddress(&ctx_p, g_ctx);
    float* qkv = (float*)qkv_p;
    float* ctx = (float*)ctx_p;

    // 1) QKV projection: [4096,1024] x [3072,1024]^T -> [4096,3072]
    {
        dim3 grid(QKV_COLS / 64, BN_ROWS / 64);
        gemm_nt<64, 64, 16><<<grid, 256>>>(X, Wqkv, bqkv, qkv,
                                           BN_ROWS, QKV_COLS, Dd);
    }

    // 2) Attention -> ctx [B,N,D]
    {
        dim3 grid(Nn / 64, Hh, Bb);
        attn_kernel<<<grid, 64>>>(qkv, t_idx, mask, alpha, ctx);
    }

    // 3) Output projection: [4096,1024] x [1024,1024]^T -> [4096,1024]
    {
        dim3 grid(Dd / 64, BN_ROWS / 64);
        gemm_nt<64, 64, 16><<<grid, 256>>>(ctx, Wo, bo, out,
                                           BN_ROWS, Dd, Dd);
    }
}

// round 4
// speedup vs baseline: 1.7958x; 1.3946x over previous
#include <cuda_runtime.h>
#include <cuda_bf16.h>
#include <cstdint>

// Fixed problem shapes
#define Bb 2
#define Nn 2048
#define Dd 1024
#define Hh 16
#define HD 64
#define BN_ROWS 4096
#define QKV_COLS 3072

// Scratch (device globals: allocation-guard safe)
__device__ float g_qkv[BN_ROWS * QKV_COLS];   // [B*N, 3D]
__device__ float g_ctx[BN_ROWS * Dd];         // [B*N, D]

// ---------------------------------------------------------------------------
// mma.sync helpers (baseline ISA — no 'a' features; HMMA fallback on sm_103)
// ---------------------------------------------------------------------------
__device__ __forceinline__ uint32_t smem_u32(const void* p) {
    uint32_t a;
    asm("{ .reg .u64 t; cvta.to.shared.u64 t, %1; cvt.u32.u64 %0, t; }" : "=r"(a) : "l"(p));
    return a;
}

#define LDSM_X4(r0, r1, r2, r3, addr) \
    asm volatile("ldmatrix.sync.aligned.m8n8.x4.shared.b16 {%0,%1,%2,%3}, [%4];" \
                 : "=r"(r0), "=r"(r1), "=r"(r2), "=r"(r3) : "r"(addr))

#define MMA_BF16(d, a, b0, b1) \
    asm volatile("mma.sync.aligned.m16n8k16.row.col.f32.bf16.bf16.f32 " \
                 "{%0,%1,%2,%3},{%4,%5,%6,%7},{%8,%9},{%0,%1,%2,%3};" \
                 : "+f"((d)[0]), "+f"((d)[1]), "+f"((d)[2]), "+f"((d)[3]) \
                 : "r"((a)[0]), "r"((a)[1]), "r"((a)[2]), "r"((a)[3]), \
                   "r"(b0), "r"(b1))

// ---------------------------------------------------------------------------
// bf16x3 tensor-core GEMM: C[M,Nc] = A[M,K]*B[Nc,K]^T + bias
// 128x128 block tile, BK=32, 256 threads (8 warps, 4m x 2n), warp tile 32x64.
// Split: v = hi(bf16) + lo(bf16); D = Ah*Bh + Ah*Bl + Al*Bh (fp32 accum).
// ---------------------------------------------------------------------------
#define BKROW 40   // padded row stride in bf16 (80B): conflict-free ldmatrix

__global__ __launch_bounds__(256)
void gemm_bf16x3(const float* __restrict__ A, const float* __restrict__ B,
                 const float* __restrict__ bias, float* __restrict__ C,
                 int Nc, int K) {
    __shared__ __nv_bfloat16 sAh[128][BKROW];
    __shared__ __nv_bfloat16 sAl[128][BKROW];
    __shared__ __nv_bfloat16 sBh[128][BKROW];
    __shared__ __nv_bfloat16 sBl[128][BKROW];

    const int tid = threadIdx.x;
    const int row0 = blockIdx.y * 128;
    const int col0 = blockIdx.x * 128;

    const int warp = tid >> 5;
    const int lane = tid & 31;
    const int wm = warp & 3;            // m block: 32 rows
    const int wn = warp >> 2;           // n block: 64 cols

    // ldmatrix per-lane byte offsets (row stride 80B)
    const int quad = lane >> 3, r8 = lane & 7;
    const uint32_t offA = (uint32_t)(((quad & 1) * 8 + r8) * 80 + ((quad >> 1) * 8) * 2);
    const uint32_t offB = (uint32_t)(((quad >> 1) * 8 + r8) * 80 + ((quad & 1) * 8) * 2);

    const uint32_t aHiB = smem_u32(&sAh[0][0]) + (uint32_t)(wm * 32 * 80) + offA;
    const uint32_t aLoB = smem_u32(&sAl[0][0]) + (uint32_t)(wm * 32 * 80) + offA;
    const uint32_t bHiB = smem_u32(&sBh[0][0]) + (uint32_t)(wn * 64 * 80) + offB;
    const uint32_t bLoB = smem_u32(&sBl[0][0]) + (uint32_t)(wn * 64 * 80) + offB;

    float acc[2][8][4];
#pragma unroll
    for (int mt = 0; mt < 2; mt++)
#pragma unroll
        for (int j = 0; j < 8; j++)
#pragma unroll
            for (int e = 0; e < 4; e++) acc[mt][j][e] = 0.0f;

    const int nk = K >> 5;
    for (int ks = 0; ks < nk; ks++) {
        const int k0 = ks * 32;
        // ---- load + split + store (each thread: 4 float4 of A, 4 of B) ----
#pragma unroll
        for (int p = 0; p < 4; p++) {
            const int idx = p * 256 + tid;
            const int row = idx >> 3;
            const int c4 = (idx & 7) * 4;
            float4 va = *reinterpret_cast<const float4*>(&A[(size_t)(row0 + row) * K + k0 + c4]);
            float4 vb = *reinterpret_cast<const float4*>(&B[(size_t)(col0 + row) * K + k0 + c4]);

            __nv_bfloat16 hx = __float2bfloat16_rn(va.x), hy = __float2bfloat16_rn(va.y),
                          hz = __float2bfloat16_rn(va.z), hw = __float2bfloat16_rn(va.w);
            __nv_bfloat162 h01; h01.x = hx; h01.y = hy;
            __nv_bfloat162 h23; h23.x = hz; h23.y = hw;
            *reinterpret_cast<__nv_bfloat162*>(&sAh[row][c4]) = h01;
            *reinterpret_cast<__nv_bfloat162*>(&sAh[row][c4 + 2]) = h23;
            __nv_bfloat162 l01, l23;
            l01.x = __float2bfloat16_rn(va.x - __bfloat162float(hx));
            l01.y = __float2bfloat16_rn(va.y - __bfloat162float(hy));
            l23.x = __float2bfloat16_rn(va.z - __bfloat162float(hz));
            l23.y = __float2bfloat16_rn(va.w - __bfloat162float(hw));
            *reinterpret_cast<__nv_bfloat162*>(&sAl[row][c4]) = l01;
            *reinterpret_cast<__nv_bfloat162*>(&sAl[row][c4 + 2]) = l23;

            hx = __float2bfloat16_rn(vb.x); hy = __float2bfloat16_rn(vb.y);
            hz = __float2bfloat16_rn(vb.z); hw = __float2bfloat16_rn(vb.w);
            h01.x = hx; h01.y = hy; h23.x = hz; h23.y = hw;
            *reinterpret_cast<__nv_bfloat162*>(&sBh[row][c4]) = h01;
            *reinterpret_cast<__nv_bfloat162*>(&sBh[row][c4 + 2]) = h23;
            l01.x = __float2bfloat16_rn(vb.x - __bfloat162float(hx));
            l01.y = __float2bfloat16_rn(vb.y - __bfloat162float(hy));
            l23.x = __float2bfloat16_rn(vb.z - __bfloat162float(hz));
            l23.y = __float2bfloat16_rn(vb.w - __bfloat162float(hw));
            *reinterpret_cast<__nv_bfloat162*>(&sBl[row][c4]) = l01;
            *reinterpret_cast<__nv_bfloat162*>(&sBl[row][c4 + 2]) = l23;
        }
        __syncthreads();

        // ---- compute: 2 k-chunks of 16 ----
#pragma unroll
        for (int kc = 0; kc < 2; kc++) {
            const uint32_t kadd = (uint32_t)(kc * 32);  // 16 bf16 = 32B
            uint32_t ah[2][4], al[2][4], bh[8][2], bl[8][2];
#pragma unroll
            for (int mt = 0; mt < 2; mt++) {
                LDSM_X4(ah[mt][0], ah[mt][1], ah[mt][2], ah[mt][3],
                        aHiB + (uint32_t)(mt * 16 * 80) + kadd);
                LDSM_X4(al[mt][0], al[mt][1], al[mt][2], al[mt][3],
                        aLoB + (uint32_t)(mt * 16 * 80) + kadd);
            }
#pragma unroll
            for (int g = 0; g < 4; g++) {
                uint32_t t0, t1, t2, t3;
                LDSM_X4(t0, t1, t2, t3, bHiB + (uint32_t)(g * 16 * 80) + kadd);
                bh[2 * g][0] = t0; bh[2 * g][1] = t1;
                bh[2 * g + 1][0] = t2; bh[2 * g + 1][1] = t3;
                LDSM_X4(t0, t1, t2, t3, bLoB + (uint32_t)(g * 16 * 80) + kadd);
                bl[2 * g][0] = t0; bl[2 * g][1] = t1;
                bl[2 * g + 1][0] = t2; bl[2 * g + 1][1] = t3;
            }
#pragma unroll
            for (int mt = 0; mt < 2; mt++)
#pragma unroll
                for (int j = 0; j < 8; j++)
                    MMA_BF16(acc[mt][j], ah[mt], bh[j][0], bh[j][1]);
#pragma unroll
            for (int mt = 0; mt < 2; mt++)
#pragma unroll
                for (int j = 0; j < 8; j++)
                    MMA_BF16(acc[mt][j], ah[mt], bl[j][0], bl[j][1]);
#pragma unroll
            for (int mt = 0; mt < 2; mt++)
#pragma unroll
                for (int j = 0; j < 8; j++)
                    MMA_BF16(acc[mt][j], al[mt], bh[j][0], bh[j][1]);
        }
        __syncthreads();
    }

    // ---- epilogue ----
    const int mrow = row0 + wm * 32 + (lane >> 2);
    const int ncol = col0 + wn * 64 + (lane & 3) * 2;
#pragma unroll
    for (int mt = 0; mt < 2; mt++) {
        const int r_up = mrow + mt * 16;
#pragma unroll
        for (int j = 0; j < 8; j++) {
            const int c = ncol + j * 8;
            const float b0 = bias[c], b1 = bias[c + 1];
            float2 v0 = make_float2(acc[mt][j][0] + b0, acc[mt][j][1] + b1);
            float2 v1 = make_float2(acc[mt][j][2] + b0, acc[mt][j][3] + b1);
            *reinterpret_cast<float2*>(&C[(size_t)r_up * Nc + c]) = v0;
            *reinterpret_cast<float2*>(&C[(size_t)(r_up + 8) * Nc + c]) = v1;
        }
    }
}

// ---------------------------------------------------------------------------
// Flash-style attention with recency bias (branch-free softmax, no max).
// grid: (N/64, H, B); block: 64 threads. Each thread owns one query row.
// ---------------------------------------------------------------------------
__global__ __launch_bounds__(64)
void attn_kernel(const float* __restrict__ qkv,
                 const int* __restrict__ t_idx,
                 const unsigned char* __restrict__ mask,
                 const float* __restrict__ alpha,
                 float* __restrict__ ctx) {
    const int qt = blockIdx.x, h = blockIdx.y, b = blockIdx.z;
    const int tid = threadIdx.x;
    const int qrow = qt * 64 + tid;

    __shared__ float Ks[64][68];
    __shared__ float Vs[64][68];
    __shared__ int   tks[64];

    const float a_h = alpha[h];
    const float scale = 0.125f;

    float q[64];
    const float* qptr = qkv + ((size_t)(b * Nn + qrow)) * QKV_COLS + h * HD;
#pragma unroll
    for (int d4 = 0; d4 < 16; d4++) {
        float4 v = *reinterpret_cast<const float4*>(qptr + d4 * 4);
        q[d4 * 4 + 0] = v.x * scale;
        q[d4 * 4 + 1] = v.y * scale;
        q[d4 * 4 + 2] = v.z * scale;
        q[d4 * 4 + 3] = v.w * scale;
    }
    const float t_qf = (float)t_idx[b * Nn + qrow];
    const unsigned char* mrow_base = mask + ((size_t)(b * Nn + qrow)) * Nn;

    float acc[64];
#pragma unroll
    for (int d = 0; d < 64; d++) acc[d] = 0.0f;
    float l = 0.0f;

    const float* kbase = qkv + ((size_t)(b * Nn)) * QKV_COLS + Dd + h * HD;
    const float* vbase = kbase + Dd;

    for (int k0 = 0; k0 < Nn; k0 += 64) {
        {
            const float* kr = kbase + (size_t)(k0 + tid) * QKV_COLS;
            const float* vr = vbase + (size_t)(k0 + tid) * QKV_COLS;
#pragma unroll
            for (int d4 = 0; d4 < 16; d4++) {
                *reinterpret_cast<float4*>(&Ks[tid][d4 * 4]) =
                    *reinterpret_cast<const float4*>(kr + d4 * 4);
                *reinterpret_cast<float4*>(&Vs[tid][d4 * 4]) =
                    *reinterpret_cast<const float4*>(vr + d4 * 4);
            }
            tks[tid] = t_idx[b * Nn + k0 + tid];
        }
        __syncthreads();

        const uint4* m16 = reinterpret_cast<const uint4*>(mrow_base + k0);
        uint4 ma = m16[0], mb = m16[1], mc = m16[2], md = m16[3];
        unsigned any = ma.x | ma.y | ma.z | ma.w | mb.x | mb.y | mb.z | mb.w |
                       mc.x | mc.y | mc.z | mc.w | md.x | md.y | md.z | md.w;

        if (any == 0) {
#pragma unroll 2
            for (int j = 0; j < 64; j++) {
                float s0 = 0.f, s1 = 0.f, s2 = 0.f, s3 = 0.f;
#pragma unroll
                for (int d4 = 0; d4 < 16; d4 += 4) {
                    float4 k0v = *reinterpret_cast<const float4*>(&Ks[j][(d4 + 0) * 4]);
                    float4 k1v = *reinterpret_cast<const float4*>(&Ks[j][(d4 + 1) * 4]);
                    float4 k2v = *reinterpret_cast<const float4*>(&Ks[j][(d4 + 2) * 4]);
                    float4 k3v = *reinterpret_cast<const float4*>(&Ks[j][(d4 + 3) * 4]);
                    s0 += q[(d4 + 0) * 4 + 0] * k0v.x + q[(d4 + 0) * 4 + 1] * k0v.y
                        + q[(d4 + 0) * 4 + 2] * k0v.z + q[(d4 + 0) * 4 + 3] * k0v.w;
                    s1 += q[(d4 + 1) * 4 + 0] * k1v.x + q[(d4 + 1) * 4 + 1] * k1v.y
                        + q[(d4 + 1) * 4 + 2] * k1v.z + q[(d4 + 1) * 4 + 3] * k1v.w;
                    s2 += q[(d4 + 2) * 4 + 0] * k2v.x + q[(d4 + 2) * 4 + 1] * k2v.y
                        + q[(d4 + 2) * 4 + 2] * k2v.z + q[(d4 + 2) * 4 + 3] * k2v.w;
                    s3 += q[(d4 + 3) * 4 + 0] * k3v.x + q[(d4 + 3) * 4 + 1] * k3v.y
                        + q[(d4 + 3) * 4 + 2] * k3v.z + q[(d4 + 3) * 4 + 3] * k3v.w;
                }
                float s = (s0 + s1) + (s2 + s3);
                s -= a_h * fmaxf(t_qf - (float)tks[j], 0.0f);
                const float p = __expf(s);
                l += p;
#pragma unroll
                for (int d4 = 0; d4 < 16; d4++) {
                    float4 vv = *reinterpret_cast<const float4*>(&Vs[j][d4 * 4]);
                    acc[d4 * 4 + 0] += p * vv.x;
                    acc[d4 * 4 + 1] += p * vv.y;
                    acc[d4 * 4 + 2] += p * vv.z;
                    acc[d4 * 4 + 3] += p * vv.w;
                }
            }
        } else {
            const unsigned char* mrow = mrow_base + k0;
            for (int j = 0; j < 64; j++) {
                float s0 = 0.f, s1 = 0.f, s2 = 0.f, s3 = 0.f;
#pragma unroll
                for (int d4 = 0; d4 < 16; d4 += 4) {
                    float4 k0v = *reinterpret_cast<const float4*>(&Ks[j][(d4 + 0) * 4]);
                    float4 k1v = *reinterpret_cast<const float4*>(&Ks[j][(d4 + 1) * 4]);
                    float4 k2v = *reinterpret_cast<const float4*>(&Ks[j][(d4 + 2) * 4]);
                    float4 k3v = *reinterpret_cast<const float4*>(&Ks[j][(d4 + 3) * 4]);
                    s0 += q[(d4 + 0) * 4 + 0] * k0v.x + q[(d4 + 0) * 4 + 1] * k0v.y
                        + q[(d4 + 0) * 4 + 2] * k0v.z + q[(d4 + 0) * 4 + 3] * k0v.w;
                    s1 += q[(d4 + 1) * 4 + 0] * k1v.x + q[(d4 + 1) * 4 + 1] * k1v.y
                        + q[(d4 + 1) * 4 + 2] * k1v.z + q[(d4 + 1) * 4 + 3] * k1v.w;
                    s2 += q[(d4 + 2) * 4 + 0] * k2v.x + q[(d4 + 2) * 4 + 1] * k2v.y
                        + q[(d4 + 2) * 4 + 2] * k2v.z + q[(d4 + 2) * 4 + 3] * k2v.w;
                    s3 += q[(d4 + 3) * 4 + 0] * k3v.x + q[(d4 + 3) * 4 + 1] * k3v.y
                        + q[(d4 + 3) * 4 + 2] * k3v.z + q[(d4 + 3) * 4 + 3] * k3v.w;
                }
                float s = (s0 + s1) + (s2 + s3);
                s -= a_h * fmaxf(t_qf - (float)tks[j], 0.0f);
                float p = __expf(s);
                p = mrow[j] ? 0.0f : p;
                l += p;
#pragma unroll
                for (int d4 = 0; d4 < 16; d4++) {
                    float4 vv = *reinterpret_cast<const float4*>(&Vs[j][d4 * 4]);
                    acc[d4 * 4 + 0] += p * vv.x;
                    acc[d4 * 4 + 1] += p * vv.y;
                    acc[d4 * 4 + 2] += p * vv.z;
                    acc[d4 * 4 + 3] += p * vv.w;
                }
            }
        }
        __syncthreads();
    }

    const float inv = (l > 0.0f) ? (1.0f / l) : 0.0f;
    float* cptr = ctx + ((size_t)(b * Nn + qrow)) * Dd + h * HD;
#pragma unroll
    for (int d4 = 0; d4 < 16; d4++) {
        float4 o;
        o.x = acc[d4 * 4 + 0] * inv;
        o.y = acc[d4 * 4 + 1] * inv;
        o.z = acc[d4 * 4 + 2] * inv;
        o.w = acc[d4 * 4 + 3] * inv;
        *reinterpret_cast<float4*>(cptr + d4 * 4) = o;
    }
}

// ---------------------------------------------------------------------------
extern "C" void kernel_launch(void* const* d_in, const int* in_sizes, int n_in,
                              void* d_out, int out_size) {
    const float*         X     = (const float*)d_in[0];
    const int*           t_idx = (const int*)d_in[1];
    const unsigned char* mask  = (const unsigned char*)d_in[2];
    const float*         Wqkv  = (const float*)d_in[3];
    const float*         bqkv  = (const float*)d_in[4];
    const float*         Wo    = (const float*)d_in[5];
    const float*         bo    = (const float*)d_in[6];
    const float*         alpha = (const float*)d_in[7];
    float*               out   = (float*)d_out;

    void* qkv_p = nullptr;
    void* ctx_p = nullptr;
    cudaGetSymbolAddress(&qkv_p, g_qkv);
    cudaGetSymbolAddress(&ctx_p, g_ctx);
    float* qkv = (float*)qkv_p;
    float* ctx = (float*)ctx_p;

    // 1) QKV projection: [4096,1024] x [3072,1024]^T -> [4096,3072]
    {
        dim3 grid(QKV_COLS / 128, BN_ROWS / 128);
        gemm_bf16x3<<<grid, 256>>>(X, Wqkv, bqkv, qkv, QKV_COLS, Dd);
    }

    // 2) Attention -> ctx [B,N,D]
    {
        dim3 grid(Nn / 64, Hh, Bb);
        attn_kernel<<<grid, 64>>>(qkv, t_idx, mask, alpha, ctx);
    }

    // 3) Output projection: [4096,1024] x [1024,1024]^T -> [4096,1024]
    {
        dim3 grid(Dd / 128, BN_ROWS / 128);
        gemm_bf16x3<<<grid, 256>>>(ctx, Wo, bo, out, Dd, Dd);
    }
}

// round 8
// speedup vs baseline: 4.2305x; 2.3558x over previous
#include <cuda_runtime.h>
#include <cuda_bf16.h>
#include <cuda_fp16.h>
#include <cstdint>

// Fixed problem shapes
#define Bb 2
#define Nn 2048
#define Dd 1024
#define Hh 16
#define HD 64
#define BN_ROWS 4096
#define QKV_COLS 3072

// Scratch (device globals: allocation-guard safe)
__device__ float g_qkv[BN_ROWS * QKV_COLS];   // [B*N, 3D]
__device__ float g_ctx[BN_ROWS * Dd];         // [B*N, D]

// ---------------------------------------------------------------------------
// mma.sync helpers (baseline ISA — HMMA on sm_103)
// ---------------------------------------------------------------------------
__device__ __forceinline__ uint32_t smem_u32(const void* p) {
    uint32_t a;
    asm("{ .reg .u64 t; cvta.to.shared.u64 t, %1; cvt.u32.u64 %0, t; }" : "=r"(a) : "l"(p));
    return a;
}

__device__ __forceinline__ uint32_t h2_as_u32(__half2 h) {
    return *reinterpret_cast<uint32_t*>(&h);
}

#define LDSM_X4(r0, r1, r2, r3, addr) \
    asm volatile("ldmatrix.sync.aligned.m8n8.x4.shared.b16 {%0,%1,%2,%3}, [%4];" \
                 : "=r"(r0), "=r"(r1), "=r"(r2), "=r"(r3) : "r"(addr))

#define MMA_BF16(d, a, b0, b1) \
    asm volatile("mma.sync.aligned.m16n8k16.row.col.f32.bf16.bf16.f32 " \
                 "{%0,%1,%2,%3},{%4,%5,%6,%7},{%8,%9},{%0,%1,%2,%3};" \
                 : "+f"((d)[0]), "+f"((d)[1]), "+f"((d)[2]), "+f"((d)[3]) \
                 : "r"((a)[0]), "r"((a)[1]), "r"((a)[2]), "r"((a)[3]), \
                   "r"(b0), "r"(b1))

#define MMA_FP16(d, a, b0, b1) \
    asm volatile("mma.sync.aligned.m16n8k16.row.col.f32.f16.f16.f32 " \
                 "{%0,%1,%2,%3},{%4,%5,%6,%7},{%8,%9},{%0,%1,%2,%3};" \
                 : "+f"((d)[0]), "+f"((d)[1]), "+f"((d)[2]), "+f"((d)[3]) \
                 : "r"((a)[0]), "r"((a)[1]), "r"((a)[2]), "r"((a)[3]), \
                   "r"(b0), "r"(b1))

// ---------------------------------------------------------------------------
// bf16x3 tensor-core GEMM: C[M,Nc] = A[M,K]*B[Nc,K]^T + bias  (validated R4)
// ---------------------------------------------------------------------------
#define BKROW 40   // padded row stride (80B) for 32-col GEMM tiles

__global__ __launch_bounds__(256)
void gemm_bf16x3(const float* __restrict__ A, const float* __restrict__ B,
                 const float* __restrict__ bias, float* __restrict__ C,
                 int Nc, int K) {
    __shared__ __nv_bfloat16 sAh[128][BKROW];
    __shared__ __nv_bfloat16 sAl[128][BKROW];
    __shared__ __nv_bfloat16 sBh[128][BKROW];
    __shared__ __nv_bfloat16 sBl[128][BKROW];

    const int tid = threadIdx.x;
    const int row0 = blockIdx.y * 128;
    const int col0 = blockIdx.x * 128;

    const int warp = tid >> 5;
    const int lane = tid & 31;
    const int wm = warp & 3;
    const int wn = warp >> 2;

    const int quad = lane >> 3, r8 = lane & 7;
    const uint32_t offA = (uint32_t)(((quad & 1) * 8 + r8) * 80 + ((quad >> 1) * 8) * 2);
    const uint32_t offB = (uint32_t)(((quad >> 1) * 8 + r8) * 80 + ((quad & 1) * 8) * 2);

    const uint32_t aHiB = smem_u32(&sAh[0][0]) + (uint32_t)(wm * 32 * 80) + offA;
    const uint32_t aLoB = smem_u32(&sAl[0][0]) + (uint32_t)(wm * 32 * 80) + offA;
    const uint32_t bHiB = smem_u32(&sBh[0][0]) + (uint32_t)(wn * 64 * 80) + offB;
    const uint32_t bLoB = smem_u32(&sBl[0][0]) + (uint32_t)(wn * 64 * 80) + offB;

    float acc[2][8][4];
#pragma unroll
    for (int mt = 0; mt < 2; mt++)
#pragma unroll
        for (int j = 0; j < 8; j++)
#pragma unroll
            for (int e = 0; e < 4; e++) acc[mt][j][e] = 0.0f;

    const int nk = K >> 5;
    for (int ks = 0; ks < nk; ks++) {
        const int k0 = ks * 32;
#pragma unroll
        for (int p = 0; p < 4; p++) {
            const int idx = p * 256 + tid;
            const int row = idx >> 3;
            const int c4 = (idx & 7) * 4;
            float4 va = *reinterpret_cast<const float4*>(&A[(size_t)(row0 + row) * K + k0 + c4]);
            float4 vb = *reinterpret_cast<const float4*>(&B[(size_t)(col0 + row) * K + k0 + c4]);

            __nv_bfloat16 hx = __float2bfloat16_rn(va.x), hy = __float2bfloat16_rn(va.y),
                          hz = __float2bfloat16_rn(va.z), hw = __float2bfloat16_rn(va.w);
            __nv_bfloat162 h01; h01.x = hx; h01.y = hy;
            __nv_bfloat162 h23; h23.x = hz; h23.y = hw;
            *reinterpret_cast<__nv_bfloat162*>(&sAh[row][c4]) = h01;
            *reinterpret_cast<__nv_bfloat162*>(&sAh[row][c4 + 2]) = h23;
            __nv_bfloat162 l01, l23;
            l01.x = __float2bfloat16_rn(va.x - __bfloat162float(hx));
            l01.y = __float2bfloat16_rn(va.y - __bfloat162float(hy));
            l23.x = __float2bfloat16_rn(va.z - __bfloat162float(hz));
            l23.y = __float2bfloat16_rn(va.w - __bfloat162float(hw));
            *reinterpret_cast<__nv_bfloat162*>(&sAl[row][c4]) = l01;
            *reinterpret_cast<__nv_bfloat162*>(&sAl[row][c4 + 2]) = l23;

            hx = __float2bfloat16_rn(vb.x); hy = __float2bfloat16_rn(vb.y);
            hz = __float2bfloat16_rn(vb.z); hw = __float2bfloat16_rn(vb.w);
            h01.x = hx; h01.y = hy; h23.x = hz; h23.y = hw;
            *reinterpret_cast<__nv_bfloat162*>(&sBh[row][c4]) = h01;
            *reinterpret_cast<__nv_bfloat162*>(&sBh[row][c4 + 2]) = h23;
            l01.x = __float2bfloat16_rn(vb.x - __bfloat162float(hx));
            l01.y = __float2bfloat16_rn(vb.y - __bfloat162float(hy));
            l23.x = __float2bfloat16_rn(vb.z - __bfloat162float(hz));
            l23.y = __float2bfloat16_rn(vb.w - __bfloat162float(hw));
            *reinterpret_cast<__nv_bfloat162*>(&sBl[row][c4]) = l01;
            *reinterpret_cast<__nv_bfloat162*>(&sBl[row][c4 + 2]) = l23;
        }
        __syncthreads();

#pragma unroll
        for (int kc = 0; kc < 2; kc++) {
            const uint32_t kadd = (uint32_t)(kc * 32);
            uint32_t ah[2][4], al[2][4], bh[8][2], bl[8][2];
#pragma unroll
            for (int mt = 0; mt < 2; mt++) {
                LDSM_X4(ah[mt][0], ah[mt][1], ah[mt][2], ah[mt][3],
                        aHiB + (uint32_t)(mt * 16 * 80) + kadd);
                LDSM_X4(al[mt][0], al[mt][1], al[mt][2], al[mt][3],
                        aLoB + (uint32_t)(mt * 16 * 80) + kadd);
            }
#pragma unroll
            for (int g = 0; g < 4; g++) {
                uint32_t t0, t1, t2, t3;
                LDSM_X4(t0, t1, t2, t3, bHiB + (uint32_t)(g * 16 * 80) + kadd);
                bh[2 * g][0] = t0; bh[2 * g][1] = t1;
                bh[2 * g + 1][0] = t2; bh[2 * g + 1][1] = t3;
                LDSM_X4(t0, t1, t2, t3, bLoB + (uint32_t)(g * 16 * 80) + kadd);
                bl[2 * g][0] = t0; bl[2 * g][1] = t1;
                bl[2 * g + 1][0] = t2; bl[2 * g + 1][1] = t3;
            }
#pragma unroll
            for (int mt = 0; mt < 2; mt++)
#pragma unroll
                for (int j = 0; j < 8; j++)
                    MMA_BF16(acc[mt][j], ah[mt], bh[j][0], bh[j][1]);
#pragma unroll
            for (int mt = 0; mt < 2; mt++)
#pragma unroll
                for (int j = 0; j < 8; j++)
                    MMA_BF16(acc[mt][j], ah[mt], bl[j][0], bl[j][1]);
#pragma unroll
            for (int mt = 0; mt < 2; mt++)
#pragma unroll
                for (int j = 0; j < 8; j++)
                    MMA_BF16(acc[mt][j], al[mt], bh[j][0], bh[j][1]);
        }
        __syncthreads();
    }

    const int mrow = row0 + wm * 32 + (lane >> 2);
    const int ncol = col0 + wn * 64 + (lane & 3) * 2;
#pragma unroll
    for (int mt = 0; mt < 2; mt++) {
        const int r_up = mrow + mt * 16;
#pragma unroll
        for (int j = 0; j < 8; j++) {
            const int c = ncol + j * 8;
            const float b0 = bias[c], b1 = bias[c + 1];
            float2 v0 = make_float2(acc[mt][j][0] + b0, acc[mt][j][1] + b1);
            float2 v1 = make_float2(acc[mt][j][2] + b0, acc[mt][j][3] + b1);
            *reinterpret_cast<float2*>(&C[(size_t)r_up * Nc + c]) = v0;
            *reinterpret_cast<float2*>(&C[(size_t)(r_up + 8) * Nc + c]) = v1;
        }
    }
}

// ---------------------------------------------------------------------------
// Tensor-core flash attention with recency bias.
// CTA = (q-tile 64, h, b); 128 threads (4 warps x 16 q-rows).
// smem rows: 64 cols of fp16 + pad -> AROW=72 halves (144B stride,
// odd multiple of 16B -> ldmatrix conflict-free).
// S = Qh.Kh + Qh.Kl + Ql.Kh (fp16x3). Online per-tile max. P fp16 in [0,1].
// PV = P x (Vh + Vl), V transposed [hd][key], fp16 hi/lo split.
// ---------------------------------------------------------------------------
#define AROW 72
#define ARS  144   // row stride bytes

__global__ __launch_bounds__(128)
void attn_tc(const float* __restrict__ qkv,
             const int* __restrict__ t_idx,
             const unsigned char* __restrict__ mask,
             const float* __restrict__ alpha,
             float* __restrict__ ctx) {
    __shared__ __half sQh[64][AROW];
    __shared__ __half sQl[64][AROW];
    __shared__ __half sKh[64][AROW];
    __shared__ __half sKl[64][AROW];
    __shared__ __half sVh[64][AROW];   // transposed: [hd][key]
    __shared__ __half sVl[64][AROW];
    __shared__ int tks[64];

    const int qt = blockIdx.x, h = blockIdx.y, b = blockIdx.z;
    const int tid = threadIdx.x, warp = tid >> 5, lane = tid & 31;
    const int q0 = qt * 64;

    const float a_h = alpha[h];
    const size_t bn0 = (size_t)(b * Nn);

    // ---- stage Q (scaled by 1/8) with fp16 hi/lo split: 64 rows x 64 cols ----
#pragma unroll
    for (int p = 0; p < 8; p++) {
        const int idx = p * 128 + tid;
        const int row = idx >> 4, c4 = (idx & 15) * 4;
        const float4 v = *reinterpret_cast<const float4*>(
            &qkv[(bn0 + q0 + row) * QKV_COLS + h * HD + c4]);
        float f[4] = {v.x * 0.125f, v.y * 0.125f, v.z * 0.125f, v.w * 0.125f};
        __half hh[4], ll[4];
#pragma unroll
        for (int i = 0; i < 4; i++) {
            hh[i] = __float2half_rn(f[i]);
            ll[i] = __float2half_rn(f[i] - __half2float(hh[i]));
        }
        *reinterpret_cast<__half2*>(&sQh[row][c4])     = __halves2half2(hh[0], hh[1]);
        *reinterpret_cast<__half2*>(&sQh[row][c4 + 2]) = __halves2half2(hh[2], hh[3]);
        *reinterpret_cast<__half2*>(&sQl[row][c4])     = __halves2half2(ll[0], ll[1]);
        *reinterpret_cast<__half2*>(&sQl[row][c4 + 2]) = __halves2half2(ll[2], ll[3]);
    }

    // per-lane fragment row info
    const int g8 = lane >> 2;
    const int row_lo = q0 + warp * 16 + g8;
    const int row_hi = row_lo + 8;
    const float tq0 = (float)t_idx[bn0 + row_lo];
    const float tq1 = (float)t_idx[bn0 + row_hi];

    float ctxacc[8][4];
#pragma unroll
    for (int j = 0; j < 8; j++)
#pragma unroll
        for (int e = 0; e < 4; e++) ctxacc[j][e] = 0.0f;
    float lsum0 = 0.0f, lsum1 = 0.0f;
    float m0 = -1e30f, m1 = -1e30f;

    // ldmatrix bases (144B rows)
    const int quad = lane >> 3, r8 = lane & 7;
    const uint32_t offA = (uint32_t)(((quad & 1) * 8 + r8) * ARS + ((quad >> 1) * 8) * 2);
    const uint32_t offB = (uint32_t)(((quad >> 1) * 8 + r8) * ARS + ((quad & 1) * 8) * 2);
    const uint32_t aQh = smem_u32(&sQh[0][0]) + (uint32_t)(warp * 16 * ARS) + offA;
    const uint32_t aQl = smem_u32(&sQl[0][0]) + (uint32_t)(warp * 16 * ARS) + offA;
    const uint32_t bKh = smem_u32(&sKh[0][0]) + offB;
    const uint32_t bKl = smem_u32(&sKl[0][0]) + offB;
    const uint32_t bVh = smem_u32(&sVh[0][0]) + offB;
    const uint32_t bVl = smem_u32(&sVl[0][0]) + offB;

    const float* kbase = qkv + bn0 * QKV_COLS + Dd + h * HD;
    const float* vbase = qkv + bn0 * QKV_COLS + 2 * Dd + h * HD;

    for (int k0 = 0; k0 < Nn; k0 += 64) {
        // mask any-check: 2 threads per q-row, 32B each
        int myMask;
        {
            const int row = tid >> 1, half = tid & 1;
            const uint4* mp = reinterpret_cast<const uint4*>(
                &mask[(bn0 + q0 + row) * Nn + k0 + half * 32]);
            uint4 mA = mp[0], mB = mp[1];
            myMask = (mA.x | mA.y | mA.z | mA.w | mB.x | mB.y | mB.z | mB.w) != 0;
        }

        // stage K tile (64 rows x 64 cols) with fp16 hi/lo split
#pragma unroll
        for (int p = 0; p < 8; p++) {
            const int idx = p * 128 + tid;
            const int row = idx >> 4, c4 = (idx & 15) * 4;
            const float4 v = *reinterpret_cast<const float4*>(
                &kbase[(size_t)(k0 + row) * QKV_COLS + c4]);
            float f[4] = {v.x, v.y, v.z, v.w};
            __half hh[4], ll[4];
#pragma unroll
            for (int i = 0; i < 4; i++) {
                hh[i] = __float2half_rn(f[i]);
                ll[i] = __float2half_rn(f[i] - __half2float(hh[i]));
            }
            *reinterpret_cast<__half2*>(&sKh[row][c4])     = __halves2half2(hh[0], hh[1]);
            *reinterpret_cast<__half2*>(&sKh[row][c4 + 2]) = __halves2half2(hh[2], hh[3]);
            *reinterpret_cast<__half2*>(&sKl[row][c4])     = __halves2half2(ll[0], ll[1]);
            *reinterpret_cast<__half2*>(&sKl[row][c4 + 2]) = __halves2half2(ll[2], ll[3]);
        }

        // stage V transposed [hd][key] with fp16 hi/lo split
        {
            const int kp = lane;  // keys 2kp, 2kp+1
#pragma unroll
            for (int p = 0; p < 2; p++) {
                const int hd0 = warp * 8 + p * 32;
                const float* r0 = &vbase[(size_t)(k0 + 2 * kp) * QKV_COLS + hd0];
                const float* r1 = r0 + QKV_COLS;
                float4 x0 = *reinterpret_cast<const float4*>(r0);
                float4 x1 = *reinterpret_cast<const float4*>(r0 + 4);
                float4 y0 = *reinterpret_cast<const float4*>(r1);
                float4 y1 = *reinterpret_cast<const float4*>(r1 + 4);
                float vx[8] = {x0.x, x0.y, x0.z, x0.w, x1.x, x1.y, x1.z, x1.w};
                float vy[8] = {y0.x, y0.y, y0.z, y0.w, y1.x, y1.y, y1.z, y1.w};
#pragma unroll
                for (int i = 0; i < 8; i++) {
                    __half ah = __float2half_rn(vx[i]);
                    __half bh = __float2half_rn(vy[i]);
                    __half al = __float2half_rn(vx[i] - __half2float(ah));
                    __half bl = __float2half_rn(vy[i] - __half2float(bh));
                    *reinterpret_cast<__half2*>(&sVh[hd0 + i][2 * kp]) = __halves2half2(ah, bh);
                    *reinterpret_cast<__half2*>(&sVl[hd0 + i][2 * kp]) = __halves2half2(al, bl);
                }
            }
        }
        if (tid < 64) tks[tid] = t_idx[bn0 + k0 + tid];

        const int tileMasked = __syncthreads_or(myMask);

        // ---- S = Qh.Kh + Qh.Kl + Ql.Kh ----
        float sacc[8][4];
#pragma unroll
        for (int j = 0; j < 8; j++)
#pragma unroll
            for (int e = 0; e < 4; e++) sacc[j][e] = 0.0f;

#pragma unroll
        for (int pass = 0; pass < 3; pass++) {
            const uint32_t aBase = (pass == 2) ? aQl : aQh;
            const uint32_t bBase = (pass == 1) ? bKl : bKh;
#pragma unroll
            for (int kc = 0; kc < 4; kc++) {
                uint32_t aq[4];
                LDSM_X4(aq[0], aq[1], aq[2], aq[3], aBase + (uint32_t)(kc * 32));
#pragma unroll
                for (int g = 0; g < 4; g++) {
                    uint32_t t0, t1, t2, t3;
                    LDSM_X4(t0, t1, t2, t3, bBase + (uint32_t)(g * 16 * ARS + kc * 32));
                    MMA_FP16(sacc[2 * g], aq, t0, t1);
                    MMA_FP16(sacc[2 * g + 1], aq, t2, t3);
                }
            }
        }

        // ---- bias + tile max ----
        float tmax0 = -1e30f, tmax1 = -1e30f;
#pragma unroll
        for (int j = 0; j < 8; j++) {
            const int c0 = 8 * j + 2 * (lane & 3);
            const float tk0 = (float)tks[c0];
            const float tk1 = (float)tks[c0 + 1];
            sacc[j][0] -= a_h * fmaxf(tq0 - tk0, 0.0f);
            sacc[j][1] -= a_h * fmaxf(tq0 - tk1, 0.0f);
            sacc[j][2] -= a_h * fmaxf(tq1 - tk0, 0.0f);
            sacc[j][3] -= a_h * fmaxf(tq1 - tk1, 0.0f);
            tmax0 = fmaxf(tmax0, fmaxf(sacc[j][0], sacc[j][1]));
            tmax1 = fmaxf(tmax1, fmaxf(sacc[j][2], sacc[j][3]));
        }
        tmax0 = fmaxf(tmax0, __shfl_xor_sync(0xFFFFFFFF, tmax0, 1));
        tmax0 = fmaxf(tmax0, __shfl_xor_sync(0xFFFFFFFF, tmax0, 2));
        tmax1 = fmaxf(tmax1, __shfl_xor_sync(0xFFFFFFFF, tmax1, 1));
        tmax1 = fmaxf(tmax1, __shfl_xor_sync(0xFFFFFFFF, tmax1, 2));

        const float mn0 = fmaxf(m0, tmax0);
        const float mn1 = fmaxf(m1, tmax1);
        const float sc0 = __expf(m0 - mn0);
        const float sc1 = __expf(m1 - mn1);
        m0 = mn0; m1 = mn1;
        lsum0 *= sc0; lsum1 *= sc1;
#pragma unroll
        for (int j = 0; j < 8; j++) {
            ctxacc[j][0] *= sc0; ctxacc[j][1] *= sc0;
            ctxacc[j][2] *= sc1; ctxacc[j][3] *= sc1;
        }

        // ---- exp + mask + pack P ----
        uint32_t pa[4][4];
#pragma unroll
        for (int j = 0; j < 8; j++) {
            const int c0 = 8 * j + 2 * (lane & 3);
            float p0 = __expf(sacc[j][0] - m0);
            float p1 = __expf(sacc[j][1] - m0);
            float p2 = __expf(sacc[j][2] - m1);
            float p3 = __expf(sacc[j][3] - m1);
            if (tileMasked) {
                const unsigned char* mr0 = &mask[(bn0 + row_lo) * Nn + k0 + c0];
                const unsigned char* mr1 = &mask[(bn0 + row_hi) * Nn + k0 + c0];
                p0 = mr0[0] ? 0.0f : p0;
                p1 = mr0[1] ? 0.0f : p1;
                p2 = mr1[0] ? 0.0f : p2;
                p3 = mr1[1] ? 0.0f : p3;
            }
            const __half2 lo_h = __float22half2_rn(make_float2(p0, p1));
            const __half2 hi_h = __float22half2_rn(make_float2(p2, p3));
            const float2 lo_r = __half22float2(lo_h);
            const float2 hi_r = __half22float2(hi_h);
            lsum0 += lo_r.x + lo_r.y;
            lsum1 += hi_r.x + hi_r.y;
            pa[j >> 1][(j & 1) * 2 + 0] = h2_as_u32(lo_h);
            pa[j >> 1][(j & 1) * 2 + 1] = h2_as_u32(hi_h);
        }

        // ---- ctx += P x (Vh + Vl) ----
#pragma unroll
        for (int kc = 0; kc < 4; kc++) {
#pragma unroll
            for (int g = 0; g < 4; g++) {
                uint32_t t0, t1, t2, t3;
                LDSM_X4(t0, t1, t2, t3, bVh + (uint32_t)(g * 16 * ARS + kc * 32));
                MMA_FP16(ctxacc[2 * g], pa[kc], t0, t1);
                MMA_FP16(ctxacc[2 * g + 1], pa[kc], t2, t3);
                LDSM_X4(t0, t1, t2, t3, bVl + (uint32_t)(g * 16 * ARS + kc * 32));
                MMA_FP16(ctxacc[2 * g], pa[kc], t0, t1);
                MMA_FP16(ctxacc[2 * g + 1], pa[kc], t2, t3);
            }
        }
        __syncthreads();
    }

    // reduce l across the 4 lanes of each row group
    lsum0 += __shfl_xor_sync(0xFFFFFFFF, lsum0, 1);
    lsum0 += __shfl_xor_sync(0xFFFFFFFF, lsum0, 2);
    lsum1 += __shfl_xor_sync(0xFFFFFFFF, lsum1, 1);
    lsum1 += __shfl_xor_sync(0xFFFFFFFF, lsum1, 2);
    const float inv0 = (lsum0 > 0.0f) ? (1.0f / lsum0) : 0.0f;
    const float inv1 = (lsum1 > 0.0f) ? (1.0f / lsum1) : 0.0f;

    // write ctx[b, q, h*64 + hd]
#pragma unroll
    for (int j = 0; j < 8; j++) {
        const int c0 = h * HD + 8 * j + 2 * (lane & 3);
        float2 lo = make_float2(ctxacc[j][0] * inv0, ctxacc[j][1] * inv0);
        float2 hi = make_float2(ctxacc[j][2] * inv1, ctxacc[j][3] * inv1);
        *reinterpret_cast<float2*>(&ctx[(bn0 + row_lo) * Dd + c0]) = lo;
        *reinterpret_cast<float2*>(&ctx[(bn0 + row_hi) * Dd + c0]) = hi;
    }
}

// ---------------------------------------------------------------------------
extern "C" void kernel_launch(void* const* d_in, const int* in_sizes, int n_in,
                              void* d_out, int out_size) {
    const float*         X     = (const float*)d_in[0];
    const int*           t_idx = (const int*)d_in[1];
    const unsigned char* mask  = (const unsigned char*)d_in[2];
    const float*         Wqkv  = (const float*)d_in[3];
    const float*         bqkv  = (const float*)d_in[4];
    const float*         Wo    = (const float*)d_in[5];
    const float*         bo    = (const float*)d_in[6];
    const float*         alpha = (const float*)d_in[7];
    float*               out   = (float*)d_out;

    void* qkv_p = nullptr;
    void* ctx_p = nullptr;
    cudaGetSymbolAddress(&qkv_p, g_qkv);
    cudaGetSymbolAddress(&ctx_p, g_ctx);
    float* qkv = (float*)qkv_p;
    float* ctx = (float*)ctx_p;

    // 1) QKV projection
    {
        dim3 grid(QKV_COLS / 128, BN_ROWS / 128);
        gemm_bf16x3<<<grid, 256>>>(X, Wqkv, bqkv, qkv, QKV_COLS, Dd);
    }

    // 2) Tensor-core flash attention -> ctx
    {
        dim3 grid(Nn / 64, Hh, Bb);
        attn_tc<<<grid, 128>>>(qkv, t_idx, mask, alpha, ctx);
    }

    // 3) Output projection
    {
        dim3 grid(Dd / 128, BN_ROWS / 128);
        gemm_bf16x3<<<grid, 256>>>(ctx, Wo, bo, out, Dd, Dd);
    }
}

// round 9
// speedup vs baseline: 4.5472x; 1.0749x over previous
#include <cuda_runtime.h>
#include <cuda_bf16.h>
#include <cuda_fp16.h>
#include <cstdint>

// Fixed problem shapes
#define Bb 2
#define Nn 2048
#define Dd 1024
#define Hh 16
#define HD 64
#define BN_ROWS 4096
#define QKV_COLS 3072
#define NH (Bb * Hh)               // 32
#define HSZ (Nn * HD)              // 131072 per (b,h)

// Scratch (device globals: allocation-guard safe)
__device__ float g_qkv[BN_ROWS * QKV_COLS];            // fp32 qkv
__device__ __nv_bfloat16 g_xh[BN_ROWS * Dd], g_xl[BN_ROWS * Dd];
__device__ __nv_bfloat16 g_wqh[QKV_COLS * Dd], g_wql[QKV_COLS * Dd];
__device__ __nv_bfloat16 g_woh[Dd * Dd], g_wol[Dd * Dd];
__device__ __nv_bfloat16 g_ctxh[BN_ROWS * Dd], g_ctxl[BN_ROWS * Dd];
__device__ __half g_q16h[NH * HSZ], g_q16l[NH * HSZ];
__device__ __half g_k16h[NH * HSZ], g_k16l[NH * HSZ];
__device__ __half g_v16h[NH * HSZ], g_v16l[NH * HSZ];  // transposed [bh][hd][n]

// ---------------------------------------------------------------------------
// helpers
// ---------------------------------------------------------------------------
__device__ __forceinline__ uint32_t smem_u32(const void* p) {
    uint32_t a;
    asm("{ .reg .u64 t; cvta.to.shared.u64 t, %1; cvt.u32.u64 %0, t; }" : "=r"(a) : "l"(p));
    return a;
}
__device__ __forceinline__ uint32_t h2_as_u32(__half2 h) {
    return *reinterpret_cast<uint32_t*>(&h);
}

#define LDSM_X4(r0, r1, r2, r3, addr) \
    asm volatile("ldmatrix.sync.aligned.m8n8.x4.shared.b16 {%0,%1,%2,%3}, [%4];" \
                 : "=r"(r0), "=r"(r1), "=r"(r2), "=r"(r3) : "r"(addr))

#define MMA_BF16(d, a, b0, b1) \
    asm volatile("mma.sync.aligned.m16n8k16.row.col.f32.bf16.bf16.f32 " \
                 "{%0,%1,%2,%3},{%4,%5,%6,%7},{%8,%9},{%0,%1,%2,%3};" \
                 : "+f"((d)[0]), "+f"((d)[1]), "+f"((d)[2]), "+f"((d)[3]) \
                 : "r"((a)[0]), "r"((a)[1]), "r"((a)[2]), "r"((a)[3]), \
                   "r"(b0), "r"(b1))

#define MMA_FP16(d, a, b0, b1) \
    asm volatile("mma.sync.aligned.m16n8k16.row.col.f32.f16.f16.f32 " \
                 "{%0,%1,%2,%3},{%4,%5,%6,%7},{%8,%9},{%0,%1,%2,%3};" \
                 : "+f"((d)[0]), "+f"((d)[1]), "+f"((d)[2]), "+f"((d)[3]) \
                 : "r"((a)[0]), "r"((a)[1]), "r"((a)[2]), "r"((a)[3]), \
                   "r"(b0), "r"(b1))

// ---------------------------------------------------------------------------
// prep1: elementwise fp32 -> bf16 hi/lo split
// ---------------------------------------------------------------------------
__global__ __launch_bounds__(256)
void split_bf16(const float* __restrict__ in, __nv_bfloat16* __restrict__ oh,
                __nv_bfloat16* __restrict__ ol, int n4) {
    const int i = blockIdx.x * 256 + threadIdx.x;
    if (i >= n4) return;
    const float4 v = reinterpret_cast<const float4*>(in)[i];
    float f[4] = {v.x, v.y, v.z, v.w};
    __nv_bfloat16 h[4], l[4];
#pragma unroll
    for (int e = 0; e < 4; e++) {
        h[e] = __float2bfloat16_rn(f[e]);
        l[e] = __float2bfloat16_rn(f[e] - __bfloat162float(h[e]));
    }
    __nv_bfloat162 h01; h01.x = h[0]; h01.y = h[1];
    __nv_bfloat162 h23; h23.x = h[2]; h23.y = h[3];
    __nv_bfloat162 l01; l01.x = l[0]; l01.y = l[1];
    __nv_bfloat162 l23; l23.x = l[2]; l23.y = l[3];
    reinterpret_cast<__nv_bfloat162*>(oh)[2 * i]     = h01;
    reinterpret_cast<__nv_bfloat162*>(oh)[2 * i + 1] = h23;
    reinterpret_cast<__nv_bfloat162*>(ol)[2 * i]     = l01;
    reinterpret_cast<__nv_bfloat162*>(ol)[2 * i + 1] = l23;
}

// ---------------------------------------------------------------------------
// prep2: qkv fp32 -> packed per-head fp16 hi/lo (Q scaled 1/8; V transposed)
// grid: (32 n-tiles, 32 bh); 128 threads
// ---------------------------------------------------------------------------
__global__ __launch_bounds__(128)
void attn_prep(const float* __restrict__ qkv,
               __half* __restrict__ qh, __half* __restrict__ ql,
               __half* __restrict__ kh, __half* __restrict__ kl,
               __half* __restrict__ vh, __half* __restrict__ vl) {
    __shared__ float sv[64][65];
    const int tid = threadIdx.x;
    const int nt = blockIdx.x, bh = blockIdx.y;
    const int b = bh >> 4, h = bh & 15;
    const int n0 = nt * 64;
    const size_t obase = (size_t)bh * HSZ;

#pragma unroll
    for (int p = 0; p < 8; p++) {
        const int idx = p * 128 + tid;
        const int row = idx >> 4, c4 = (idx & 15) * 4;
        const size_t src = (size_t)(b * Nn + n0 + row) * QKV_COLS + h * HD + c4;
        // Q (scaled 1/8)
        {
            const float4 v = *reinterpret_cast<const float4*>(&qkv[src]);
            float f[4] = {v.x * 0.125f, v.y * 0.125f, v.z * 0.125f, v.w * 0.125f};
            __half hh[4], ll[4];
#pragma unroll
            for (int e = 0; e < 4; e++) {
                hh[e] = __float2half_rn(f[e]);
                ll[e] = __float2half_rn(f[e] - __half2float(hh[e]));
            }
            const size_t o = obase + (size_t)(n0 + row) * HD + c4;
            *reinterpret_cast<__half2*>(&qh[o])     = __halves2half2(hh[0], hh[1]);
            *reinterpret_cast<__half2*>(&qh[o + 2]) = __halves2half2(hh[2], hh[3]);
            *reinterpret_cast<__half2*>(&ql[o])     = __halves2half2(ll[0], ll[1]);
            *reinterpret_cast<__half2*>(&ql[o + 2]) = __halves2half2(ll[2], ll[3]);
        }
        // K
        {
            const float4 v = *reinterpret_cast<const float4*>(&qkv[src + Dd]);
            float f[4] = {v.x, v.y, v.z, v.w};
            __half hh[4], ll[4];
#pragma unroll
            for (int e = 0; e < 4; e++) {
                hh[e] = __float2half_rn(f[e]);
                ll[e] = __float2half_rn(f[e] - __half2float(hh[e]));
            }
            const size_t o = obase + (size_t)(n0 + row) * HD + c4;
            *reinterpret_cast<__half2*>(&kh[o])     = __halves2half2(hh[0], hh[1]);
            *reinterpret_cast<__half2*>(&kh[o + 2]) = __halves2half2(hh[2], hh[3]);
            *reinterpret_cast<__half2*>(&kl[o])     = __halves2half2(ll[0], ll[1]);
            *reinterpret_cast<__half2*>(&kl[o + 2]) = __halves2half2(ll[2], ll[3]);
        }
        // V -> smem
        {
            const float4 v = *reinterpret_cast<const float4*>(&qkv[src + 2 * Dd]);
            sv[row][c4 + 0] = v.x; sv[row][c4 + 1] = v.y;
            sv[row][c4 + 2] = v.z; sv[row][c4 + 3] = v.w;
        }
    }
    __syncthreads();
    // V transposed write: [hd][n]
#pragma unroll
    for (int p = 0; p < 8; p++) {
        const int idx = p * 128 + tid;
        const int hd = idx >> 4, oc4 = (idx & 15) * 4;
        float f[4] = {sv[oc4 + 0][hd], sv[oc4 + 1][hd], sv[oc4 + 2][hd], sv[oc4 + 3][hd]};
        __half hh[4], ll[4];
#pragma unroll
        for (int e = 0; e < 4; e++) {
            hh[e] = __float2half_rn(f[e]);
            ll[e] = __float2half_rn(f[e] - __half2float(hh[e]));
        }
        const size_t o = obase + (size_t)hd * Nn + n0 + oc4;
        *reinterpret_cast<__half2*>(&vh[o])     = __halves2half2(hh[0], hh[1]);
        *reinterpret_cast<__half2*>(&vh[o + 2]) = __halves2half2(hh[2], hh[3]);
        *reinterpret_cast<__half2*>(&vl[o])     = __halves2half2(ll[0], ll[1]);
        *reinterpret_cast<__half2*>(&vl[o + 2]) = __halves2half2(ll[2], ll[3]);
    }
}

// ---------------------------------------------------------------------------
// bf16x3 GEMM on pre-split inputs: C = A*B^T + bias (mma core validated R4)
// ---------------------------------------------------------------------------
#define BKROW 40   // 80B row stride

__global__ __launch_bounds__(256)
void gemm_sp(const __nv_bfloat16* __restrict__ Ah, const __nv_bfloat16* __restrict__ Al,
             const __nv_bfloat16* __restrict__ Bh, const __nv_bfloat16* __restrict__ Bl,
             const float* __restrict__ bias, float* __restrict__ C,
             int Nc, int K) {
    __shared__ __nv_bfloat16 sAh[128][BKROW];
    __shared__ __nv_bfloat16 sAl[128][BKROW];
    __shared__ __nv_bfloat16 sBh[128][BKROW];
    __shared__ __nv_bfloat16 sBl[128][BKROW];

    const int tid = threadIdx.x;
    const int row0 = blockIdx.y * 128;
    const int col0 = blockIdx.x * 128;
    const int warp = tid >> 5, lane = tid & 31;
    const int wm = warp & 3, wn = warp >> 2;

    const int quad = lane >> 3, r8 = lane & 7;
    const uint32_t offA = (uint32_t)(((quad & 1) * 8 + r8) * 80 + ((quad >> 1) * 8) * 2);
    const uint32_t offB = (uint32_t)(((quad >> 1) * 8 + r8) * 80 + ((quad & 1) * 8) * 2);

    const uint32_t aHiB = smem_u32(&sAh[0][0]) + (uint32_t)(wm * 32 * 80) + offA;
    const uint32_t aLoB = smem_u32(&sAl[0][0]) + (uint32_t)(wm * 32 * 80) + offA;
    const uint32_t bHiB = smem_u32(&sBh[0][0]) + (uint32_t)(wn * 64 * 80) + offB;
    const uint32_t bLoB = smem_u32(&sBl[0][0]) + (uint32_t)(wn * 64 * 80) + offB;

    float acc[2][8][4];
#pragma unroll
    for (int mt = 0; mt < 2; mt++)
#pragma unroll
        for (int j = 0; j < 8; j++)
#pragma unroll
            for (int e = 0; e < 4; e++) acc[mt][j][e] = 0.0f;

    const int nk = K >> 5;
    for (int ks = 0; ks < nk; ks++) {
        const int k0 = ks * 32;
        // pure-copy staging: 128 rows x 32 bf16 per array
#pragma unroll
        for (int p = 0; p < 2; p++) {
            const int idx = p * 256 + tid;
            const int row = idx >> 2, u = idx & 3;
            const size_t ra = (size_t)(row0 + row) * K + k0 + u * 8;
            const size_t rb = (size_t)(col0 + row) * K + k0 + u * 8;
            *reinterpret_cast<uint4*>(&sAh[row][u * 8]) = *reinterpret_cast<const uint4*>(&Ah[ra]);
            *reinterpret_cast<uint4*>(&sAl[row][u * 8]) = *reinterpret_cast<const uint4*>(&Al[ra]);
            *reinterpret_cast<uint4*>(&sBh[row][u * 8]) = *reinterpret_cast<const uint4*>(&Bh[rb]);
            *reinterpret_cast<uint4*>(&sBl[row][u * 8]) = *reinterpret_cast<const uint4*>(&Bl[rb]);
        }
        __syncthreads();

#pragma unroll
        for (int kc = 0; kc < 2; kc++) {
            const uint32_t kadd = (uint32_t)(kc * 32);
            uint32_t ah[2][4], al[2][4], bh[8][2], bl[8][2];
#pragma unroll
            for (int mt = 0; mt < 2; mt++) {
                LDSM_X4(ah[mt][0], ah[mt][1], ah[mt][2], ah[mt][3],
                        aHiB + (uint32_t)(mt * 16 * 80) + kadd);
                LDSM_X4(al[mt][0], al[mt][1], al[mt][2], al[mt][3],
                        aLoB + (uint32_t)(mt * 16 * 80) + kadd);
            }
#pragma unroll
            for (int g = 0; g < 4; g++) {
                uint32_t t0, t1, t2, t3;
                LDSM_X4(t0, t1, t2, t3, bHiB + (uint32_t)(g * 16 * 80) + kadd);
                bh[2 * g][0] = t0; bh[2 * g][1] = t1;
                bh[2 * g + 1][0] = t2; bh[2 * g + 1][1] = t3;
                LDSM_X4(t0, t1, t2, t3, bLoB + (uint32_t)(g * 16 * 80) + kadd);
                bl[2 * g][0] = t0; bl[2 * g][1] = t1;
                bl[2 * g + 1][0] = t2; bl[2 * g + 1][1] = t3;
            }
#pragma unroll
            for (int mt = 0; mt < 2; mt++)
#pragma unroll
                for (int j = 0; j < 8; j++)
                    MMA_BF16(acc[mt][j], ah[mt], bh[j][0], bh[j][1]);
#pragma unroll
            for (int mt = 0; mt < 2; mt++)
#pragma unroll
                for (int j = 0; j < 8; j++)
                    MMA_BF16(acc[mt][j], ah[mt], bl[j][0], bl[j][1]);
#pragma unroll
            for (int mt = 0; mt < 2; mt++)
#pragma unroll
                for (int j = 0; j < 8; j++)
                    MMA_BF16(acc[mt][j], al[mt], bh[j][0], bh[j][1]);
        }
        __syncthreads();
    }

    const int mrow = row0 + wm * 32 + (lane >> 2);
    const int ncol = col0 + wn * 64 + (lane & 3) * 2;
#pragma unroll
    for (int mt = 0; mt < 2; mt++) {
        const int r_up = mrow + mt * 16;
#pragma unroll
        for (int j = 0; j < 8; j++) {
            const int c = ncol + j * 8;
            const float b0 = bias[c], b1 = bias[c + 1];
            float2 v0 = make_float2(acc[mt][j][0] + b0, acc[mt][j][1] + b1);
            float2 v1 = make_float2(acc[mt][j][2] + b0, acc[mt][j][3] + b1);
            *reinterpret_cast<float2*>(&C[(size_t)r_up * Nc + c]) = v0;
            *reinterpret_cast<float2*>(&C[(size_t)(r_up + 8) * Nc + c]) = v1;
        }
    }
}

// ---------------------------------------------------------------------------
// Tensor-core flash attention (pre-split fp16 inputs; logic validated R8).
// Writes ctx directly as bf16 hi/lo for the out-projection.
// ---------------------------------------------------------------------------
#define AROW 72
#define ARS  144

__global__ __launch_bounds__(128)
void attn_tc(const __half* __restrict__ qh, const __half* __restrict__ ql,
             const __half* __restrict__ kh, const __half* __restrict__ kl,
             const __half* __restrict__ vh, const __half* __restrict__ vl,
             const int* __restrict__ t_idx,
             const unsigned char* __restrict__ mask,
             const float* __restrict__ alpha,
             __nv_bfloat16* __restrict__ ctxh, __nv_bfloat16* __restrict__ ctxl) {
    __shared__ __half sQh[64][AROW];
    __shared__ __half sQl[64][AROW];
    __shared__ __half sKh[64][AROW];
    __shared__ __half sKl[64][AROW];
    __shared__ __half sVh[64][AROW];
    __shared__ __half sVl[64][AROW];
    __shared__ int tks[64];

    const int qt = blockIdx.x, h = blockIdx.y, b = blockIdx.z;
    const int tid = threadIdx.x, warp = tid >> 5, lane = tid & 31;
    const int q0 = qt * 64;

    const float a_h = alpha[h];
    const size_t bn0 = (size_t)(b * Nn);
    const size_t hb = (size_t)(b * Hh + h) * HSZ;

    // ---- stage Q (already scaled+split): 64 rows x 8 uint4 per array ----
#pragma unroll
    for (int p = 0; p < 4; p++) {
        const int idx = p * 128 + tid;
        const int row = idx >> 3, u = idx & 7;
        const size_t src = hb + (size_t)(q0 + row) * HD + u * 8;
        *reinterpret_cast<uint4*>(&sQh[row][u * 8]) = *reinterpret_cast<const uint4*>(&qh[src]);
        *reinterpret_cast<uint4*>(&sQl[row][u * 8]) = *reinterpret_cast<const uint4*>(&ql[src]);
    }

    const int g8 = lane >> 2;
    const int row_lo = q0 + warp * 16 + g8;
    const int row_hi = row_lo + 8;
    const float tq0 = (float)t_idx[bn0 + row_lo];
    const float tq1 = (float)t_idx[bn0 + row_hi];

    float ctxacc[8][4];
#pragma unroll
    for (int j = 0; j < 8; j++)
#pragma unroll
        for (int e = 0; e < 4; e++) ctxacc[j][e] = 0.0f;
    float lsum0 = 0.0f, lsum1 = 0.0f;
    float m0 = -1e30f, m1 = -1e30f;

    const int quad = lane >> 3, r8 = lane & 7;
    const uint32_t offA = (uint32_t)(((quad & 1) * 8 + r8) * ARS + ((quad >> 1) * 8) * 2);
    const uint32_t offB = (uint32_t)(((quad >> 1) * 8 + r8) * ARS + ((quad & 1) * 8) * 2);
    const uint32_t aQh = smem_u32(&sQh[0][0]) + (uint32_t)(warp * 16 * ARS) + offA;
    const uint32_t aQl = smem_u32(&sQl[0][0]) + (uint32_t)(warp * 16 * ARS) + offA;
    const uint32_t bKh = smem_u32(&sKh[0][0]) + offB;
    const uint32_t bKl = smem_u32(&sKl[0][0]) + offB;
    const uint32_t bVh = smem_u32(&sVh[0][0]) + offB;
    const uint32_t bVl = smem_u32(&sVl[0][0]) + offB;

    for (int k0 = 0; k0 < Nn; k0 += 64) {
        // mask any-check
        int myMask;
        {
            const int row = tid >> 1, half = tid & 1;
            const uint4* mp = reinterpret_cast<const uint4*>(
                &mask[(bn0 + q0 + row) * Nn + k0 + half * 32]);
            uint4 mA = mp[0], mB = mp[1];
            myMask = (mA.x | mA.y | mA.z | mA.w | mB.x | mB.y | mB.z | mB.w) != 0;
        }

        // stage K/V tiles (pure copies)
#pragma unroll
        for (int p = 0; p < 4; p++) {
            const int idx = p * 128 + tid;
            const int row = idx >> 3, u = idx & 7;
            const size_t srcK = hb + (size_t)(k0 + row) * HD + u * 8;
            const size_t srcV = hb + (size_t)row * Nn + k0 + u * 8;
            *reinterpret_cast<uint4*>(&sKh[row][u * 8]) = *reinterpret_cast<const uint4*>(&kh[srcK]);
            *reinterpret_cast<uint4*>(&sKl[row][u * 8]) = *reinterpret_cast<const uint4*>(&kl[srcK]);
            *reinterpret_cast<uint4*>(&sVh[row][u * 8]) = *reinterpret_cast<const uint4*>(&vh[srcV]);
            *reinterpret_cast<uint4*>(&sVl[row][u * 8]) = *reinterpret_cast<const uint4*>(&vl[srcV]);
        }
        if (tid < 64) tks[tid] = t_idx[bn0 + k0 + tid];

        const int tileMasked = __syncthreads_or(myMask);

        // ---- S = Qh.Kh + Qh.Kl + Ql.Kh ----
        float sacc[8][4];
#pragma unroll
        for (int j = 0; j < 8; j++)
#pragma unroll
            for (int e = 0; e < 4; e++) sacc[j][e] = 0.0f;

#pragma unroll
        for (int pass = 0; pass < 3; pass++) {
            const uint32_t aBase = (pass == 2) ? aQl : aQh;
            const uint32_t bBase = (pass == 1) ? bKl : bKh;
#pragma unroll
            for (int kc = 0; kc < 4; kc++) {
                uint32_t aq[4];
                LDSM_X4(aq[0], aq[1], aq[2], aq[3], aBase + (uint32_t)(kc * 32));
#pragma unroll
                for (int g = 0; g < 4; g++) {
                    uint32_t t0, t1, t2, t3;
                    LDSM_X4(t0, t1, t2, t3, bBase + (uint32_t)(g * 16 * ARS + kc * 32));
                    MMA_FP16(sacc[2 * g], aq, t0, t1);
                    MMA_FP16(sacc[2 * g + 1], aq, t2, t3);
                }
            }
        }

        // ---- bias + tile max ----
        float tmax0 = -1e30f, tmax1 = -1e30f;
#pragma unroll
        for (int j = 0; j < 8; j++) {
            const int c0 = 8 * j + 2 * (lane & 3);
            const float tk0 = (float)tks[c0];
            const float tk1 = (float)tks[c0 + 1];
            sacc[j][0] -= a_h * fmaxf(tq0 - tk0, 0.0f);
            sacc[j][1] -= a_h * fmaxf(tq0 - tk1, 0.0f);
            sacc[j][2] -= a_h * fmaxf(tq1 - tk0, 0.0f);
            sacc[j][3] -= a_h * fmaxf(tq1 - tk1, 0.0f);
            tmax0 = fmaxf(tmax0, fmaxf(sacc[j][0], sacc[j][1]));
            tmax1 = fmaxf(tmax1, fmaxf(sacc[j][2], sacc[j][3]));
        }
        tmax0 = fmaxf(tmax0, __shfl_xor_sync(0xFFFFFFFF, tmax0, 1));
        tmax0 = fmaxf(tmax0, __shfl_xor_sync(0xFFFFFFFF, tmax0, 2));
        tmax1 = fmaxf(tmax1, __shfl_xor_sync(0xFFFFFFFF, tmax1, 1));
        tmax1 = fmaxf(tmax1, __shfl_xor_sync(0xFFFFFFFF, tmax1, 2));

        const float mn0 = fmaxf(m0, tmax0);
        const float mn1 = fmaxf(m1, tmax1);
        const float sc0 = __expf(m0 - mn0);
        const float sc1 = __expf(m1 - mn1);
        m0 = mn0; m1 = mn1;
        lsum0 *= sc0; lsum1 *= sc1;
#pragma unroll
        for (int j = 0; j < 8; j++) {
            ctxacc[j][0] *= sc0; ctxacc[j][1] *= sc0;
            ctxacc[j][2] *= sc1; ctxacc[j][3] *= sc1;
        }

        // ---- exp + mask + pack P ----
        uint32_t pa[4][4];
#pragma unroll
        for (int j = 0; j < 8; j++) {
            const int c0 = 8 * j + 2 * (lane & 3);
            float p0 = __expf(sacc[j][0] - m0);
            float p1 = __expf(sacc[j][1] - m0);
            float p2 = __expf(sacc[j][2] - m1);
            float p3 = __expf(sacc[j][3] - m1);
            if (tileMasked) {
                const unsigned char* mr0 = &mask[(bn0 + row_lo) * Nn + k0 + c0];
                const unsigned char* mr1 = &mask[(bn0 + row_hi) * Nn + k0 + c0];
                p0 = mr0[0] ? 0.0f : p0;
                p1 = mr0[1] ? 0.0f : p1;
                p2 = mr1[0] ? 0.0f : p2;
                p3 = mr1[1] ? 0.0f : p3;
            }
            const __half2 lo_h = __float22half2_rn(make_float2(p0, p1));
            const __half2 hi_h = __float22half2_rn(make_float2(p2, p3));
            const float2 lo_r = __half22float2(lo_h);
            const float2 hi_r = __half22float2(hi_h);
            lsum0 += lo_r.x + lo_r.y;
            lsum1 += hi_r.x + hi_r.y;
            pa[j >> 1][(j & 1) * 2 + 0] = h2_as_u32(lo_h);
            pa[j >> 1][(j & 1) * 2 + 1] = h2_as_u32(hi_h);
        }

        // ---- ctx += P x (Vh + Vl) ----
#pragma unroll
        for (int kc = 0; kc < 4; kc++) {
#pragma unroll
            for (int g = 0; g < 4; g++) {
                uint32_t t0, t1, t2, t3;
                LDSM_X4(t0, t1, t2, t3, bVh + (uint32_t)(g * 16 * ARS + kc * 32));
                MMA_FP16(ctxacc[2 * g], pa[kc], t0, t1);
                MMA_FP16(ctxacc[2 * g + 1], pa[kc], t2, t3);
                LDSM_X4(t0, t1, t2, t3, bVl + (uint32_t)(g * 16 * ARS + kc * 32));
                MMA_FP16(ctxacc[2 * g], pa[kc], t0, t1);
                MMA_FP16(ctxacc[2 * g + 1], pa[kc], t2, t3);
            }
        }
        __syncthreads();
    }

    lsum0 += __shfl_xor_sync(0xFFFFFFFF, lsum0, 1);
    lsum0 += __shfl_xor_sync(0xFFFFFFFF, lsum0, 2);
    lsum1 += __shfl_xor_sync(0xFFFFFFFF, lsum1, 1);
    lsum1 += __shfl_xor_sync(0xFFFFFFFF, lsum1, 2);
    const float inv0 = (lsum0 > 0.0f) ? (1.0f / lsum0) : 0.0f;
    const float inv1 = (lsum1 > 0.0f) ? (1.0f / lsum1) : 0.0f;

    // write ctx as bf16 hi/lo (feeds out-projection directly)
#pragma unroll
    for (int j = 0; j < 8; j++) {
        const int c0 = h * HD + 8 * j + 2 * (lane & 3);
        const float o0 = ctxacc[j][0] * inv0, o1 = ctxacc[j][1] * inv0;
        const float o2 = ctxacc[j][2] * inv1, o3 = ctxacc[j][3] * inv1;
        __nv_bfloat16 h0 = __float2bfloat16_rn(o0), h1 = __float2bfloat16_rn(o1);
        __nv_bfloat16 h2 = __float2bfloat16_rn(o2), h3 = __float2bfloat16_rn(o3);
        __nv_bfloat162 hl; hl.x = h0; hl.y = h1;
        __nv_bfloat162 hh; hh.x = h2; hh.y = h3;
        __nv_bfloat162 ll; ll.x = __float2bfloat16_rn(o0 - __bfloat162float(h0));
        ll.y = __float2bfloat16_rn(o1 - __bfloat162float(h1));
        __nv_bfloat162 lh; lh.x = __float2bfloat16_rn(o2 - __bfloat162float(h2));
        lh.y = __float2bfloat16_rn(o3 - __bfloat162float(h3));
        *reinterpret_cast<__nv_bfloat162*>(&ctxh[(bn0 + row_lo) * Dd + c0]) = hl;
        *reinterpret_cast<__nv_bfloat162*>(&ctxh[(bn0 + row_hi) * Dd + c0]) = hh;
        *reinterpret_cast<__nv_bfloat162*>(&ctxl[(bn0 + row_lo) * Dd + c0]) = ll;
        *reinterpret_cast<__nv_bfloat162*>(&ctxl[(bn0 + row_hi) * Dd + c0]) = lh;
    }
}

// ---------------------------------------------------------------------------
extern "C" void kernel_launch(void* const* d_in, const int* in_sizes, int n_in,
                              void* d_out, int out_size) {
    const float*         X     = (const float*)d_in[0];
    const int*           t_idx = (const int*)d_in[1];
    const unsigned char* mask  = (const unsigned char*)d_in[2];
    const float*         Wqkv  = (const float*)d_in[3];
    const float*         bqkv  = (const float*)d_in[4];
    const float*         Wo    = (const float*)d_in[5];
    const float*         bo    = (const float*)d_in[6];
    const float*         alpha = (const float*)d_in[7];
    float*               out   = (float*)d_out;

    void *qkv_p, *xh_p, *xl_p, *wqh_p, *wql_p, *woh_p, *wol_p, *ctxh_p, *ctxl_p;
    void *qh_p, *ql_p, *kh_p, *kl_p, *vh_p, *vl_p;
    cudaGetSymbolAddress(&qkv_p, g_qkv);
    cudaGetSymbolAddress(&xh_p, g_xh);   cudaGetSymbolAddress(&xl_p, g_xl);
    cudaGetSymbolAddress(&wqh_p, g_wqh); cudaGetSymbolAddress(&wql_p, g_wql);
    cudaGetSymbolAddress(&woh_p, g_woh); cudaGetSymbolAddress(&wol_p, g_wol);
    cudaGetSymbolAddress(&ctxh_p, g_ctxh); cudaGetSymbolAddress(&ctxl_p, g_ctxl);
    cudaGetSymbolAddress(&qh_p, g_q16h); cudaGetSymbolAddress(&ql_p, g_q16l);
    cudaGetSymbolAddress(&kh_p, g_k16h); cudaGetSymbolAddress(&kl_p, g_k16l);
    cudaGetSymbolAddress(&vh_p, g_v16h); cudaGetSymbolAddress(&vl_p, g_v16l);

    // prep1: split X, Wqkv, Wo
    split_bf16<<<(BN_ROWS * Dd / 4 + 255) / 256, 256>>>(
        X, (__nv_bfloat16*)xh_p, (__nv_bfloat16*)xl_p, BN_ROWS * Dd / 4);
    split_bf16<<<(QKV_COLS * Dd / 4 + 255) / 256, 256>>>(
        Wqkv, (__nv_bfloat16*)wqh_p, (__nv_bfloat16*)wql_p, QKV_COLS * Dd / 4);
    split_bf16<<<(Dd * Dd / 4 + 255) / 256, 256>>>(
        Wo, (__nv_bfloat16*)woh_p, (__nv_bfloat16*)wol_p, Dd * Dd / 4);

    // 1) QKV projection
    {
        dim3 grid(QKV_COLS / 128, BN_ROWS / 128);
        gemm_sp<<<grid, 256>>>((__nv_bfloat16*)xh_p, (__nv_bfloat16*)xl_p,
                               (__nv_bfloat16*)wqh_p, (__nv_bfloat16*)wql_p,
                               bqkv, (float*)qkv_p, QKV_COLS, Dd);
    }

    // prep2: per-head fp16 split + V transpose
    {
        dim3 grid(Nn / 64, NH);
        attn_prep<<<grid, 128>>>((const float*)qkv_p,
                                 (__half*)qh_p, (__half*)ql_p,
                                 (__half*)kh_p, (__half*)kl_p,
                                 (__half*)vh_p, (__half*)vl_p);
    }

    // 2) Tensor-core flash attention -> ctx (bf16 hi/lo)
    {
        dim3 grid(Nn / 64, Hh, Bb);
        attn_tc<<<grid, 128>>>((const __half*)qh_p, (const __half*)ql_p,
                               (const __half*)kh_p, (const __half*)kl_p,
                               (const __half*)vh_p, (const __half*)vl_p,
                               t_idx, mask, alpha,
                               (__nv_bfloat16*)ctxh_p, (__nv_bfloat16*)ctxl_p);
    }

    // 3) Output projection
    {
        dim3 grid(Dd / 128, BN_ROWS / 128);
        gemm_sp<<<grid, 256>>>((__nv_bfloat16*)ctxh_p, (__nv_bfloat16*)ctxl_p,
                               (__nv_bfloat16*)woh_p, (__nv_bfloat16*)wol_p,
                               bo, out, Dd, Dd);
    }
}

// round 10
// speedup vs baseline: 4.5532x; 1.0013x over previous
#include <cuda_runtime.h>
#include <cuda_bf16.h>
#include <cuda_fp16.h>
#include <cstdint>

// Fixed problem shapes
#define Bb 2
#define Nn 2048
#define Dd 1024
#define Hh 16
#define HD 64
#define BN_ROWS 4096
#define QKV_COLS 3072
#define NH (Bb * Hh)               // 32
#define HSZ (Nn * HD)              // 131072 per (b,h)

// Scratch (device globals: allocation-guard safe)
__device__ float g_qkv[BN_ROWS * QKV_COLS];            // fp32 qkv
__device__ __nv_bfloat16 g_xh[BN_ROWS * Dd], g_xl[BN_ROWS * Dd];
__device__ __nv_bfloat16 g_wqh[QKV_COLS * Dd], g_wql[QKV_COLS * Dd];
__device__ __nv_bfloat16 g_woh[Dd * Dd], g_wol[Dd * Dd];
__device__ __nv_bfloat16 g_ctxh[BN_ROWS * Dd], g_ctxl[BN_ROWS * Dd];
__device__ __half g_q16h[NH * HSZ], g_q16l[NH * HSZ];
__device__ __half g_k16h[NH * HSZ], g_k16l[NH * HSZ];
__device__ __half g_v16h[NH * HSZ], g_v16l[NH * HSZ];  // transposed [bh][hd][n]

// ---------------------------------------------------------------------------
// helpers
// ---------------------------------------------------------------------------
__device__ __forceinline__ uint32_t smem_u32(const void* p) {
    uint32_t a;
    asm("{ .reg .u64 t; cvta.to.shared.u64 t, %1; cvt.u32.u64 %0, t; }" : "=r"(a) : "l"(p));
    return a;
}
__device__ __forceinline__ uint32_t h2_as_u32(__half2 h) {
    return *reinterpret_cast<uint32_t*>(&h);
}

#define LDSM_X4(r0, r1, r2, r3, addr) \
    asm volatile("ldmatrix.sync.aligned.m8n8.x4.shared.b16 {%0,%1,%2,%3}, [%4];" \
                 : "=r"(r0), "=r"(r1), "=r"(r2), "=r"(r3) : "r"(addr))

#define MMA_BF16(d, a, b0, b1) \
    asm volatile("mma.sync.aligned.m16n8k16.row.col.f32.bf16.bf16.f32 " \
                 "{%0,%1,%2,%3},{%4,%5,%6,%7},{%8,%9},{%0,%1,%2,%3};" \
                 : "+f"((d)[0]), "+f"((d)[1]), "+f"((d)[2]), "+f"((d)[3]) \
                 : "r"((a)[0]), "r"((a)[1]), "r"((a)[2]), "r"((a)[3]), \
                   "r"(b0), "r"(b1))

#define MMA_FP16(d, a, b0, b1) \
    asm volatile("mma.sync.aligned.m16n8k16.row.col.f32.f16.f16.f32 " \
                 "{%0,%1,%2,%3},{%4,%5,%6,%7},{%8,%9},{%0,%1,%2,%3};" \
                 : "+f"((d)[0]), "+f"((d)[1]), "+f"((d)[2]), "+f"((d)[3]) \
                 : "r"((a)[0]), "r"((a)[1]), "r"((a)[2]), "r"((a)[3]), \
                   "r"(b0), "r"(b1))

// ---------------------------------------------------------------------------
// prep1: elementwise fp32 -> bf16 hi/lo split
// ---------------------------------------------------------------------------
__global__ __launch_bounds__(256)
void split_bf16(const float* __restrict__ in, __nv_bfloat16* __restrict__ oh,
                __nv_bfloat16* __restrict__ ol, int n4) {
    const int i = blockIdx.x * 256 + threadIdx.x;
    if (i >= n4) return;
    const float4 v = reinterpret_cast<const float4*>(in)[i];
    float f[4] = {v.x, v.y, v.z, v.w};
    __nv_bfloat16 h[4], l[4];
#pragma unroll
    for (int e = 0; e < 4; e++) {
        h[e] = __float2bfloat16_rn(f[e]);
        l[e] = __float2bfloat16_rn(f[e] - __bfloat162float(h[e]));
    }
    __nv_bfloat162 h01; h01.x = h[0]; h01.y = h[1];
    __nv_bfloat162 h23; h23.x = h[2]; h23.y = h[3];
    __nv_bfloat162 l01; l01.x = l[0]; l01.y = l[1];
    __nv_bfloat162 l23; l23.x = l[2]; l23.y = l[3];
    reinterpret_cast<__nv_bfloat162*>(oh)[2 * i]     = h01;
    reinterpret_cast<__nv_bfloat162*>(oh)[2 * i + 1] = h23;
    reinterpret_cast<__nv_bfloat162*>(ol)[2 * i]     = l01;
    reinterpret_cast<__nv_bfloat162*>(ol)[2 * i + 1] = l23;
}

// ---------------------------------------------------------------------------
// prep2: qkv fp32 -> packed per-head fp16 hi/lo (Q scaled 1/8; V transposed)
// grid: (32 n-tiles, 32 bh); 128 threads
// ---------------------------------------------------------------------------
__global__ __launch_bounds__(128)
void attn_prep(const float* __restrict__ qkv,
               __half* __restrict__ qh, __half* __restrict__ ql,
               __half* __restrict__ kh, __half* __restrict__ kl,
               __half* __restrict__ vh, __half* __restrict__ vl) {
    __shared__ float sv[64][65];
    const int tid = threadIdx.x;
    const int nt = blockIdx.x, bh = blockIdx.y;
    const int b = bh >> 4, h = bh & 15;
    const int n0 = nt * 64;
    const size_t obase = (size_t)bh * HSZ;

#pragma unroll
    for (int p = 0; p < 8; p++) {
        const int idx = p * 128 + tid;
        const int row = idx >> 4, c4 = (idx & 15) * 4;
        const size_t src = (size_t)(b * Nn + n0 + row) * QKV_COLS + h * HD + c4;
        // Q (scaled 1/8)
        {
            const float4 v = *reinterpret_cast<const float4*>(&qkv[src]);
            float f[4] = {v.x * 0.125f, v.y * 0.125f, v.z * 0.125f, v.w * 0.125f};
            __half hh[4], ll[4];
#pragma unroll
            for (int e = 0; e < 4; e++) {
                hh[e] = __float2half_rn(f[e]);
                ll[e] = __float2half_rn(f[e] - __half2float(hh[e]));
            }
            const size_t o = obase + (size_t)(n0 + row) * HD + c4;
            *reinterpret_cast<__half2*>(&qh[o])     = __halves2half2(hh[0], hh[1]);
            *reinterpret_cast<__half2*>(&qh[o + 2]) = __halves2half2(hh[2], hh[3]);
            *reinterpret_cast<__half2*>(&ql[o])     = __halves2half2(ll[0], ll[1]);
            *reinterpret_cast<__half2*>(&ql[o + 2]) = __halves2half2(ll[2], ll[3]);
        }
        // K
        {
            const float4 v = *reinterpret_cast<const float4*>(&qkv[src + Dd]);
            float f[4] = {v.x, v.y, v.z, v.w};
            __half hh[4], ll[4];
#pragma unroll
            for (int e = 0; e < 4; e++) {
                hh[e] = __float2half_rn(f[e]);
                ll[e] = __float2half_rn(f[e] - __half2float(hh[e]));
            }
            const size_t o = obase + (size_t)(n0 + row) * HD + c4;
            *reinterpret_cast<__half2*>(&kh[o])     = __halves2half2(hh[0], hh[1]);
            *reinterpret_cast<__half2*>(&kh[o + 2]) = __halves2half2(hh[2], hh[3]);
            *reinterpret_cast<__half2*>(&kl[o])     = __halves2half2(ll[0], ll[1]);
            *reinterpret_cast<__half2*>(&kl[o + 2]) = __halves2half2(ll[2], ll[3]);
        }
        // V -> smem
        {
            const float4 v = *reinterpret_cast<const float4*>(&qkv[src + 2 * Dd]);
            sv[row][c4 + 0] = v.x; sv[row][c4 + 1] = v.y;
            sv[row][c4 + 2] = v.z; sv[row][c4 + 3] = v.w;
        }
    }
    __syncthreads();
    // V transposed write: [hd][n]
#pragma unroll
    for (int p = 0; p < 8; p++) {
        const int idx = p * 128 + tid;
        const int hd = idx >> 4, oc4 = (idx & 15) * 4;
        float f[4] = {sv[oc4 + 0][hd], sv[oc4 + 1][hd], sv[oc4 + 2][hd], sv[oc4 + 3][hd]};
        __half hh[4], ll[4];
#pragma unroll
        for (int e = 0; e < 4; e++) {
            hh[e] = __float2half_rn(f[e]);
            ll[e] = __float2half_rn(f[e] - __half2float(hh[e]));
        }
        const size_t o = obase + (size_t)hd * Nn + n0 + oc4;
        *reinterpret_cast<__half2*>(&vh[o])     = __halves2half2(hh[0], hh[1]);
        *reinterpret_cast<__half2*>(&vh[o + 2]) = __halves2half2(hh[2], hh[3]);
        *reinterpret_cast<__half2*>(&vl[o])     = __halves2half2(ll[0], ll[1]);
        *reinterpret_cast<__half2*>(&vl[o + 2]) = __halves2half2(ll[2], ll[3]);
    }
}

// ---------------------------------------------------------------------------
// bf16x3 GEMM on pre-split inputs: C = A*B^T + bias (mma core validated R4)
// ---------------------------------------------------------------------------
#define BKROW 40   // 80B row stride

__global__ __launch_bounds__(256)
void gemm_sp(const __nv_bfloat16* __restrict__ Ah, const __nv_bfloat16* __restrict__ Al,
             const __nv_bfloat16* __restrict__ Bh, const __nv_bfloat16* __restrict__ Bl,
             const float* __restrict__ bias, float* __restrict__ C,
             int Nc, int K) {
    __shared__ __nv_bfloat16 sAh[128][BKROW];
    __shared__ __nv_bfloat16 sAl[128][BKROW];
    __shared__ __nv_bfloat16 sBh[128][BKROW];
    __shared__ __nv_bfloat16 sBl[128][BKROW];

    const int tid = threadIdx.x;
    const int row0 = blockIdx.y * 128;
    const int col0 = blockIdx.x * 128;
    const int warp = tid >> 5, lane = tid & 31;
    const int wm = warp & 3, wn = warp >> 2;

    const int quad = lane >> 3, r8 = lane & 7;
    const uint32_t offA = (uint32_t)(((quad & 1) * 8 + r8) * 80 + ((quad >> 1) * 8) * 2);
    const uint32_t offB = (uint32_t)(((quad >> 1) * 8 + r8) * 80 + ((quad & 1) * 8) * 2);

    const uint32_t aHiB = smem_u32(&sAh[0][0]) + (uint32_t)(wm * 32 * 80) + offA;
    const uint32_t aLoB = smem_u32(&sAl[0][0]) + (uint32_t)(wm * 32 * 80) + offA;
    const uint32_t bHiB = smem_u32(&sBh[0][0]) + (uint32_t)(wn * 64 * 80) + offB;
    const uint32_t bLoB = smem_u32(&sBl[0][0]) + (uint32_t)(wn * 64 * 80) + offB;

    float acc[2][8][4];
#pragma unroll
    for (int mt = 0; mt < 2; mt++)
#pragma unroll
        for (int j = 0; j < 8; j++)
#pragma unroll
            for (int e = 0; e < 4; e++) acc[mt][j][e] = 0.0f;

    const int nk = K >> 5;
    for (int ks = 0; ks < nk; ks++) {
        const int k0 = ks * 32;
        // pure-copy staging: 128 rows x 32 bf16 per array
#pragma unroll
        for (int p = 0; p < 2; p++) {
            const int idx = p * 256 + tid;
            const int row = idx >> 2, u = idx & 3;
            const size_t ra = (size_t)(row0 + row) * K + k0 + u * 8;
            const size_t rb = (size_t)(col0 + row) * K + k0 + u * 8;
            *reinterpret_cast<uint4*>(&sAh[row][u * 8]) = *reinterpret_cast<const uint4*>(&Ah[ra]);
            *reinterpret_cast<uint4*>(&sAl[row][u * 8]) = *reinterpret_cast<const uint4*>(&Al[ra]);
            *reinterpret_cast<uint4*>(&sBh[row][u * 8]) = *reinterpret_cast<const uint4*>(&Bh[rb]);
            *reinterpret_cast<uint4*>(&sBl[row][u * 8]) = *reinterpret_cast<const uint4*>(&Bl[rb]);
        }
        __syncthreads();

#pragma unroll
        for (int kc = 0; kc < 2; kc++) {
            const uint32_t kadd = (uint32_t)(kc * 32);
            uint32_t ah[2][4], al[2][4], bh[8][2], bl[8][2];
#pragma unroll
            for (int mt = 0; mt < 2; mt++) {
                LDSM_X4(ah[mt][0], ah[mt][1], ah[mt][2], ah[mt][3],
                        aHiB + (uint32_t)(mt * 16 * 80) + kadd);
                LDSM_X4(al[mt][0], al[mt][1], al[mt][2], al[mt][3],
                        aLoB + (uint32_t)(mt * 16 * 80) + kadd);
            }
#pragma unroll
            for (int g = 0; g < 4; g++) {
                uint32_t t0, t1, t2, t3;
                LDSM_X4(t0, t1, t2, t3, bHiB + (uint32_t)(g * 16 * 80) + kadd);
                bh[2 * g][0] = t0; bh[2 * g][1] = t1;
                bh[2 * g + 1][0] = t2; bh[2 * g + 1][1] = t3;
                LDSM_X4(t0, t1, t2, t3, bLoB + (uint32_t)(g * 16 * 80) + kadd);
                bl[2 * g][0] = t0; bl[2 * g][1] = t1;
                bl[2 * g + 1][0] = t2; bl[2 * g + 1][1] = t3;
            }
#pragma unroll
            for (int mt = 0; mt < 2; mt++)
#pragma unroll
                for (int j = 0; j < 8; j++)
                    MMA_BF16(acc[mt][j], ah[mt], bh[j][0], bh[j][1]);
#pragma unroll
            for (int mt = 0; mt < 2; mt++)
#pragma unroll
                for (int j = 0; j < 8; j++)
                    MMA_BF16(acc[mt][j], ah[mt], bl[j][0], bl[j][1]);
#pragma unroll
            for (int mt = 0; mt < 2; mt++)
#pragma unroll
                for (int j = 0; j < 8; j++)
                    MMA_BF16(acc[mt][j], al[mt], bh[j][0], bh[j][1]);
        }
        __syncthreads();
    }

    const int mrow = row0 + wm * 32 + (lane >> 2);
    const int ncol = col0 + wn * 64 + (lane & 3) * 2;
#pragma unroll
    for (int mt = 0; mt < 2; mt++) {
        const int r_up = mrow + mt * 16;
#pragma unroll
        for (int j = 0; j < 8; j++) {
            const int c = ncol + j * 8;
            const float b0 = bias[c], b1 = bias[c + 1];
            float2 v0 = make_float2(acc[mt][j][0] + b0, acc[mt][j][1] + b1);
            float2 v1 = make_float2(acc[mt][j][2] + b0, acc[mt][j][3] + b1);
            *reinterpret_cast<float2*>(&C[(size_t)r_up * Nc + c]) = v0;
            *reinterpret_cast<float2*>(&C[(size_t)(r_up + 8) * Nc + c]) = v1;
        }
    }
}

// ---------------------------------------------------------------------------
// Tensor-core flash attention (pre-split fp16 inputs; logic validated R8).
// Writes ctx directly as bf16 hi/lo for the out-projection.
// ---------------------------------------------------------------------------
#define AROW 72
#define ARS  144

__global__ __launch_bounds__(128)
void attn_tc(const __half* __restrict__ qh, const __half* __restrict__ ql,
             const __half* __restrict__ kh, const __half* __restrict__ kl,
             const __half* __restrict__ vh, const __half* __restrict__ vl,
             const int* __restrict__ t_idx,
             const unsigned char* __restrict__ mask,
             const float* __restrict__ alpha,
             __nv_bfloat16* __restrict__ ctxh, __nv_bfloat16* __restrict__ ctxl) {
    __shared__ __half sQh[64][AROW];
    __shared__ __half sQl[64][AROW];
    __shared__ __half sKh[64][AROW];
    __shared__ __half sKl[64][AROW];
    __shared__ __half sVh[64][AROW];
    __shared__ __half sVl[64][AROW];
    __shared__ int tks[64];

    const int qt = blockIdx.x, h = blockIdx.y, b = blockIdx.z;
    const int tid = threadIdx.x, warp = tid >> 5, lane = tid & 31;
    const int q0 = qt * 64;

    const float a_h = alpha[h];
    const size_t bn0 = (size_t)(b * Nn);
    const size_t hb = (size_t)(b * Hh + h) * HSZ;

    // ---- stage Q (already scaled+split): 64 rows x 8 uint4 per array ----
#pragma unroll
    for (int p = 0; p < 4; p++) {
        const int idx = p * 128 + tid;
        const int row = idx >> 3, u = idx & 7;
        const size_t src = hb + (size_t)(q0 + row) * HD + u * 8;
        *reinterpret_cast<uint4*>(&sQh[row][u * 8]) = *reinterpret_cast<const uint4*>(&qh[src]);
        *reinterpret_cast<uint4*>(&sQl[row][u * 8]) = *reinterpret_cast<const uint4*>(&ql[src]);
    }

    const int g8 = lane >> 2;
    const int row_lo = q0 + warp * 16 + g8;
    const int row_hi = row_lo + 8;
    const float tq0 = (float)t_idx[bn0 + row_lo];
    const float tq1 = (float)t_idx[bn0 + row_hi];

    float ctxacc[8][4];
#pragma unroll
    for (int j = 0; j < 8; j++)
#pragma unroll
        for (int e = 0; e < 4; e++) ctxacc[j][e] = 0.0f;
    float lsum0 = 0.0f, lsum1 = 0.0f;
    float m0 = -1e30f, m1 = -1e30f;

    const int quad = lane >> 3, r8 = lane & 7;
    const uint32_t offA = (uint32_t)(((quad & 1) * 8 + r8) * ARS + ((quad >> 1) * 8) * 2);
    const uint32_t offB = (uint32_t)(((quad >> 1) * 8 + r8) * ARS + ((quad & 1) * 8) * 2);
    const uint32_t aQh = smem_u32(&sQh[0][0]) + (uint32_t)(warp * 16 * ARS) + offA;
    const uint32_t aQl = smem_u32(&sQl[0][0]) + (uint32_t)(warp * 16 * ARS) + offA;
    const uint32_t bKh = smem_u32(&sKh[0][0]) + offB;
    const uint32_t bKl = smem_u32(&sKl[0][0]) + offB;
    const uint32_t bVh = smem_u32(&sVh[0][0]) + offB;
    const uint32_t bVl = smem_u32(&sVl[0][0]) + offB;

    for (int k0 = 0; k0 < Nn; k0 += 64) {
        // mask any-check
        int myMask;
        {
            const int row = tid >> 1, half = tid & 1;
            const uint4* mp = reinterpret_cast<const uint4*>(
                &mask[(bn0 + q0 + row) * Nn + k0 + half * 32]);
            uint4 mA = mp[0], mB = mp[1];
            myMask = (mA.x | mA.y | mA.z | mA.w | mB.x | mB.y | mB.z | mB.w) != 0;
        }

        // stage K/V tiles (pure copies)
#pragma unroll
        for (int p = 0; p < 4; p++) {
            const int idx = p * 128 + tid;
            const int row = idx >> 3, u = idx & 7;
            const size_t srcK = hb + (size_t)(k0 + row) * HD + u * 8;
            const size_t srcV = hb + (size_t)row * Nn + k0 + u * 8;
            *reinterpret_cast<uint4*>(&sKh[row][u * 8]) = *reinterpret_cast<const uint4*>(&kh[srcK]);
            *reinterpret_cast<uint4*>(&sKl[row][u * 8]) = *reinterpret_cast<const uint4*>(&kl[srcK]);
            *reinterpret_cast<uint4*>(&sVh[row][u * 8]) = *reinterpret_cast<const uint4*>(&vh[srcV]);
            *reinterpret_cast<uint4*>(&sVl[row][u * 8]) = *reinterpret_cast<const uint4*>(&vl[srcV]);
        }
        if (tid < 64) tks[tid] = t_idx[bn0 + k0 + tid];

        const int tileMasked = __syncthreads_or(myMask);

        // ---- S = Qh.Kh + Qh.Kl + Ql.Kh ----
        float sacc[8][4];
#pragma unroll
        for (int j = 0; j < 8; j++)
#pragma unroll
            for (int e = 0; e < 4; e++) sacc[j][e] = 0.0f;

#pragma unroll
        for (int pass = 0; pass < 3; pass++) {
            const uint32_t aBase = (pass == 2) ? aQl : aQh;
            const uint32_t bBase = (pass == 1) ? bKl : bKh;
#pragma unroll
            for (int kc = 0; kc < 4; kc++) {
                uint32_t aq[4];
                LDSM_X4(aq[0], aq[1], aq[2], aq[3], aBase + (uint32_t)(kc * 32));
#pragma unroll
                for (int g = 0; g < 4; g++) {
                    uint32_t t0, t1, t2, t3;
                    LDSM_X4(t0, t1, t2, t3, bBase + (uint32_t)(g * 16 * ARS + kc * 32));
                    MMA_FP16(sacc[2 * g], aq, t0, t1);
                    MMA_FP16(sacc[2 * g + 1], aq, t2, t3);
                }
            }
        }

        // ---- bias + tile max ----
        float tmax0 = -1e30f, tmax1 = -1e30f;
#pragma unroll
        for (int j = 0; j < 8; j++) {
            const int c0 = 8 * j + 2 * (lane & 3);
            const float tk0 = (float)tks[c0];
            const float tk1 = (float)tks[c0 + 1];
            sacc[j][0] -= a_h * fmaxf(tq0 - tk0, 0.0f);
            sacc[j][1] -= a_h * fmaxf(tq0 - tk1, 0.0f);
            sacc[j][2] -= a_h * fmaxf(tq1 - tk0, 0.0f);
            sacc[j][3] -= a_h * fmaxf(tq1 - tk1, 0.0f);
            tmax0 = fmaxf(tmax0, fmaxf(sacc[j][0], sacc[j][1]));
            tmax1 = fmaxf(tmax1, fmaxf(sacc[j][2], sacc[j][3]));
        }
        tmax0 = fmaxf(tmax0, __shfl_xor_sync(0xFFFFFFFF, tmax0, 1));
        tmax0 = fmaxf(tmax0, __shfl_xor_sync(0xFFFFFFFF, tmax0, 2));
        tmax1 = fmaxf(tmax1, __shfl_xor_sync(0xFFFFFFFF, tmax1, 1));
        tmax1 = fmaxf(tmax1, __shfl_xor_sync(0xFFFFFFFF, tmax1, 2));

        const float mn0 = fmaxf(m0, tmax0);
        const float mn1 = fmaxf(m1, tmax1);
        const float sc0 = __expf(m0 - mn0);
        const float sc1 = __expf(m1 - mn1);
        m0 = mn0; m1 = mn1;
        lsum0 *= sc0; lsum1 *= sc1;
#pragma unroll
        for (int j = 0; j < 8; j++) {
            ctxacc[j][0] *= sc0; ctxacc[j][1] *= sc0;
            ctxacc[j][2] *= sc1; ctxacc[j][3] *= sc1;
        }

        // ---- exp + mask + pack P ----
        uint32_t pa[4][4];
#pragma unroll
        for (int j = 0; j < 8; j++) {
            const int c0 = 8 * j + 2 * (lane & 3);
            float p0 = __expf(sacc[j][0] - m0);
            float p1 = __expf(sacc[j][1] - m0);
            float p2 = __expf(sacc[j][2] - m1);
            float p3 = __expf(sacc[j][3] - m1);
            if (tileMasked) {
                const unsigned char* mr0 = &mask[(bn0 + row_lo) * Nn + k0 + c0];
                const unsigned char* mr1 = &mask[(bn0 + row_hi) * Nn + k0 + c0];
                p0 = mr0[0] ? 0.0f : p0;
                p1 = mr0[1] ? 0.0f : p1;
                p2 = mr1[0] ? 0.0f : p2;
                p3 = mr1[1] ? 0.0f : p3;
            }
            const __half2 lo_h = __float22half2_rn(make_float2(p0, p1));
            const __half2 hi_h = __float22half2_rn(make_float2(p2, p3));
            const float2 lo_r = __half22float2(lo_h);
            const float2 hi_r = __half22float2(hi_h);
            lsum0 += lo_r.x + lo_r.y;
            lsum1 += hi_r.x + hi_r.y;
            pa[j >> 1][(j & 1) * 2 + 0] = h2_as_u32(lo_h);
            pa[j >> 1][(j & 1) * 2 + 1] = h2_as_u32(hi_h);
        }

        // ---- ctx += P x (Vh + Vl) ----
#pragma unroll
        for (int kc = 0; kc < 4; kc++) {
#pragma unroll
            for (int g = 0; g < 4; g++) {
                uint32_t t0, t1, t2, t3;
                LDSM_X4(t0, t1, t2, t3, bVh + (uint32_t)(g * 16 * ARS + kc * 32));
                MMA_FP16(ctxacc[2 * g], pa[kc], t0, t1);
                MMA_FP16(ctxacc[2 * g + 1], pa[kc], t2, t3);
                LDSM_X4(t0, t1, t2, t3, bVl + (uint32_t)(g * 16 * ARS + kc * 32));
                MMA_FP16(ctxacc[2 * g], pa[kc], t0, t1);
                MMA_FP16(ctxacc[2 * g + 1], pa[kc], t2, t3);
            }
        }
        __syncthreads();
    }

    lsum0 += __shfl_xor_sync(0xFFFFFFFF, lsum0, 1);
    lsum0 += __shfl_xor_sync(0xFFFFFFFF, lsum0, 2);
    lsum1 += __shfl_xor_sync(0xFFFFFFFF, lsum1, 1);
    lsum1 += __shfl_xor_sync(0xFFFFFFFF, lsum1, 2);
    const float inv0 = (lsum0 > 0.0f) ? (1.0f / lsum0) : 0.0f;
    const float inv1 = (lsum1 > 0.0f) ? (1.0f / lsum1) : 0.0f;

    // write ctx as bf16 hi/lo (feeds out-projection directly)
#pragma unroll
    for (int j = 0; j < 8; j++) {
        const int c0 = h * HD + 8 * j + 2 * (lane & 3);
        const float o0 = ctxacc[j][0] * inv0, o1 = ctxacc[j][1] * inv0;
        const float o2 = ctxacc[j][2] * inv1, o3 = ctxacc[j][3] * inv1;
        __nv_bfloat16 h0 = __float2bfloat16_rn(o0), h1 = __float2bfloat16_rn(o1);
        __nv_bfloat16 h2 = __float2bfloat16_rn(o2), h3 = __float2bfloat16_rn(o3);
        __nv_bfloat162 hl; hl.x = h0; hl.y = h1;
        __nv_bfloat162 hh; hh.x = h2; hh.y = h3;
        __nv_bfloat162 ll; ll.x = __float2bfloat16_rn(o0 - __bfloat162float(h0));
        ll.y = __float2bfloat16_rn(o1 - __bfloat162float(h1));
        __nv_bfloat162 lh; lh.x = __float2bfloat16_rn(o2 - __bfloat162float(h2));
        lh.y = __float2bfloat16_rn(o3 - __bfloat162float(h3));
        *reinterpret_cast<__nv_bfloat162*>(&ctxh[(bn0 + row_lo) * Dd + c0]) = hl;
        *reinterpret_cast<__nv_bfloat162*>(&ctxh[(bn0 + row_hi) * Dd + c0]) = hh;
        *reinterpret_cast<__nv_bfloat162*>(&ctxl[(bn0 + row_lo) * Dd + c0]) = ll;
        *reinterpret_cast<__nv_bfloat162*>(&ctxl[(bn0 + row_hi) * Dd + c0]) = lh;
    }
}

// ---------------------------------------------------------------------------
extern "C" void kernel_launch(void* const* d_in, const int* in_sizes, int n_in,
                              void* d_out, int out_size) {
    const float*         X     = (const float*)d_in[0];
    const int*           t_idx = (const int*)d_in[1];
    const unsigned char* mask  = (const unsigned char*)d_in[2];
    const float*         Wqkv  = (const float*)d_in[3];
    const float*         bqkv  = (const float*)d_in[4];
    const float*         Wo    = (const float*)d_in[5];
    const float*         bo    = (const float*)d_in[6];
    const float*         alpha = (const float*)d_in[7];
    float*               out   = (float*)d_out;

    void *qkv_p, *xh_p, *xl_p, *wqh_p, *wql_p, *woh_p, *wol_p, *ctxh_p, *ctxl_p;
    void *qh_p, *ql_p, *kh_p, *kl_p, *vh_p, *vl_p;
    cudaGetSymbolAddress(&qkv_p, g_qkv);
    cudaGetSymbolAddress(&xh_p, g_xh);   cudaGetSymbolAddress(&xl_p, g_xl);
    cudaGetSymbolAddress(&wqh_p, g_wqh); cudaGetSymbolAddress(&wql_p, g_wql);
    cudaGetSymbolAddress(&woh_p, g_woh); cudaGetSymbolAddress(&wol_p, g_wol);
    cudaGetSymbolAddress(&ctxh_p, g_ctxh); cudaGetSymbolAddress(&ctxl_p, g_ctxl);
    cudaGetSymbolAddress(&qh_p, g_q16h); cudaGetSymbolAddress(&ql_p, g_q16l);
    cudaGetSymbolAddress(&kh_p, g_k16h); cudaGetSymbolAddress(&kl_p, g_k16l);
    cudaGetSymbolAddress(&vh_p, g_v16h); cudaGetSymbolAddress(&vl_p, g_v16l);

    // prep1: split X, Wqkv, Wo
    split_bf16<<<(BN_ROWS * Dd / 4 + 255) / 256, 256>>>(
        X, (__nv_bfloat16*)xh_p, (__nv_bfloat16*)xl_p, BN_ROWS * Dd / 4);
    split_bf16<<<(QKV_COLS * Dd / 4 + 255) / 256, 256>>>(
        Wqkv, (__nv_bfloat16*)wqh_p, (__nv_bfloat16*)wql_p, QKV_COLS * Dd / 4);
    split_bf16<<<(Dd * Dd / 4 + 255) / 256, 256>>>(
        Wo, (__nv_bfloat16*)woh_p, (__nv_bfloat16*)wol_p, Dd * Dd / 4);

    // 1) QKV projection
    {
        dim3 grid(QKV_COLS / 128, BN_ROWS / 128);
        gemm_sp<<<grid, 256>>>((__nv_bfloat16*)xh_p, (__nv_bfloat16*)xl_p,
                               (__nv_bfloat16*)wqh_p, (__nv_bfloat16*)wql_p,
                               bqkv, (float*)qkv_p, QKV_COLS, Dd);
    }

    // prep2: per-head fp16 split + V transpose
    {
        dim3 grid(Nn / 64, NH);
        attn_prep<<<grid, 128>>>((const float*)qkv_p,
                                 (__half*)qh_p, (__half*)ql_p,
                                 (__half*)kh_p, (__half*)kl_p,
                                 (__half*)vh_p, (__half*)vl_p);
    }

    // 2) Tensor-core flash attention -> ctx (bf16 hi/lo)
    {
        dim3 grid(Nn / 64, Hh, Bb);
        attn_tc<<<grid, 128>>>((const __half*)qh_p, (const __half*)ql_p,
                               (const __half*)kh_p, (const __half*)kl_p,
                               (const __half*)vh_p, (const __half*)vl_p,
                               t_idx, mask, alpha,
                               (__nv_bfloat16*)ctxh_p, (__nv_bfloat16*)ctxl_p);
    }

    // 3) Output projection
    {
        dim3 grid(Dd / 128, BN_ROWS / 128);
        gemm_sp<<<grid, 256>>>((__nv_bfloat16*)ctxh_p, (__nv_bfloat16*)ctxl_p,
                               (__nv_bfloat16*)woh_p, (__nv_bfloat16*)wol_p,
                               bo, out, Dd, Dd);
    }
}

// round 11
// speedup vs baseline: 4.5602x; 1.0015x over previous
#include <cuda_runtime.h>
#include <cuda_bf16.h>
#include <cuda_fp16.h>
#include <cstdint>

// Fixed problem shapes
#define Bb 2
#define Nn 2048
#define Dd 1024
#define Hh 16
#define HD 64
#define BN_ROWS 4096
#define QKV_COLS 3072
#define NH (Bb * Hh)               // 32
#define HSZ (Nn * HD)              // 131072 per (b,h)

// Scratch (device globals: allocation-guard safe)
__device__ float g_qkv[BN_ROWS * QKV_COLS];            // fp32 qkv
__device__ __nv_bfloat16 g_xh[BN_ROWS * Dd], g_xl[BN_ROWS * Dd];
__device__ __nv_bfloat16 g_wqh[QKV_COLS * Dd], g_wql[QKV_COLS * Dd];
__device__ __nv_bfloat16 g_woh[Dd * Dd], g_wol[Dd * Dd];
__device__ __nv_bfloat16 g_ctxh[BN_ROWS * Dd], g_ctxl[BN_ROWS * Dd];
__device__ __half g_q16h[NH * HSZ], g_q16l[NH * HSZ];
__device__ __half g_k16h[NH * HSZ], g_k16l[NH * HSZ];
__device__ __half g_v16h[NH * HSZ], g_v16l[NH * HSZ];  // transposed [bh][hd][n]

// ---------------------------------------------------------------------------
// helpers
// ---------------------------------------------------------------------------
__device__ __forceinline__ uint32_t smem_u32(const void* p) {
    uint32_t a;
    asm("{ .reg .u64 t; cvta.to.shared.u64 t, %1; cvt.u32.u64 %0, t; }" : "=r"(a) : "l"(p));
    return a;
}
__device__ __forceinline__ uint32_t h2_as_u32(__half2 h) {
    return *reinterpret_cast<uint32_t*>(&h);
}

#define LDSM_X4(r0, r1, r2, r3, addr) \
    asm volatile("ldmatrix.sync.aligned.m8n8.x4.shared.b16 {%0,%1,%2,%3}, [%4];" \
                 : "=r"(r0), "=r"(r1), "=r"(r2), "=r"(r3) : "r"(addr))

#define MMA_BF16(d, a, b0, b1) \
    asm volatile("mma.sync.aligned.m16n8k16.row.col.f32.bf16.bf16.f32 " \
                 "{%0,%1,%2,%3},{%4,%5,%6,%7},{%8,%9},{%0,%1,%2,%3};" \
                 : "+f"((d)[0]), "+f"((d)[1]), "+f"((d)[2]), "+f"((d)[3]) \
                 : "r"((a)[0]), "r"((a)[1]), "r"((a)[2]), "r"((a)[3]), \
                   "r"(b0), "r"(b1))

#define MMA_FP16(d, a, b0, b1) \
    asm volatile("mma.sync.aligned.m16n8k16.row.col.f32.f16.f16.f32 " \
                 "{%0,%1,%2,%3},{%4,%5,%6,%7},{%8,%9},{%0,%1,%2,%3};" \
                 : "+f"((d)[0]), "+f"((d)[1]), "+f"((d)[2]), "+f"((d)[3]) \
                 : "r"((a)[0]), "r"((a)[1]), "r"((a)[2]), "r"((a)[3]), \
                   "r"(b0), "r"(b1))

// ---------------------------------------------------------------------------
// prep1: elementwise fp32 -> bf16 hi/lo split
// ---------------------------------------------------------------------------
__global__ __launch_bounds__(256)
void split_bf16(const float* __restrict__ in, __nv_bfloat16* __restrict__ oh,
                __nv_bfloat16* __restrict__ ol, int n4) {
    const int i = blockIdx.x * 256 + threadIdx.x;
    if (i >= n4) return;
    const float4 v = reinterpret_cast<const float4*>(in)[i];
    float f[4] = {v.x, v.y, v.z, v.w};
    __nv_bfloat16 h[4], l[4];
#pragma unroll
    for (int e = 0; e < 4; e++) {
        h[e] = __float2bfloat16_rn(f[e]);
        l[e] = __float2bfloat16_rn(f[e] - __bfloat162float(h[e]));
    }
    __nv_bfloat162 h01; h01.x = h[0]; h01.y = h[1];
    __nv_bfloat162 h23; h23.x = h[2]; h23.y = h[3];
    __nv_bfloat162 l01; l01.x = l[0]; l01.y = l[1];
    __nv_bfloat162 l23; l23.x = l[2]; l23.y = l[3];
    reinterpret_cast<__nv_bfloat162*>(oh)[2 * i]     = h01;
    reinterpret_cast<__nv_bfloat162*>(oh)[2 * i + 1] = h23;
    reinterpret_cast<__nv_bfloat162*>(ol)[2 * i]     = l01;
    reinterpret_cast<__nv_bfloat162*>(ol)[2 * i + 1] = l23;
}

// ---------------------------------------------------------------------------
// prep2: qkv fp32 -> packed per-head fp16 hi/lo (Q scaled 1/8; V transposed)
// grid: (32 n-tiles, 32 bh); 128 threads
// ---------------------------------------------------------------------------
__global__ __launch_bounds__(128)
void attn_prep(const float* __restrict__ qkv,
               __half* __restrict__ qh, __half* __restrict__ ql,
               __half* __restrict__ kh, __half* __restrict__ kl,
               __half* __restrict__ vh, __half* __restrict__ vl) {
    __shared__ float sv[64][65];
    const int tid = threadIdx.x;
    const int nt = blockIdx.x, bh = blockIdx.y;
    const int b = bh >> 4, h = bh & 15;
    const int n0 = nt * 64;
    const size_t obase = (size_t)bh * HSZ;

#pragma unroll
    for (int p = 0; p < 8; p++) {
        const int idx = p * 128 + tid;
        const int row = idx >> 4, c4 = (idx & 15) * 4;
        const size_t src = (size_t)(b * Nn + n0 + row) * QKV_COLS + h * HD + c4;
        // Q (scaled 1/8)
        {
            const float4 v = *reinterpret_cast<const float4*>(&qkv[src]);
            float f[4] = {v.x * 0.125f, v.y * 0.125f, v.z * 0.125f, v.w * 0.125f};
            __half hh[4], ll[4];
#pragma unroll
            for (int e = 0; e < 4; e++) {
                hh[e] = __float2half_rn(f[e]);
                ll[e] = __float2half_rn(f[e] - __half2float(hh[e]));
            }
            const size_t o = obase + (size_t)(n0 + row) * HD + c4;
            *reinterpret_cast<__half2*>(&qh[o])     = __halves2half2(hh[0], hh[1]);
            *reinterpret_cast<__half2*>(&qh[o + 2]) = __halves2half2(hh[2], hh[3]);
            *reinterpret_cast<__half2*>(&ql[o])     = __halves2half2(ll[0], ll[1]);
            *reinterpret_cast<__half2*>(&ql[o + 2]) = __halves2half2(ll[2], ll[3]);
        }
        // K
        {
            const float4 v = *reinterpret_cast<const float4*>(&qkv[src + Dd]);
            float f[4] = {v.x, v.y, v.z, v.w};
            __half hh[4], ll[4];
#pragma unroll
            for (int e = 0; e < 4; e++) {
                hh[e] = __float2half_rn(f[e]);
                ll[e] = __float2half_rn(f[e] - __half2float(hh[e]));
            }
            const size_t o = obase + (size_t)(n0 + row) * HD + c4;
            *reinterpret_cast<__half2*>(&kh[o])     = __halves2half2(hh[0], hh[1]);
            *reinterpret_cast<__half2*>(&kh[o + 2]) = __halves2half2(hh[2], hh[3]);
            *reinterpret_cast<__half2*>(&kl[o])     = __halves2half2(ll[0], ll[1]);
            *reinterpret_cast<__half2*>(&kl[o + 2]) = __halves2half2(ll[2], ll[3]);
        }
        // V -> smem
        {
            const float4 v = *reinterpret_cast<const float4*>(&qkv[src + 2 * Dd]);
            sv[row][c4 + 0] = v.x; sv[row][c4 + 1] = v.y;
            sv[row][c4 + 2] = v.z; sv[row][c4 + 3] = v.w;
        }
    }
    __syncthreads();
    // V transposed write: [hd][n]
#pragma unroll
    for (int p = 0; p < 8; p++) {
        const int idx = p * 128 + tid;
        const int hd = idx >> 4, oc4 = (idx & 15) * 4;
        float f[4] = {sv[oc4 + 0][hd], sv[oc4 + 1][hd], sv[oc4 + 2][hd], sv[oc4 + 3][hd]};
        __half hh[4], ll[4];
#pragma unroll
        for (int e = 0; e < 4; e++) {
            hh[e] = __float2half_rn(f[e]);
            ll[e] = __float2half_rn(f[e] - __half2float(hh[e]));
        }
        const size_t o = obase + (size_t)hd * Nn + n0 + oc4;
        *reinterpret_cast<__half2*>(&vh[o])     = __halves2half2(hh[0], hh[1]);
        *reinterpret_cast<__half2*>(&vh[o + 2]) = __halves2half2(hh[2], hh[3]);
        *reinterpret_cast<__half2*>(&vl[o])     = __halves2half2(ll[0], ll[1]);
        *reinterpret_cast<__half2*>(&vl[o + 2]) = __halves2half2(ll[2], ll[3]);
    }
}

// ---------------------------------------------------------------------------
// bf16x3 GEMM on pre-split inputs: C = A*B^T + bias (mma core validated R4)
// ---------------------------------------------------------------------------
#define BKROW 40   // 80B row stride

__global__ __launch_bounds__(256)
void gemm_sp(const __nv_bfloat16* __restrict__ Ah, const __nv_bfloat16* __restrict__ Al,
             const __nv_bfloat16* __restrict__ Bh, const __nv_bfloat16* __restrict__ Bl,
             const float* __restrict__ bias, float* __restrict__ C,
             int Nc, int K) {
    __shared__ __nv_bfloat16 sAh[128][BKROW];
    __shared__ __nv_bfloat16 sAl[128][BKROW];
    __shared__ __nv_bfloat16 sBh[128][BKROW];
    __shared__ __nv_bfloat16 sBl[128][BKROW];

    const int tid = threadIdx.x;
    const int row0 = blockIdx.y * 128;
    const int col0 = blockIdx.x * 128;
    const int warp = tid >> 5, lane = tid & 31;
    const int wm = warp & 3, wn = warp >> 2;

    const int quad = lane >> 3, r8 = lane & 7;
    const uint32_t offA = (uint32_t)(((quad & 1) * 8 + r8) * 80 + ((quad >> 1) * 8) * 2);
    const uint32_t offB = (uint32_t)(((quad >> 1) * 8 + r8) * 80 + ((quad & 1) * 8) * 2);

    const uint32_t aHiB = smem_u32(&sAh[0][0]) + (uint32_t)(wm * 32 * 80) + offA;
    const uint32_t aLoB = smem_u32(&sAl[0][0]) + (uint32_t)(wm * 32 * 80) + offA;
    const uint32_t bHiB = smem_u32(&sBh[0][0]) + (uint32_t)(wn * 64 * 80) + offB;
    const uint32_t bLoB = smem_u32(&sBl[0][0]) + (uint32_t)(wn * 64 * 80) + offB;

    float acc[2][8][4];
#pragma unroll
    for (int mt = 0; mt < 2; mt++)
#pragma unroll
        for (int j = 0; j < 8; j++)
#pragma unroll
            for (int e = 0; e < 4; e++) acc[mt][j][e] = 0.0f;

    const int nk = K >> 5;
    for (int ks = 0; ks < nk; ks++) {
        const int k0 = ks * 32;
        // pure-copy staging: 128 rows x 32 bf16 per array
#pragma unroll
        for (int p = 0; p < 2; p++) {
            const int idx = p * 256 + tid;
            const int row = idx >> 2, u = idx & 3;
            const size_t ra = (size_t)(row0 + row) * K + k0 + u * 8;
            const size_t rb = (size_t)(col0 + row) * K + k0 + u * 8;
            *reinterpret_cast<uint4*>(&sAh[row][u * 8]) = *reinterpret_cast<const uint4*>(&Ah[ra]);
            *reinterpret_cast<uint4*>(&sAl[row][u * 8]) = *reinterpret_cast<const uint4*>(&Al[ra]);
            *reinterpret_cast<uint4*>(&sBh[row][u * 8]) = *reinterpret_cast<const uint4*>(&Bh[rb]);
            *reinterpret_cast<uint4*>(&sBl[row][u * 8]) = *reinterpret_cast<const uint4*>(&Bl[rb]);
        }
        __syncthreads();

#pragma unroll
        for (int kc = 0; kc < 2; kc++) {
            const uint32_t kadd = (uint32_t)(kc * 32);
            uint32_t ah[2][4], al[2][4], bh[8][2], bl[8][2];
#pragma unroll
            for (int mt = 0; mt < 2; mt++) {
                LDSM_X4(ah[mt][0], ah[mt][1], ah[mt][2], ah[mt][3],
                        aHiB + (uint32_t)(mt * 16 * 80) + kadd);
                LDSM_X4(al[mt][0], al[mt][1], al[mt][2], al[mt][3],
                        aLoB + (uint32_t)(mt * 16 * 80) + kadd);
            }
#pragma unroll
            for (int g = 0; g < 4; g++) {
                uint32_t t0, t1, t2, t3;
                LDSM_X4(t0, t1, t2, t3, bHiB + (uint32_t)(g * 16 * 80) + kadd);
                bh[2 * g][0] = t0; bh[2 * g][1] = t1;
                bh[2 * g + 1][0] = t2; bh[2 * g + 1][1] = t3;
                LDSM_X4(t0, t1, t2, t3, bLoB + (uint32_t)(g * 16 * 80) + kadd);
                bl[2 * g][0] = t0; bl[2 * g][1] = t1;
                bl[2 * g + 1][0] = t2; bl[2 * g + 1][1] = t3;
            }
#pragma unroll
            for (int mt = 0; mt < 2; mt++)
#pragma unroll
                for (int j = 0; j < 8; j++)
                    MMA_BF16(acc[mt][j], ah[mt], bh[j][0], bh[j][1]);
#pragma unroll
            for (int mt = 0; mt < 2; mt++)
#pragma unroll
                for (int j = 0; j < 8; j++)
                    MMA_BF16(acc[mt][j], ah[mt], bl[j][0], bl[j][1]);
#pragma unroll
            for (int mt = 0; mt < 2; mt++)
#pragma unroll
                for (int j = 0; j < 8; j++)
                    MMA_BF16(acc[mt][j], al[mt], bh[j][0], bh[j][1]);
        }
        __syncthreads();
    }

    const int mrow = row0 + wm * 32 + (lane >> 2);
    const int ncol = col0 + wn * 64 + (lane & 3) * 2;
#pragma unroll
    for (int mt = 0; mt < 2; mt++) {
        const int r_up = mrow + mt * 16;
#pragma unroll
        for (int j = 0; j < 8; j++) {
            const int c = ncol + j * 8;
            const float b0 = bias[c], b1 = bias[c + 1];
            float2 v0 = make_float2(acc[mt][j][0] + b0, acc[mt][j][1] + b1);
            float2 v1 = make_float2(acc[mt][j][2] + b0, acc[mt][j][3] + b1);
            *reinterpret_cast<float2*>(&C[(size_t)r_up * Nc + c]) = v0;
            *reinterpret_cast<float2*>(&C[(size_t)(r_up + 8) * Nc + c]) = v1;
        }
    }
}

// ---------------------------------------------------------------------------
// Tensor-core flash attention (pre-split fp16 inputs; logic validated R8).
// Writes ctx directly as bf16 hi/lo for the out-projection.
// ---------------------------------------------------------------------------
#define AROW 72
#define ARS  144

__global__ __launch_bounds__(128)
void attn_tc(const __half* __restrict__ qh, const __half* __restrict__ ql,
             const __half* __restrict__ kh, const __half* __restrict__ kl,
             const __half* __restrict__ vh, const __half* __restrict__ vl,
             const int* __restrict__ t_idx,
             const unsigned char* __restrict__ mask,
             const float* __restrict__ alpha,
             __nv_bfloat16* __restrict__ ctxh, __nv_bfloat16* __restrict__ ctxl) {
    __shared__ __half sQh[64][AROW];
    __shared__ __half sQl[64][AROW];
    __shared__ __half sKh[64][AROW];
    __shared__ __half sKl[64][AROW];
    __shared__ __half sVh[64][AROW];
    __shared__ __half sVl[64][AROW];
    __shared__ int tks[64];

    const int qt = blockIdx.x, h = blockIdx.y, b = blockIdx.z;
    const int tid = threadIdx.x, warp = tid >> 5, lane = tid & 31;
    const int q0 = qt * 64;

    const float a_h = alpha[h];
    const size_t bn0 = (size_t)(b * Nn);
    const size_t hb = (size_t)(b * Hh + h) * HSZ;

    // ---- stage Q (already scaled+split): 64 rows x 8 uint4 per array ----
#pragma unroll
    for (int p = 0; p < 4; p++) {
        const int idx = p * 128 + tid;
        const int row = idx >> 3, u = idx & 7;
        const size_t src = hb + (size_t)(q0 + row) * HD + u * 8;
        *reinterpret_cast<uint4*>(&sQh[row][u * 8]) = *reinterpret_cast<const uint4*>(&qh[src]);
        *reinterpret_cast<uint4*>(&sQl[row][u * 8]) = *reinterpret_cast<const uint4*>(&ql[src]);
    }

    const int g8 = lane >> 2;
    const int row_lo = q0 + warp * 16 + g8;
    const int row_hi = row_lo + 8;
    const float tq0 = (float)t_idx[bn0 + row_lo];
    const float tq1 = (float)t_idx[bn0 + row_hi];

    float ctxacc[8][4];
#pragma unroll
    for (int j = 0; j < 8; j++)
#pragma unroll
        for (int e = 0; e < 4; e++) ctxacc[j][e] = 0.0f;
    float lsum0 = 0.0f, lsum1 = 0.0f;
    float m0 = -1e30f, m1 = -1e30f;

    const int quad = lane >> 3, r8 = lane & 7;
    const uint32_t offA = (uint32_t)(((quad & 1) * 8 + r8) * ARS + ((quad >> 1) * 8) * 2);
    const uint32_t offB = (uint32_t)(((quad >> 1) * 8 + r8) * ARS + ((quad & 1) * 8) * 2);
    const uint32_t aQh = smem_u32(&sQh[0][0]) + (uint32_t)(warp * 16 * ARS) + offA;
    const uint32_t aQl = smem_u32(&sQl[0][0]) + (uint32_t)(warp * 16 * ARS) + offA;
    const uint32_t bKh = smem_u32(&sKh[0][0]) + offB;
    const uint32_t bKl = smem_u32(&sKl[0][0]) + offB;
    const uint32_t bVh = smem_u32(&sVh[0][0]) + offB;
    const uint32_t bVl = smem_u32(&sVl[0][0]) + offB;

    for (int k0 = 0; k0 < Nn; k0 += 64) {
        // mask any-check
        int myMask;
        {
            const int row = tid >> 1, half = tid & 1;
            const uint4* mp = reinterpret_cast<const uint4*>(
                &mask[(bn0 + q0 + row) * Nn + k0 + half * 32]);
            uint4 mA = mp[0], mB = mp[1];
            myMask = (mA.x | mA.y | mA.z | mA.w | mB.x | mB.y | mB.z | mB.w) != 0;
        }

        // stage K/V tiles (pure copies)
#pragma unroll
        for (int p = 0; p < 4; p++) {
            const int idx = p * 128 + tid;
            const int row = idx >> 3, u = idx & 7;
            const size_t srcK = hb + (size_t)(k0 + row) * HD + u * 8;
            const size_t srcV = hb + (size_t)row * Nn + k0 + u * 8;
            *reinterpret_cast<uint4*>(&sKh[row][u * 8]) = *reinterpret_cast<const uint4*>(&kh[srcK]);
            *reinterpret_cast<uint4*>(&sKl[row][u * 8]) = *reinterpret_cast<const uint4*>(&kl[srcK]);
            *reinterpret_cast<uint4*>(&sVh[row][u * 8]) = *reinterpret_cast<const uint4*>(&vh[srcV]);
            *reinterpret_cast<uint4*>(&sVl[row][u * 8]) = *reinterpret_cast<const uint4*>(&vl[srcV]);
        }
        if (tid < 64) tks[tid] = t_idx[bn0 + k0 + tid];

        const int tileMasked = __syncthreads_or(myMask);

        // ---- S = Qh.Kh + Qh.Kl + Ql.Kh ----
        float sacc[8][4];
#pragma unroll
        for (int j = 0; j < 8; j++)
#pragma unroll
            for (int e = 0; e < 4; e++) sacc[j][e] = 0.0f;

#pragma unroll
        for (int pass = 0; pass < 3; pass++) {
            const uint32_t aBase = (pass == 2) ? aQl : aQh;
            const uint32_t bBase = (pass == 1) ? bKl : bKh;
#pragma unroll
            for (int kc = 0; kc < 4; kc++) {
                uint32_t aq[4];
                LDSM_X4(aq[0], aq[1], aq[2], aq[3], aBase + (uint32_t)(kc * 32));
#pragma unroll
                for (int g = 0; g < 4; g++) {
                    uint32_t t0, t1, t2, t3;
                    LDSM_X4(t0, t1, t2, t3, bBase + (uint32_t)(g * 16 * ARS + kc * 32));
                    MMA_FP16(sacc[2 * g], aq, t0, t1);
                    MMA_FP16(sacc[2 * g + 1], aq, t2, t3);
                }
            }
        }

        // ---- bias + tile max ----
        float tmax0 = -1e30f, tmax1 = -1e30f;
#pragma unroll
        for (int j = 0; j < 8; j++) {
            const int c0 = 8 * j + 2 * (lane & 3);
            const float tk0 = (float)tks[c0];
            const float tk1 = (float)tks[c0 + 1];
            sacc[j][0] -= a_h * fmaxf(tq0 - tk0, 0.0f);
            sacc[j][1] -= a_h * fmaxf(tq0 - tk1, 0.0f);
            sacc[j][2] -= a_h * fmaxf(tq1 - tk0, 0.0f);
            sacc[j][3] -= a_h * fmaxf(tq1 - tk1, 0.0f);
            tmax0 = fmaxf(tmax0, fmaxf(sacc[j][0], sacc[j][1]));
            tmax1 = fmaxf(tmax1, fmaxf(sacc[j][2], sacc[j][3]));
        }
        tmax0 = fmaxf(tmax0, __shfl_xor_sync(0xFFFFFFFF, tmax0, 1));
        tmax0 = fmaxf(tmax0, __shfl_xor_sync(0xFFFFFFFF, tmax0, 2));
        tmax1 = fmaxf(tmax1, __shfl_xor_sync(0xFFFFFFFF, tmax1, 1));
        tmax1 = fmaxf(tmax1, __shfl_xor_sync(0xFFFFFFFF, tmax1, 2));

        const float mn0 = fmaxf(m0, tmax0);
        const float mn1 = fmaxf(m1, tmax1);
        const float sc0 = __expf(m0 - mn0);
        const float sc1 = __expf(m1 - mn1);
        m0 = mn0; m1 = mn1;
        lsum0 *= sc0; lsum1 *= sc1;
#pragma unroll
        for (int j = 0; j < 8; j++) {
            ctxacc[j][0] *= sc0; ctxacc[j][1] *= sc0;
            ctxacc[j][2] *= sc1; ctxacc[j][3] *= sc1;
        }

        // ---- exp + mask + pack P ----
        uint32_t pa[4][4];
#pragma unroll
        for (int j = 0; j < 8; j++) {
            const int c0 = 8 * j + 2 * (lane & 3);
            float p0 = __expf(sacc[j][0] - m0);
            float p1 = __expf(sacc[j][1] - m0);
            float p2 = __expf(sacc[j][2] - m1);
            float p3 = __expf(sacc[j][3] - m1);
            if (tileMasked) {
                const unsigned char* mr0 = &mask[(bn0 + row_lo) * Nn + k0 + c0];
                const unsigned char* mr1 = &mask[(bn0 + row_hi) * Nn + k0 + c0];
                p0 = mr0[0] ? 0.0f : p0;
                p1 = mr0[1] ? 0.0f : p1;
                p2 = mr1[0] ? 0.0f : p2;
                p3 = mr1[1] ? 0.0f : p3;
            }
            const __half2 lo_h = __float22half2_rn(make_float2(p0, p1));
            const __half2 hi_h = __float22half2_rn(make_float2(p2, p3));
            const float2 lo_r = __half22float2(lo_h);
            const float2 hi_r = __half22float2(hi_h);
            lsum0 += lo_r.x + lo_r.y;
            lsum1 += hi_r.x + hi_r.y;
            pa[j >> 1][(j & 1) * 2 + 0] = h2_as_u32(lo_h);
            pa[j >> 1][(j & 1) * 2 + 1] = h2_as_u32(hi_h);
        }

        // ---- ctx += P x (Vh + Vl) ----
#pragma unroll
        for (int kc = 0; kc < 4; kc++) {
#pragma unroll
            for (int g = 0; g < 4; g++) {
                uint32_t t0, t1, t2, t3;
                LDSM_X4(t0, t1, t2, t3, bVh + (uint32_t)(g * 16 * ARS + kc * 32));
                MMA_FP16(ctxacc[2 * g], pa[kc], t0, t1);
                MMA_FP16(ctxacc[2 * g + 1], pa[kc], t2, t3);
                LDSM_X4(t0, t1, t2, t3, bVl + (uint32_t)(g * 16 * ARS + kc * 32));
                MMA_FP16(ctxacc[2 * g], pa[kc], t0, t1);
                MMA_FP16(ctxacc[2 * g + 1], pa[kc], t2, t3);
            }
        }
        __syncthreads();
    }

    lsum0 += __shfl_xor_sync(0xFFFFFFFF, lsum0, 1);
    lsum0 += __shfl_xor_sync(0xFFFFFFFF, lsum0, 2);
    lsum1 += __shfl_xor_sync(0xFFFFFFFF, lsum1, 1);
    lsum1 += __shfl_xor_sync(0xFFFFFFFF, lsum1, 2);
    const float inv0 = (lsum0 > 0.0f) ? (1.0f / lsum0) : 0.0f;
    const float inv1 = (lsum1 > 0.0f) ? (1.0f / lsum1) : 0.0f;

    // write ctx as bf16 hi/lo (feeds out-projection directly)
#pragma unroll
    for (int j = 0; j < 8; j++) {
        const int c0 = h * HD + 8 * j + 2 * (lane & 3);
        const float o0 = ctxacc[j][0] * inv0, o1 = ctxacc[j][1] * inv0;
        const float o2 = ctxacc[j][2] * inv1, o3 = ctxacc[j][3] * inv1;
        __nv_bfloat16 h0 = __float2bfloat16_rn(o0), h1 = __float2bfloat16_rn(o1);
        __nv_bfloat16 h2 = __float2bfloat16_rn(o2), h3 = __float2bfloat16_rn(o3);
        __nv_bfloat162 hl; hl.x = h0; hl.y = h1;
        __nv_bfloat162 hh; hh.x = h2; hh.y = h3;
        __nv_bfloat162 ll; ll.x = __float2bfloat16_rn(o0 - __bfloat162float(h0));
        ll.y = __float2bfloat16_rn(o1 - __bfloat162float(h1));
        __nv_bfloat162 lh; lh.x = __float2bfloat16_rn(o2 - __bfloat162float(h2));
        lh.y = __float2bfloat16_rn(o3 - __bfloat162float(h3));
        *reinterpret_cast<__nv_bfloat162*>(&ctxh[(bn0 + row_lo) * Dd + c0]) = hl;
        *reinterpret_cast<__nv_bfloat162*>(&ctxh[(bn0 + row_hi) * Dd + c0]) = hh;
        *reinterpret_cast<__nv_bfloat162*>(&ctxl[(bn0 + row_lo) * Dd + c0]) = ll;
        *reinterpret_cast<__nv_bfloat162*>(&ctxl[(bn0 + row_hi) * Dd + c0]) = lh;
    }
}

// ---------------------------------------------------------------------------
extern "C" void kernel_launch(void* const* d_in, const int* in_sizes, int n_in,
                              void* d_out, int out_size) {
    const float*         X     = (const float*)d_in[0];
    const int*           t_idx = (const int*)d_in[1];
    const unsigned char* mask  = (const unsigned char*)d_in[2];
    const float*         Wqkv  = (const float*)d_in[3];
    const float*         bqkv  = (const float*)d_in[4];
    const float*         Wo    = (const float*)d_in[5];
    const float*         bo    = (const float*)d_in[6];
    const float*         alpha = (const float*)d_in[7];
    float*               out   = (float*)d_out;

    void *qkv_p, *xh_p, *xl_p, *wqh_p, *wql_p, *woh_p, *wol_p, *ctxh_p, *ctxl_p;
    void *qh_p, *ql_p, *kh_p, *kl_p, *vh_p, *vl_p;
    cudaGetSymbolAddress(&qkv_p, g_qkv);
    cudaGetSymbolAddress(&xh_p, g_xh);   cudaGetSymbolAddress(&xl_p, g_xl);
    cudaGetSymbolAddress(&wqh_p, g_wqh); cudaGetSymbolAddress(&wql_p, g_wql);
    cudaGetSymbolAddress(&woh_p, g_woh); cudaGetSymbolAddress(&wol_p, g_wol);
    cudaGetSymbolAddress(&ctxh_p, g_ctxh); cudaGetSymbolAddress(&ctxl_p, g_ctxl);
    cudaGetSymbolAddress(&qh_p, g_q16h); cudaGetSymbolAddress(&ql_p, g_q16l);
    cudaGetSymbolAddress(&kh_p, g_k16h); cudaGetSymbolAddress(&kl_p, g_k16l);
    cudaGetSymbolAddress(&vh_p, g_v16h); cudaGetSymbolAddress(&vl_p, g_v16l);

    // prep1: split X, Wqkv, Wo
    split_bf16<<<(BN_ROWS * Dd / 4 + 255) / 256, 256>>>(
        X, (__nv_bfloat16*)xh_p, (__nv_bfloat16*)xl_p, BN_ROWS * Dd / 4);
    split_bf16<<<(QKV_COLS * Dd / 4 + 255) / 256, 256>>>(
        Wqkv, (__nv_bfloat16*)wqh_p, (__nv_bfloat16*)wql_p, QKV_COLS * Dd / 4);
    split_bf16<<<(Dd * Dd / 4 + 255) / 256, 256>>>(
        Wo, (__nv_bfloat16*)woh_p, (__nv_bfloat16*)wol_p, Dd * Dd / 4);

    // 1) QKV projection
    {
        dim3 grid(QKV_COLS / 128, BN_ROWS / 128);
        gemm_sp<<<grid, 256>>>((__nv_bfloat16*)xh_p, (__nv_bfloat16*)xl_p,
                               (__nv_bfloat16*)wqh_p, (__nv_bfloat16*)wql_p,
                               bqkv, (float*)qkv_p, QKV_COLS, Dd);
    }

    // prep2: per-head fp16 split + V transpose
    {
        dim3 grid(Nn / 64, NH);
        attn_prep<<<grid, 128>>>((const float*)qkv_p,
                                 (__half*)qh_p, (__half*)ql_p,
                                 (__half*)kh_p, (__half*)kl_p,
                                 (__half*)vh_p, (__half*)vl_p);
    }

    // 2) Tensor-core flash attention -> ctx (bf16 hi/lo)
    {
        dim3 grid(Nn / 64, Hh, Bb);
        attn_tc<<<grid, 128>>>((const __half*)qh_p, (const __half*)ql_p,
                               (const __half*)kh_p, (const __half*)kl_p,
                               (const __half*)vh_p, (const __half*)vl_p,
                               t_idx, mask, alpha,
                               (__nv_bfloat16*)ctxh_p, (__nv_bfloat16*)ctxl_p);
    }

    // 3) Output projection
    {
        dim3 grid(Dd / 128, BN_ROWS / 128);
        gemm_sp<<<grid, 256>>>((__nv_bfloat16*)ctxh_p, (__nv_bfloat16*)ctxl_p,
                               (__nv_bfloat16*)woh_p, (__nv_bfloat16*)wol_p,
                               bo, out, Dd, Dd);
    }
}

// round 12
// speedup vs baseline: 4.6935x; 1.0292x over previous
#include <cuda_runtime.h>
#include <cuda_bf16.h>
#include <cuda_fp16.h>
#include <cstdint>

// Fixed problem shapes
#define Bb 2
#define Nn 2048
#define Dd 1024
#define Hh 16
#define HD 64
#define BN_ROWS 4096
#define QKV_COLS 3072
#define NH (Bb * Hh)
#define HSZ (Nn * HD)

// Scratch (device globals: allocation-guard safe)
__device__ float g_qkv[BN_ROWS * QKV_COLS];
__device__ __nv_bfloat16 g_xh[BN_ROWS * Dd], g_xl[BN_ROWS * Dd];
__device__ __nv_bfloat16 g_wqh[QKV_COLS * Dd], g_wql[QKV_COLS * Dd];
__device__ __nv_bfloat16 g_woh[Dd * Dd], g_wol[Dd * Dd];
__device__ __nv_bfloat16 g_ctxh[BN_ROWS * Dd], g_ctxl[BN_ROWS * Dd];
__device__ __half g_q16h[NH * HSZ], g_q16l[NH * HSZ];
__device__ __half g_k16h[NH * HSZ], g_k16l[NH * HSZ];
__device__ __half g_v16h[NH * HSZ], g_v16l[NH * HSZ];   // [bh][hd][n]

// ---------------------------------------------------------------------------
// helpers
// ---------------------------------------------------------------------------
__device__ __forceinline__ uint32_t smem_u32(const void* p) {
    uint32_t a;
    asm("{ .reg .u64 t; cvta.to.shared.u64 t, %1; cvt.u32.u64 %0, t; }" : "=r"(a) : "l"(p));
    return a;
}
__device__ __forceinline__ uint32_t h2_as_u32(__half2 h) {
    return *reinterpret_cast<uint32_t*>(&h);
}

#define CP16(dst, src) \
    asm volatile("cp.async.cg.shared.global [%0], [%1], 16;" :: "r"(dst), "l"(src))
#define CP_COMMIT() asm volatile("cp.async.commit_group;" ::: "memory")
#define CP_WAIT(n)  asm volatile("cp.async.wait_group %0;" :: "n"(n) : "memory")

#define LDSM_X4(r0, r1, r2, r3, addr) \
    asm volatile("ldmatrix.sync.aligned.m8n8.x4.shared.b16 {%0,%1,%2,%3}, [%4];" \
                 : "=r"(r0), "=r"(r1), "=r"(r2), "=r"(r3) : "r"(addr))

#define MMA_BF16(d, a, b0, b1) \
    asm volatile("mma.sync.aligned.m16n8k16.row.col.f32.bf16.bf16.f32 " \
                 "{%0,%1,%2,%3},{%4,%5,%6,%7},{%8,%9},{%0,%1,%2,%3};" \
                 : "+f"((d)[0]), "+f"((d)[1]), "+f"((d)[2]), "+f"((d)[3]) \
                 : "r"((a)[0]), "r"((a)[1]), "r"((a)[2]), "r"((a)[3]), \
                   "r"(b0), "r"(b1))

#define MMA_FP16(d, a, b0, b1) \
    asm volatile("mma.sync.aligned.m16n8k16.row.col.f32.f16.f16.f32 " \
                 "{%0,%1,%2,%3},{%4,%5,%6,%7},{%8,%9},{%0,%1,%2,%3};" \
                 : "+f"((d)[0]), "+f"((d)[1]), "+f"((d)[2]), "+f"((d)[3]) \
                 : "r"((a)[0]), "r"((a)[1]), "r"((a)[2]), "r"((a)[3]), \
                   "r"(b0), "r"(b1))

// ---------------------------------------------------------------------------
// prep1: elementwise fp32 -> bf16 hi/lo split
// ---------------------------------------------------------------------------
__global__ __launch_bounds__(256)
void split_bf16(const float* __restrict__ in, __nv_bfloat16* __restrict__ oh,
                __nv_bfloat16* __restrict__ ol, int n4) {
    const int i = blockIdx.x * 256 + threadIdx.x;
    if (i >= n4) return;
    const float4 v = reinterpret_cast<const float4*>(in)[i];
    float f[4] = {v.x, v.y, v.z, v.w};
    __nv_bfloat16 h[4], l[4];
#pragma unroll
    for (int e = 0; e < 4; e++) {
        h[e] = __float2bfloat16_rn(f[e]);
        l[e] = __float2bfloat16_rn(f[e] - __bfloat162float(h[e]));
    }
    __nv_bfloat162 h01; h01.x = h[0]; h01.y = h[1];
    __nv_bfloat162 h23; h23.x = h[2]; h23.y = h[3];
    __nv_bfloat162 l01; l01.x = l[0]; l01.y = l[1];
    __nv_bfloat162 l23; l23.x = l[2]; l23.y = l[3];
    reinterpret_cast<__nv_bfloat162*>(oh)[2 * i]     = h01;
    reinterpret_cast<__nv_bfloat162*>(oh)[2 * i + 1] = h23;
    reinterpret_cast<__nv_bfloat162*>(ol)[2 * i]     = l01;
    reinterpret_cast<__nv_bfloat162*>(ol)[2 * i + 1] = l23;
}

// ---------------------------------------------------------------------------
// prep2: qkv fp32 -> packed per-head fp16 hi/lo (Q scaled 1/8; V transposed)
// ---------------------------------------------------------------------------
__global__ __launch_bounds__(128)
void attn_prep(const float* __restrict__ qkv,
               __half* __restrict__ qh, __half* __restrict__ ql,
               __half* __restrict__ kh, __half* __restrict__ kl,
               __half* __restrict__ vh, __half* __restrict__ vl) {
    __shared__ float sv[64][65];
    const int tid = threadIdx.x;
    const int nt = blockIdx.x, bh = blockIdx.y;
    const int b = bh >> 4, h = bh & 15;
    const int n0 = nt * 64;
    const size_t obase = (size_t)bh * HSZ;

#pragma unroll
    for (int p = 0; p < 8; p++) {
        const int idx = p * 128 + tid;
        const int row = idx >> 4, c4 = (idx & 15) * 4;
        const size_t src = (size_t)(b * Nn + n0 + row) * QKV_COLS + h * HD + c4;
        {
            const float4 v = *reinterpret_cast<const float4*>(&qkv[src]);
            float f[4] = {v.x * 0.125f, v.y * 0.125f, v.z * 0.125f, v.w * 0.125f};
            __half hh[4], ll[4];
#pragma unroll
            for (int e = 0; e < 4; e++) {
                hh[e] = __float2half_rn(f[e]);
                ll[e] = __float2half_rn(f[e] - __half2float(hh[e]));
            }
            const size_t o = obase + (size_t)(n0 + row) * HD + c4;
            *reinterpret_cast<__half2*>(&qh[o])     = __halves2half2(hh[0], hh[1]);
            *reinterpret_cast<__half2*>(&qh[o + 2]) = __halves2half2(hh[2], hh[3]);
            *reinterpret_cast<__half2*>(&ql[o])     = __halves2half2(ll[0], ll[1]);
            *reinterpret_cast<__half2*>(&ql[o + 2]) = __halves2half2(ll[2], ll[3]);
        }
        {
            const float4 v = *reinterpret_cast<const float4*>(&qkv[src + Dd]);
            float f[4] = {v.x, v.y, v.z, v.w};
            __half hh[4], ll[4];
#pragma unroll
            for (int e = 0; e < 4; e++) {
                hh[e] = __float2half_rn(f[e]);
                ll[e] = __float2half_rn(f[e] - __half2float(hh[e]));
            }
            const size_t o = obase + (size_t)(n0 + row) * HD + c4;
            *reinterpret_cast<__half2*>(&kh[o])     = __halves2half2(hh[0], hh[1]);
            *reinterpret_cast<__half2*>(&kh[o + 2]) = __halves2half2(hh[2], hh[3]);
            *reinterpret_cast<__half2*>(&kl[o])     = __halves2half2(ll[0], ll[1]);
            *reinterpret_cast<__half2*>(&kl[o + 2]) = __halves2half2(ll[2], ll[3]);
        }
        {
            const float4 v = *reinterpret_cast<const float4*>(&qkv[src + 2 * Dd]);
            sv[row][c4 + 0] = v.x; sv[row][c4 + 1] = v.y;
            sv[row][c4 + 2] = v.z; sv[row][c4 + 3] = v.w;
        }
    }
    __syncthreads();
#pragma unroll
    for (int p = 0; p < 8; p++) {
        const int idx = p * 128 + tid;
        const int hd = idx >> 4, oc4 = (idx & 15) * 4;
        float f[4] = {sv[oc4 + 0][hd], sv[oc4 + 1][hd], sv[oc4 + 2][hd], sv[oc4 + 3][hd]};
        __half hh[4], ll[4];
#pragma unroll
        for (int e = 0; e < 4; e++) {
            hh[e] = __float2half_rn(f[e]);
            ll[e] = __float2half_rn(f[e] - __half2float(hh[e]));
        }
        const size_t o = obase + (size_t)hd * Nn + n0 + oc4;
        *reinterpret_cast<__half2*>(&vh[o])     = __halves2half2(hh[0], hh[1]);
        *reinterpret_cast<__half2*>(&vh[o + 2]) = __halves2half2(hh[2], hh[3]);
        *reinterpret_cast<__half2*>(&vl[o])     = __halves2half2(ll[0], ll[1]);
        *reinterpret_cast<__half2*>(&vl[o + 2]) = __halves2half2(ll[2], ll[3]);
    }
}

// ---------------------------------------------------------------------------
// bf16x3 GEMM, cp.async double-buffered. Dynamic smem: 2 x 40960B.
// ---------------------------------------------------------------------------
#define G_AH 0
#define G_AL 10240
#define G_BH 20480
#define G_BL 30720
#define G_SBUF 40960
#define G_SMEM (2 * G_SBUF)

__global__ __launch_bounds__(256, 2)
void gemm_sp(const __nv_bfloat16* __restrict__ Ah, const __nv_bfloat16* __restrict__ Al,
             const __nv_bfloat16* __restrict__ Bh, const __nv_bfloat16* __restrict__ Bl,
             const float* __restrict__ bias, float* __restrict__ C,
             int Nc, int K) {
    extern __shared__ char dsm[];
    const uint32_t sbase = smem_u32(dsm);

    const int tid = threadIdx.x;
    const int row0 = blockIdx.y * 128;
    const int col0 = blockIdx.x * 128;
    const int warp = tid >> 5, lane = tid & 31;
    const int wm = warp & 3, wn = warp >> 2;

    const int quad = lane >> 3, r8 = lane & 7;
    const uint32_t offA = (uint32_t)(((quad & 1) * 8 + r8) * 80 + ((quad >> 1) * 8) * 2);
    const uint32_t offB = (uint32_t)(((quad >> 1) * 8 + r8) * 80 + ((quad & 1) * 8) * 2);
    const uint32_t aHi0 = sbase + G_AH + (uint32_t)(wm * 32 * 80) + offA;
    const uint32_t aLo0 = sbase + G_AL + (uint32_t)(wm * 32 * 80) + offA;
    const uint32_t bHi0 = sbase + G_BH + (uint32_t)(wn * 64 * 80) + offB;
    const uint32_t bLo0 = sbase + G_BL + (uint32_t)(wn * 64 * 80) + offB;

    // staging indices: 2 phases x (row = idx>>2, u = idx&3)
    const int sr0 = tid >> 2, su = tid & 3;

    float acc[2][8][4];
#pragma unroll
    for (int mt = 0; mt < 2; mt++)
#pragma unroll
        for (int j = 0; j < 8; j++)
#pragma unroll
            for (int e = 0; e < 4; e++) acc[mt][j][e] = 0.0f;

    const int nk = K >> 5;

    // prologue: prefetch tile 0 into buf 0
    {
        const uint32_t st = sbase;
#pragma unroll
        for (int p = 0; p < 2; p++) {
            const int row = sr0 + p * 64;
            const uint32_t d = st + (uint32_t)(row * 80 + su * 16);
            const size_t ra = (size_t)(row0 + row) * K + su * 8;
            const size_t rb = (size_t)(col0 + row) * K + su * 8;
            CP16(d + G_AH, &Ah[ra]);
            CP16(d + G_AL, &Al[ra]);
            CP16(d + G_BH, &Bh[rb]);
            CP16(d + G_BL, &Bl[rb]);
        }
        CP_COMMIT();
    }

    for (int ks = 0; ks < nk; ks++) {
        const uint32_t bufOff = (uint32_t)((ks & 1) * G_SBUF);
        // prefetch next tile
        if (ks + 1 < nk) {
            const uint32_t st = sbase + (uint32_t)(((ks + 1) & 1) * G_SBUF);
            const int k0 = (ks + 1) * 32;
#pragma unroll
            for (int p = 0; p < 2; p++) {
                const int row = sr0 + p * 64;
                const uint32_t d = st + (uint32_t)(row * 80 + su * 16);
                const size_t ra = (size_t)(row0 + row) * K + k0 + su * 8;
                const size_t rb = (size_t)(col0 + row) * K + k0 + su * 8;
                CP16(d + G_AH, &Ah[ra]);
                CP16(d + G_AL, &Al[ra]);
                CP16(d + G_BH, &Bh[rb]);
                CP16(d + G_BL, &Bl[rb]);
            }
            CP_COMMIT();
            CP_WAIT(1);
        } else {
            CP_WAIT(0);
        }
        __syncthreads();

#pragma unroll
        for (int kc = 0; kc < 2; kc++) {
            const uint32_t kadd = bufOff + (uint32_t)(kc * 32);
            uint32_t ah[2][4], al[2][4], bh[8][2], bl[8][2];
#pragma unroll
            for (int mt = 0; mt < 2; mt++) {
                LDSM_X4(ah[mt][0], ah[mt][1], ah[mt][2], ah[mt][3],
                        aHi0 + (uint32_t)(mt * 16 * 80) + kadd);
                LDSM_X4(al[mt][0], al[mt][1], al[mt][2], al[mt][3],
                        aLo0 + (uint32_t)(mt * 16 * 80) + kadd);
            }
#pragma unroll
            for (int g = 0; g < 4; g++) {
                uint32_t t0, t1, t2, t3;
                LDSM_X4(t0, t1, t2, t3, bHi0 + (uint32_t)(g * 16 * 80) + kadd);
                bh[2 * g][0] = t0; bh[2 * g][1] = t1;
                bh[2 * g + 1][0] = t2; bh[2 * g + 1][1] = t3;
                LDSM_X4(t0, t1, t2, t3, bLo0 + (uint32_t)(g * 16 * 80) + kadd);
                bl[2 * g][0] = t0; bl[2 * g][1] = t1;
                bl[2 * g + 1][0] = t2; bl[2 * g + 1][1] = t3;
            }
#pragma unroll
            for (int mt = 0; mt < 2; mt++)
#pragma unroll
                for (int j = 0; j < 8; j++)
                    MMA_BF16(acc[mt][j], ah[mt], bh[j][0], bh[j][1]);
#pragma unroll
            for (int mt = 0; mt < 2; mt++)
#pragma unroll
                for (int j = 0; j < 8; j++)
                    MMA_BF16(acc[mt][j], ah[mt], bl[j][0], bl[j][1]);
#pragma unroll
            for (int mt = 0; mt < 2; mt++)
#pragma unroll
                for (int j = 0; j < 8; j++)
                    MMA_BF16(acc[mt][j], al[mt], bh[j][0], bh[j][1]);
        }
        __syncthreads();
    }

    const int mrow = row0 + wm * 32 + (lane >> 2);
    const int ncol = col0 + wn * 64 + (lane & 3) * 2;
#pragma unroll
    for (int mt = 0; mt < 2; mt++) {
        const int r_up = mrow + mt * 16;
#pragma unroll
        for (int j = 0; j < 8; j++) {
            const int c = ncol + j * 8;
            const float b0 = bias[c], b1 = bias[c + 1];
            float2 v0 = make_float2(acc[mt][j][0] + b0, acc[mt][j][1] + b1);
            float2 v1 = make_float2(acc[mt][j][2] + b0, acc[mt][j][3] + b1);
            *reinterpret_cast<float2*>(&C[(size_t)r_up * Nc + c]) = v0;
            *reinterpret_cast<float2*>(&C[(size_t)(r_up + 8) * Nc + c]) = v1;
        }
    }
}

// ---------------------------------------------------------------------------
// Tensor-core flash attention, cp.async double-buffered K/V.
// Dynamic smem: Q (2 x 9216) + 2 bufs x (4 x 9216) = 92160B.
// ---------------------------------------------------------------------------
#define AROW 72
#define ARS  144
#define A_QH 0
#define A_QL 9216
#define A_KV 18432
#define A_KH 0
#define A_KL 9216
#define A_VH 18432
#define A_VL 27648
#define A_VBUF 36864
#define A_SMEM (A_KV + 2 * A_VBUF)   // 92160

__global__ __launch_bounds__(128)
void attn_tc(const __half* __restrict__ qh, const __half* __restrict__ ql,
             const __half* __restrict__ kh, const __half* __restrict__ kl,
             const __half* __restrict__ vh, const __half* __restrict__ vl,
             const int* __restrict__ t_idx,
             const unsigned char* __restrict__ mask,
             const float* __restrict__ alpha,
             __nv_bfloat16* __restrict__ ctxh, __nv_bfloat16* __restrict__ ctxl) {
    extern __shared__ char dsm[];
    __shared__ int tks2[2][64];
    const uint32_t sbase = smem_u32(dsm);

    const int qt = blockIdx.x, h = blockIdx.y, b = blockIdx.z;
    const int tid = threadIdx.x, warp = tid >> 5, lane = tid & 31;
    const int q0 = qt * 64;

    const float a_h = alpha[h];
    const size_t bn0 = (size_t)(b * Nn);
    const size_t hb = (size_t)(b * Hh + h) * HSZ;

    // staging indices: row = idx>>3 (per phase p<4), u = idx&7
    const int sr0 = tid >> 3, su = tid & 7;

    // ---- stage Q once (regular stores) ----
#pragma unroll
    for (int p = 0; p < 4; p++) {
        const int idx = p * 128 + tid;
        const int row = idx >> 3, u = idx & 7;
        const size_t src = hb + (size_t)(q0 + row) * HD + u * 8;
        *reinterpret_cast<uint4*>(dsm + A_QH + row * ARS + u * 16) =
            *reinterpret_cast<const uint4*>(&qh[src]);
        *reinterpret_cast<uint4*>(dsm + A_QL + row * ARS + u * 16) =
            *reinterpret_cast<const uint4*>(&ql[src]);
    }

    const int g8 = lane >> 2;
    const int row_lo = q0 + warp * 16 + g8;
    const int row_hi = row_lo + 8;
    const float tq0 = (float)t_idx[bn0 + row_lo];
    const float tq1 = (float)t_idx[bn0 + row_hi];

    float ctxacc[8][4];
#pragma unroll
    for (int j = 0; j < 8; j++)
#pragma unroll
        for (int e = 0; e < 4; e++) ctxacc[j][e] = 0.0f;
    float lsum0 = 0.0f, lsum1 = 0.0f;
    float m0 = -1e30f, m1 = -1e30f;

    const int quad = lane >> 3, r8 = lane & 7;
    const uint32_t offA = (uint32_t)(((quad & 1) * 8 + r8) * ARS + ((quad >> 1) * 8) * 2);
    const uint32_t offB = (uint32_t)(((quad >> 1) * 8 + r8) * ARS + ((quad & 1) * 8) * 2);
    const uint32_t aQh = sbase + A_QH + (uint32_t)(warp * 16 * ARS) + offA;
    const uint32_t aQl = sbase + A_QL + (uint32_t)(warp * 16 * ARS) + offA;

    // ---- prologue: prefetch K/V tile 0 into buf 0; stage tks(0) ----
    {
        const uint32_t st = sbase + A_KV;
#pragma unroll
        for (int p = 0; p < 4; p++) {
            const int row = sr0 + p * 16;
            const uint32_t d = st + (uint32_t)(row * ARS + su * 16);
            const size_t srcK = hb + (size_t)row * HD + su * 8;
            const size_t srcV = hb + (size_t)row * Nn + su * 8;
            CP16(d + A_KH, &kh[srcK]);
            CP16(d + A_KL, &kl[srcK]);
            CP16(d + A_VH, &vh[srcV]);
            CP16(d + A_VL, &vl[srcV]);
        }
        CP_COMMIT();
        if (tid < 64) tks2[0][tid] = t_idx[bn0 + tid];
    }

    for (int it = 0; it < Nn / 64; it++) {
        const int k0 = it * 64;
        const uint32_t kvOff = (uint32_t)((it & 1) * A_VBUF);

        // prefetch next tile + tks
        if (it + 1 < Nn / 64) {
            const int kn = (it + 1) * 64;
            const uint32_t st = sbase + A_KV + (uint32_t)(((it + 1) & 1) * A_VBUF);
#pragma unroll
            for (int p = 0; p < 4; p++) {
                const int row = sr0 + p * 16;
                const uint32_t d = st + (uint32_t)(row * ARS + su * 16);
                const size_t srcK = hb + (size_t)(kn + row) * HD + su * 8;
                const size_t srcV = hb + (size_t)row * Nn + kn + su * 8;
                CP16(d + A_KH, &kh[srcK]);
                CP16(d + A_KL, &kl[srcK]);
                CP16(d + A_VH, &vh[srcV]);
                CP16(d + A_VL, &vl[srcV]);
            }
            CP_COMMIT();
            if (tid < 64) tks2[(it + 1) & 1][tid] = t_idx[bn0 + kn + tid];
        }

        // mask any-check for this tile
        int myMask;
        {
            const int row = tid >> 1, half = tid & 1;
            const uint4* mp = reinterpret_cast<const uint4*>(
                &mask[(bn0 + q0 + row) * Nn + k0 + half * 32]);
            uint4 mA = mp[0], mB = mp[1];
            myMask = (mA.x | mA.y | mA.z | mA.w | mB.x | mB.y | mB.z | mB.w) != 0;
        }

        if (it + 1 < Nn / 64) { CP_WAIT(1); } else { CP_WAIT(0); }
        const int tileMasked = __syncthreads_or(myMask);

        const uint32_t bKh = sbase + A_KV + kvOff + A_KH + offB;
        const uint32_t bKl = sbase + A_KV + kvOff + A_KL + offB;
        const uint32_t bVh = sbase + A_KV + kvOff + A_VH + offB;
        const uint32_t bVl = sbase + A_KV + kvOff + A_VL + offB;
        const int* tks = tks2[it & 1];

        // ---- S = Qh.Kh + Qh.Kl + Ql.Kh ----
        float sacc[8][4];
#pragma unroll
        for (int j = 0; j < 8; j++)
#pragma unroll
            for (int e = 0; e < 4; e++) sacc[j][e] = 0.0f;

#pragma unroll
        for (int pass = 0; pass < 3; pass++) {
            const uint32_t aBase = (pass == 2) ? aQl : aQh;
            const uint32_t bBase = (pass == 1) ? bKl : bKh;
#pragma unroll
            for (int kc = 0; kc < 4; kc++) {
                uint32_t aq[4];
                LDSM_X4(aq[0], aq[1], aq[2], aq[3], aBase + (uint32_t)(kc * 32));
#pragma unroll
                for (int g = 0; g < 4; g++) {
                    uint32_t t0, t1, t2, t3;
                    LDSM_X4(t0, t1, t2, t3, bBase + (uint32_t)(g * 16 * ARS + kc * 32));
                    MMA_FP16(sacc[2 * g], aq, t0, t1);
                    MMA_FP16(sacc[2 * g + 1], aq, t2, t3);
                }
            }
        }

        // ---- bias + tile max ----
        float tmax0 = -1e30f, tmax1 = -1e30f;
#pragma unroll
        for (int j = 0; j < 8; j++) {
            const int c0 = 8 * j + 2 * (lane & 3);
            const float tk0 = (float)tks[c0];
            const float tk1 = (float)tks[c0 + 1];
            sacc[j][0] -= a_h * fmaxf(tq0 - tk0, 0.0f);
            sacc[j][1] -= a_h * fmaxf(tq0 - tk1, 0.0f);
            sacc[j][2] -= a_h * fmaxf(tq1 - tk0, 0.0f);
            sacc[j][3] -= a_h * fmaxf(tq1 - tk1, 0.0f);
            tmax0 = fmaxf(tmax0, fmaxf(sacc[j][0], sacc[j][1]));
            tmax1 = fmaxf(tmax1, fmaxf(sacc[j][2], sacc[j][3]));
        }
        tmax0 = fmaxf(tmax0, __shfl_xor_sync(0xFFFFFFFF, tmax0, 1));
        tmax0 = fmaxf(tmax0, __shfl_xor_sync(0xFFFFFFFF, tmax0, 2));
        tmax1 = fmaxf(tmax1, __shfl_xor_sync(0xFFFFFFFF, tmax1, 1));
        tmax1 = fmaxf(tmax1, __shfl_xor_sync(0xFFFFFFFF, tmax1, 2));

        const float mn0 = fmaxf(m0, tmax0);
        const float mn1 = fmaxf(m1, tmax1);
        const float sc0 = __expf(m0 - mn0);
        const float sc1 = __expf(m1 - mn1);
        m0 = mn0; m1 = mn1;
        lsum0 *= sc0; lsum1 *= sc1;
#pragma unroll
        for (int j = 0; j < 8; j++) {
            ctxacc[j][0] *= sc0; ctxacc[j][1] *= sc0;
            ctxacc[j][2] *= sc1; ctxacc[j][3] *= sc1;
        }

        // ---- exp + mask + pack P ----
        uint32_t pa[4][4];
#pragma unroll
        for (int j = 0; j < 8; j++) {
            const int c0 = 8 * j + 2 * (lane & 3);
            float p0 = __expf(sacc[j][0] - m0);
            float p1 = __expf(sacc[j][1] - m0);
            float p2 = __expf(sacc[j][2] - m1);
            float p3 = __expf(sacc[j][3] - m1);
            if (tileMasked) {
                const unsigned char* mr0 = &mask[(bn0 + row_lo) * Nn + k0 + c0];
                const unsigned char* mr1 = &mask[(bn0 + row_hi) * Nn + k0 + c0];
                p0 = mr0[0] ? 0.0f : p0;
                p1 = mr0[1] ? 0.0f : p1;
                p2 = mr1[0] ? 0.0f : p2;
                p3 = mr1[1] ? 0.0f : p3;
            }
            const __half2 lo_h = __float22half2_rn(make_float2(p0, p1));
            const __half2 hi_h = __float22half2_rn(make_float2(p2, p3));
            const float2 lo_r = __half22float2(lo_h);
            const float2 hi_r = __half22float2(hi_h);
            lsum0 += lo_r.x + lo_r.y;
            lsum1 += hi_r.x + hi_r.y;
            pa[j >> 1][(j & 1) * 2 + 0] = h2_as_u32(lo_h);
            pa[j >> 1][(j & 1) * 2 + 1] = h2_as_u32(hi_h);
        }

        // ---- ctx += P x (Vh + Vl) ----
#pragma unroll
        for (int kc = 0; kc < 4; kc++) {
#pragma unroll
            for (int g = 0; g < 4; g++) {
                uint32_t t0, t1, t2, t3;
                LDSM_X4(t0, t1, t2, t3, bVh + (uint32_t)(g * 16 * ARS + kc * 32));
                MMA_FP16(ctxacc[2 * g], pa[kc], t0, t1);
                MMA_FP16(ctxacc[2 * g + 1], pa[kc], t2, t3);
                LDSM_X4(t0, t1, t2, t3, bVl + (uint32_t)(g * 16 * ARS + kc * 32));
                MMA_FP16(ctxacc[2 * g], pa[kc], t0, t1);
                MMA_FP16(ctxacc[2 * g + 1], pa[kc], t2, t3);
            }
        }
        __syncthreads();
    }

    lsum0 += __shfl_xor_sync(0xFFFFFFFF, lsum0, 1);
    lsum0 += __shfl_xor_sync(0xFFFFFFFF, lsum0, 2);
    lsum1 += __shfl_xor_sync(0xFFFFFFFF, lsum1, 1);
    lsum1 += __shfl_xor_sync(0xFFFFFFFF, lsum1, 2);
    const float inv0 = (lsum0 > 0.0f) ? (1.0f / lsum0) : 0.0f;
    const float inv1 = (lsum1 > 0.0f) ? (1.0f / lsum1) : 0.0f;

#pragma unroll
    for (int j = 0; j < 8; j++) {
        const int c0 = h * HD + 8 * j + 2 * (lane & 3);
        const float o0 = ctxacc[j][0] * inv0, o1 = ctxacc[j][1] * inv0;
        const float o2 = ctxacc[j][2] * inv1, o3 = ctxacc[j][3] * inv1;
        __nv_bfloat16 h0 = __float2bfloat16_rn(o0), h1 = __float2bfloat16_rn(o1);
        __nv_bfloat16 h2 = __float2bfloat16_rn(o2), h3 = __float2bfloat16_rn(o3);
        __nv_bfloat162 hl; hl.x = h0; hl.y = h1;
        __nv_bfloat162 hh; hh.x = h2; hh.y = h3;
        __nv_bfloat162 ll; ll.x = __float2bfloat16_rn(o0 - __bfloat162float(h0));
        ll.y = __float2bfloat16_rn(o1 - __bfloat162float(h1));
        __nv_bfloat162 lh; lh.x = __float2bfloat16_rn(o2 - __bfloat162float(h2));
        lh.y = __float2bfloat16_rn(o3 - __bfloat162float(h3));
        *reinterpret_cast<__nv_bfloat162*>(&ctxh[(bn0 + row_lo) * Dd + c0]) = hl;
        *reinterpret_cast<__nv_bfloat162*>(&ctxh[(bn0 + row_hi) * Dd + c0]) = hh;
        *reinterpret_cast<__nv_bfloat162*>(&ctxl[(bn0 + row_lo) * Dd + c0]) = ll;
        *reinterpret_cast<__nv_bfloat162*>(&ctxl[(bn0 + row_hi) * Dd + c0]) = lh;
    }
}

// ---------------------------------------------------------------------------
extern "C" void kernel_launch(void* const* d_in, const int* in_sizes, int n_in,
                              void* d_out, int out_size) {
    const float*         X     = (const float*)d_in[0];
    const int*           t_idx = (const int*)d_in[1];
    const unsigned char* mask  = (const unsigned char*)d_in[2];
    const float*         Wqkv  = (const float*)d_in[3];
    const float*         bqkv  = (const float*)d_in[4];
    const float*         Wo    = (const float*)d_in[5];
    const float*         bo    = (const float*)d_in[6];
    const float*         alpha = (const float*)d_in[7];
    float*               out   = (float*)d_out;

    void *qkv_p, *xh_p, *xl_p, *wqh_p, *wql_p, *woh_p, *wol_p, *ctxh_p, *ctxl_p;
    void *qh_p, *ql_p, *kh_p, *kl_p, *vh_p, *vl_p;
    cudaGetSymbolAddress(&qkv_p, g_qkv);
    cudaGetSymbolAddress(&xh_p, g_xh);   cudaGetSymbolAddress(&xl_p, g_xl);
    cudaGetSymbolAddress(&wqh_p, g_wqh); cudaGetSymbolAddress(&wql_p, g_wql);
    cudaGetSymbolAddress(&woh_p, g_woh); cudaGetSymbolAddress(&wol_p, g_wol);
    cudaGetSymbolAddress(&ctxh_p, g_ctxh); cudaGetSymbolAddress(&ctxl_p, g_ctxl);
    cudaGetSymbolAddress(&qh_p, g_q16h); cudaGetSymbolAddress(&ql_p, g_q16l);
    cudaGetSymbolAddress(&kh_p, g_k16h); cudaGetSymbolAddress(&kl_p, g_k16l);
    cudaGetSymbolAddress(&vh_p, g_v16h); cudaGetSymbolAddress(&vl_p, g_v16l);

    cudaFuncSetAttribute(gemm_sp, cudaFuncAttributeMaxDynamicSharedMemorySize, G_SMEM);
    cudaFuncSetAttribute(attn_tc, cudaFuncAttributeMaxDynamicSharedMemorySize, A_SMEM);

    // prep1: split X, Wqkv, Wo
    split_bf16<<<(BN_ROWS * Dd / 4 + 255) / 256, 256>>>(
        X, (__nv_bfloat16*)xh_p, (__nv_bfloat16*)xl_p, BN_ROWS * Dd / 4);
    split_bf16<<<(QKV_COLS * Dd / 4 + 255) / 256, 256>>>(
        Wqkv, (__nv_bfloat16*)wqh_p, (__nv_bfloat16*)wql_p, QKV_COLS * Dd / 4);
    split_bf16<<<(Dd * Dd / 4 + 255) / 256, 256>>>(
        Wo, (__nv_bfloat16*)woh_p, (__nv_bfloat16*)wol_p, Dd * Dd / 4);

    // 1) QKV projection
    {
        dim3 grid(QKV_COLS / 128, BN_ROWS / 128);
        gemm_sp<<<grid, 256, G_SMEM>>>((__nv_bfloat16*)xh_p, (__nv_bfloat16*)xl_p,
                                       (__nv_bfloat16*)wqh_p, (__nv_bfloat16*)wql_p,
                                       bqkv, (float*)qkv_p, QKV_COLS, Dd);
    }

    // prep2: per-head fp16 split + V transpose
    {
        dim3 grid(Nn / 64, NH);
        attn_prep<<<grid, 128>>>((const float*)qkv_p,
                                 (__half*)qh_p, (__half*)ql_p,
                                 (__half*)kh_p, (__half*)kl_p,
                                 (__half*)vh_p, (__half*)vl_p);
    }

    // 2) Tensor-core flash attention -> ctx (bf16 hi/lo)
    {
        dim3 grid(Nn / 64, Hh, Bb);
        attn_tc<<<grid, 128, A_SMEM>>>((const __half*)qh_p, (const __half*)ql_p,
                                       (const __half*)kh_p, (const __half*)kl_p,
                                       (const __half*)vh_p, (const __half*)vl_p,
                                       t_idx, mask, alpha,
                                       (__nv_bfloat16*)ctxh_p, (__nv_bfloat16*)ctxl_p);
    }

    // 3) Output projection
    {
        dim3 grid(Dd / 128, BN_ROWS / 128);
        gemm_sp<<<grid, 256, G_SMEM>>>((__nv_bfloat16*)ctxh_p, (__nv_bfloat16*)ctxl_p,
                                       (__nv_bfloat16*)woh_p, (__nv_bfloat16*)wol_p,
                                       bo, out, Dd, Dd);
    }
}

// round 13
// speedup vs baseline: 5.2549x; 1.1196x over previous
#include <cuda_runtime.h>
#include <cuda_bf16.h>
#include <cuda_fp16.h>
#include <cstdint>

// Fixed problem shapes
#define Bb 2
#define Nn 2048
#define Dd 1024
#define Hh 16
#define HD 64
#define BN_ROWS 4096
#define QKV_COLS 3072
#define NH (Bb * Hh)
#define HSZ (Nn * HD)

// Scratch (device globals: allocation-guard safe)
__device__ float g_qkv[BN_ROWS * QKV_COLS];
__device__ __nv_bfloat16 g_xh[BN_ROWS * Dd], g_xl[BN_ROWS * Dd];
__device__ __nv_bfloat16 g_wqh[QKV_COLS * Dd], g_wql[QKV_COLS * Dd];
__device__ __nv_bfloat16 g_woh[Dd * Dd], g_wol[Dd * Dd];
__device__ __nv_bfloat16 g_ctxh[BN_ROWS * Dd], g_ctxl[BN_ROWS * Dd];
__device__ __half g_q16h[NH * HSZ];
__device__ __half g_k16h[NH * HSZ], g_k16l[NH * HSZ];
__device__ __half g_v16h[NH * HSZ];                     // [bh][hd][n]

// ---------------------------------------------------------------------------
// helpers
// ---------------------------------------------------------------------------
__device__ __forceinline__ uint32_t smem_u32(const void* p) {
    uint32_t a;
    asm("{ .reg .u64 t; cvta.to.shared.u64 t, %1; cvt.u32.u64 %0, t; }" : "=r"(a) : "l"(p));
    return a;
}
__device__ __forceinline__ uint32_t h2_as_u32(__half2 h) {
    return *reinterpret_cast<uint32_t*>(&h);
}

#define CP16(dst, src) \
    asm volatile("cp.async.cg.shared.global [%0], [%1], 16;" :: "r"(dst), "l"(src))
#define CP_COMMIT() asm volatile("cp.async.commit_group;" ::: "memory")
#define CP_WAIT(n)  asm volatile("cp.async.wait_group %0;" :: "n"(n) : "memory")

#define LDSM_X4(r0, r1, r2, r3, addr) \
    asm volatile("ldmatrix.sync.aligned.m8n8.x4.shared.b16 {%0,%1,%2,%3}, [%4];" \
                 : "=r"(r0), "=r"(r1), "=r"(r2), "=r"(r3) : "r"(addr))

#define MMA_BF16(d, a, b0, b1) \
    asm volatile("mma.sync.aligned.m16n8k16.row.col.f32.bf16.bf16.f32 " \
                 "{%0,%1,%2,%3},{%4,%5,%6,%7},{%8,%9},{%0,%1,%2,%3};" \
                 : "+f"((d)[0]), "+f"((d)[1]), "+f"((d)[2]), "+f"((d)[3]) \
                 : "r"((a)[0]), "r"((a)[1]), "r"((a)[2]), "r"((a)[3]), \
                   "r"(b0), "r"(b1))

#define MMA_FP16(d, a, b0, b1) \
    asm volatile("mma.sync.aligned.m16n8k16.row.col.f32.f16.f16.f32 " \
                 "{%0,%1,%2,%3},{%4,%5,%6,%7},{%8,%9},{%0,%1,%2,%3};" \
                 : "+f"((d)[0]), "+f"((d)[1]), "+f"((d)[2]), "+f"((d)[3]) \
                 : "r"((a)[0]), "r"((a)[1]), "r"((a)[2]), "r"((a)[3]), \
                   "r"(b0), "r"(b1))

// ---------------------------------------------------------------------------
// prep1: elementwise fp32 -> bf16 hi/lo split
// ---------------------------------------------------------------------------
__global__ __launch_bounds__(256)
void split_bf16(const float* __restrict__ in, __nv_bfloat16* __restrict__ oh,
                __nv_bfloat16* __restrict__ ol, int n4) {
    const int i = blockIdx.x * 256 + threadIdx.x;
    if (i >= n4) return;
    const float4 v = reinterpret_cast<const float4*>(in)[i];
    float f[4] = {v.x, v.y, v.z, v.w};
    __nv_bfloat16 h[4], l[4];
#pragma unroll
    for (int e = 0; e < 4; e++) {
        h[e] = __float2bfloat16_rn(f[e]);
        l[e] = __float2bfloat16_rn(f[e] - __bfloat162float(h[e]));
    }
    __nv_bfloat162 h01; h01.x = h[0]; h01.y = h[1];
    __nv_bfloat162 h23; h23.x = h[2]; h23.y = h[3];
    __nv_bfloat162 l01; l01.x = l[0]; l01.y = l[1];
    __nv_bfloat162 l23; l23.x = l[2]; l23.y = l[3];
    reinterpret_cast<__nv_bfloat162*>(oh)[2 * i]     = h01;
    reinterpret_cast<__nv_bfloat162*>(oh)[2 * i + 1] = h23;
    reinterpret_cast<__nv_bfloat162*>(ol)[2 * i]     = l01;
    reinterpret_cast<__nv_bfloat162*>(ol)[2 * i + 1] = l23;
}

// ---------------------------------------------------------------------------
// prep2: qkv fp32 -> per-head fp16 (Qh scaled 1/8; Kh+Kl split; Vh transposed)
// ---------------------------------------------------------------------------
__global__ __launch_bounds__(128)
void attn_prep(const float* __restrict__ qkv,
               __half* __restrict__ qh,
               __half* __restrict__ kh, __half* __restrict__ kl,
               __half* __restrict__ vh) {
    __shared__ float sv[64][65];
    const int tid = threadIdx.x;
    const int nt = blockIdx.x, bh = blockIdx.y;
    const int b = bh >> 4, h = bh & 15;
    const int n0 = nt * 64;
    const size_t obase = (size_t)bh * HSZ;

#pragma unroll
    for (int p = 0; p < 8; p++) {
        const int idx = p * 128 + tid;
        const int row = idx >> 4, c4 = (idx & 15) * 4;
        const size_t src = (size_t)(b * Nn + n0 + row) * QKV_COLS + h * HD + c4;
        // Q (scaled 1/8, single fp16)
        {
            const float4 v = *reinterpret_cast<const float4*>(&qkv[src]);
            __half h0 = __float2half_rn(v.x * 0.125f);
            __half h1 = __float2half_rn(v.y * 0.125f);
            __half h2 = __float2half_rn(v.z * 0.125f);
            __half h3 = __float2half_rn(v.w * 0.125f);
            const size_t o = obase + (size_t)(n0 + row) * HD + c4;
            *reinterpret_cast<__half2*>(&qh[o])     = __halves2half2(h0, h1);
            *reinterpret_cast<__half2*>(&qh[o + 2]) = __halves2half2(h2, h3);
        }
        // K (fp16 hi/lo split)
        {
            const float4 v = *reinterpret_cast<const float4*>(&qkv[src + Dd]);
            float f[4] = {v.x, v.y, v.z, v.w};
            __half hh[4], ll[4];
#pragma unroll
            for (int e = 0; e < 4; e++) {
                hh[e] = __float2half_rn(f[e]);
                ll[e] = __float2half_rn(f[e] - __half2float(hh[e]));
            }
            const size_t o = obase + (size_t)(n0 + row) * HD + c4;
            *reinterpret_cast<__half2*>(&kh[o])     = __halves2half2(hh[0], hh[1]);
            *reinterpret_cast<__half2*>(&kh[o + 2]) = __halves2half2(hh[2], hh[3]);
            *reinterpret_cast<__half2*>(&kl[o])     = __halves2half2(ll[0], ll[1]);
            *reinterpret_cast<__half2*>(&kl[o + 2]) = __halves2half2(ll[2], ll[3]);
        }
        // V -> smem
        {
            const float4 v = *reinterpret_cast<const float4*>(&qkv[src + 2 * Dd]);
            sv[row][c4 + 0] = v.x; sv[row][c4 + 1] = v.y;
            sv[row][c4 + 2] = v.z; sv[row][c4 + 3] = v.w;
        }
    }
    __syncthreads();
    // V transposed write: [hd][n] (single fp16)
#pragma unroll
    for (int p = 0; p < 8; p++) {
        const int idx = p * 128 + tid;
        const int hd = idx >> 4, oc4 = (idx & 15) * 4;
        __half h0 = __float2half_rn(sv[oc4 + 0][hd]);
        __half h1 = __float2half_rn(sv[oc4 + 1][hd]);
        __half h2 = __float2half_rn(sv[oc4 + 2][hd]);
        __half h3 = __float2half_rn(sv[oc4 + 3][hd]);
        const size_t o = obase + (size_t)hd * Nn + n0 + oc4;
        *reinterpret_cast<__half2*>(&vh[o])     = __halves2half2(h0, h1);
        *reinterpret_cast<__half2*>(&vh[o + 2]) = __halves2half2(h2, h3);
    }
}

// ---------------------------------------------------------------------------
// bf16x3 GEMM, cp.async double-buffered (validated R12).
// ---------------------------------------------------------------------------
#define G_AH 0
#define G_AL 10240
#define G_BH 20480
#define G_BL 30720
#define G_SBUF 40960
#define G_SMEM (2 * G_SBUF)

__global__ __launch_bounds__(256, 2)
void gemm_sp(const __nv_bfloat16* __restrict__ Ah, const __nv_bfloat16* __restrict__ Al,
             const __nv_bfloat16* __restrict__ Bh, const __nv_bfloat16* __restrict__ Bl,
             const float* __restrict__ bias, float* __restrict__ C,
             int Nc, int K) {
    extern __shared__ char dsm[];
    const uint32_t sbase = smem_u32(dsm);

    const int tid = threadIdx.x;
    const int row0 = blockIdx.y * 128;
    const int col0 = blockIdx.x * 128;
    const int warp = tid >> 5, lane = tid & 31;
    const int wm = warp & 3, wn = warp >> 2;

    const int quad = lane >> 3, r8 = lane & 7;
    const uint32_t offA = (uint32_t)(((quad & 1) * 8 + r8) * 80 + ((quad >> 1) * 8) * 2);
    const uint32_t offB = (uint32_t)(((quad >> 1) * 8 + r8) * 80 + ((quad & 1) * 8) * 2);
    const uint32_t aHi0 = sbase + G_AH + (uint32_t)(wm * 32 * 80) + offA;
    const uint32_t aLo0 = sbase + G_AL + (uint32_t)(wm * 32 * 80) + offA;
    const uint32_t bHi0 = sbase + G_BH + (uint32_t)(wn * 64 * 80) + offB;
    const uint32_t bLo0 = sbase + G_BL + (uint32_t)(wn * 64 * 80) + offB;

    const int sr0 = tid >> 2, su = tid & 3;

    float acc[2][8][4];
#pragma unroll
    for (int mt = 0; mt < 2; mt++)
#pragma unroll
        for (int j = 0; j < 8; j++)
#pragma unroll
            for (int e = 0; e < 4; e++) acc[mt][j][e] = 0.0f;

    const int nk = K >> 5;

    {
        const uint32_t st = sbase;
#pragma unroll
        for (int p = 0; p < 2; p++) {
            const int row = sr0 + p * 64;
            const uint32_t d = st + (uint32_t)(row * 80 + su * 16);
            const size_t ra = (size_t)(row0 + row) * K + su * 8;
            const size_t rb = (size_t)(col0 + row) * K + su * 8;
            CP16(d + G_AH, &Ah[ra]);
            CP16(d + G_AL, &Al[ra]);
            CP16(d + G_BH, &Bh[rb]);
            CP16(d + G_BL, &Bl[rb]);
        }
        CP_COMMIT();
    }

    for (int ks = 0; ks < nk; ks++) {
        const uint32_t bufOff = (uint32_t)((ks & 1) * G_SBUF);
        if (ks + 1 < nk) {
            const uint32_t st = sbase + (uint32_t)(((ks + 1) & 1) * G_SBUF);
            const int k0 = (ks + 1) * 32;
#pragma unroll
            for (int p = 0; p < 2; p++) {
                const int row = sr0 + p * 64;
                const uint32_t d = st + (uint32_t)(row * 80 + su * 16);
                const size_t ra = (size_t)(row0 + row) * K + k0 + su * 8;
                const size_t rb = (size_t)(col0 + row) * K + k0 + su * 8;
                CP16(d + G_AH, &Ah[ra]);
                CP16(d + G_AL, &Al[ra]);
                CP16(d + G_BH, &Bh[rb]);
                CP16(d + G_BL, &Bl[rb]);
            }
            CP_COMMIT();
            CP_WAIT(1);
        } else {
            CP_WAIT(0);
        }
        __syncthreads();

#pragma unroll
        for (int kc = 0; kc < 2; kc++) {
            const uint32_t kadd = bufOff + (uint32_t)(kc * 32);
            uint32_t ah[2][4], al[2][4], bh[8][2], bl[8][2];
#pragma unroll
            for (int mt = 0; mt < 2; mt++) {
                LDSM_X4(ah[mt][0], ah[mt][1], ah[mt][2], ah[mt][3],
                        aHi0 + (uint32_t)(mt * 16 * 80) + kadd);
                LDSM_X4(al[mt][0], al[mt][1], al[mt][2], al[mt][3],
                        aLo0 + (uint32_t)(mt * 16 * 80) + kadd);
            }
#pragma unroll
            for (int g = 0; g < 4; g++) {
                uint32_t t0, t1, t2, t3;
                LDSM_X4(t0, t1, t2, t3, bHi0 + (uint32_t)(g * 16 * 80) + kadd);
                bh[2 * g][0] = t0; bh[2 * g][1] = t1;
                bh[2 * g + 1][0] = t2; bh[2 * g + 1][1] = t3;
                LDSM_X4(t0, t1, t2, t3, bLo0 + (uint32_t)(g * 16 * 80) + kadd);
                bl[2 * g][0] = t0; bl[2 * g][1] = t1;
                bl[2 * g + 1][0] = t2; bl[2 * g + 1][1] = t3;
            }
#pragma unroll
            for (int mt = 0; mt < 2; mt++)
#pragma unroll
                for (int j = 0; j < 8; j++)
                    MMA_BF16(acc[mt][j], ah[mt], bh[j][0], bh[j][1]);
#pragma unroll
            for (int mt = 0; mt < 2; mt++)
#pragma unroll
                for (int j = 0; j < 8; j++)
                    MMA_BF16(acc[mt][j], ah[mt], bl[j][0], bl[j][1]);
#pragma unroll
            for (int mt = 0; mt < 2; mt++)
#pragma unroll
                for (int j = 0; j < 8; j++)
                    MMA_BF16(acc[mt][j], al[mt], bh[j][0], bh[j][1]);
        }
        __syncthreads();
    }

    const int mrow = row0 + wm * 32 + (lane >> 2);
    const int ncol = col0 + wn * 64 + (lane & 3) * 2;
#pragma unroll
    for (int mt = 0; mt < 2; mt++) {
        const int r_up = mrow + mt * 16;
#pragma unroll
        for (int j = 0; j < 8; j++) {
            const int c = ncol + j * 8;
            const float b0 = bias[c], b1 = bias[c + 1];
            float2 v0 = make_float2(acc[mt][j][0] + b0, acc[mt][j][1] + b1);
            float2 v1 = make_float2(acc[mt][j][2] + b0, acc[mt][j][3] + b1);
            *reinterpret_cast<float2*>(&C[(size_t)r_up * Nc + c]) = v0;
            *reinterpret_cast<float2*>(&C[(size_t)(r_up + 8) * Nc + c]) = v1;
        }
    }
}

// ---------------------------------------------------------------------------
// Tensor-core flash attention.
// S = Qh.Kh + Qh.Kl (2 passes); PV = P x Vh (1 pass).
// Dynamic smem: Q (9216) + 2 bufs x (3 x 9216) = 64512B -> 3 CTAs/SM.
// ---------------------------------------------------------------------------
#define AROW 72
#define ARS  144
#define A_QH 0
#define A_KV 9216
#define A_KH 0
#define A_KL 9216
#define A_VH 18432
#define A_VBUF 27648
#define A_SMEM (A_KV + 2 * A_VBUF)   // 64512

__global__ __launch_bounds__(128)
void attn_tc(const __half* __restrict__ qh,
             const __half* __restrict__ kh, const __half* __restrict__ kl,
             const __half* __restrict__ vh,
             const int* __restrict__ t_idx,
             const unsigned char* __restrict__ mask,
             const float* __restrict__ alpha,
             __nv_bfloat16* __restrict__ ctxh, __nv_bfloat16* __restrict__ ctxl) {
    extern __shared__ char dsm[];
    __shared__ int tks2[2][64];
    const uint32_t sbase = smem_u32(dsm);

    const int qt = blockIdx.x, h = blockIdx.y, b = blockIdx.z;
    const int tid = threadIdx.x, warp = tid >> 5, lane = tid & 31;
    const int q0 = qt * 64;

    const float a_h = alpha[h];
    const size_t bn0 = (size_t)(b * Nn);
    const size_t hb = (size_t)(b * Hh + h) * HSZ;

    const int sr0 = tid >> 3, su = tid & 7;

    // ---- stage Q once ----
#pragma unroll
    for (int p = 0; p < 4; p++) {
        const int idx = p * 128 + tid;
        const int row = idx >> 3, u = idx & 7;
        const size_t src = hb + (size_t)(q0 + row) * HD + u * 8;
        *reinterpret_cast<uint4*>(dsm + A_QH + row * ARS + u * 16) =
            *reinterpret_cast<const uint4*>(&qh[src]);
    }

    const int g8 = lane >> 2;
    const int row_lo = q0 + warp * 16 + g8;
    const int row_hi = row_lo + 8;
    const float tq0 = (float)t_idx[bn0 + row_lo];
    const float tq1 = (float)t_idx[bn0 + row_hi];

    float ctxacc[8][4];
#pragma unroll
    for (int j = 0; j < 8; j++)
#pragma unroll
        for (int e = 0; e < 4; e++) ctxacc[j][e] = 0.0f;
    float lsum0 = 0.0f, lsum1 = 0.0f;
    float m0 = -1e30f, m1 = -1e30f;

    const int quad = lane >> 3, r8 = lane & 7;
    const uint32_t offA = (uint32_t)(((quad & 1) * 8 + r8) * ARS + ((quad >> 1) * 8) * 2);
    const uint32_t offB = (uint32_t)(((quad >> 1) * 8 + r8) * ARS + ((quad & 1) * 8) * 2);
    const uint32_t aQh = sbase + A_QH + (uint32_t)(warp * 16 * ARS) + offA;

    // ---- prologue: prefetch K/V tile 0; stage tks(0) ----
    {
        const uint32_t st = sbase + A_KV;
#pragma unroll
        for (int p = 0; p < 4; p++) {
            const int row = sr0 + p * 16;
            const uint32_t d = st + (uint32_t)(row * ARS + su * 16);
            const size_t srcK = hb + (size_t)row * HD + su * 8;
            const size_t srcV = hb + (size_t)row * Nn + su * 8;
            CP16(d + A_KH, &kh[srcK]);
            CP16(d + A_KL, &kl[srcK]);
            CP16(d + A_VH, &vh[srcV]);
        }
        CP_COMMIT();
        if (tid < 64) tks2[0][tid] = t_idx[bn0 + tid];
    }

    for (int it = 0; it < Nn / 64; it++) {
        const int k0 = it * 64;
        const uint32_t kvOff = (uint32_t)((it & 1) * A_VBUF);

        if (it + 1 < Nn / 64) {
            const int kn = (it + 1) * 64;
            const uint32_t st = sbase + A_KV + (uint32_t)(((it + 1) & 1) * A_VBUF);
#pragma unroll
            for (int p = 0; p < 4; p++) {
                const int row = sr0 + p * 16;
                const uint32_t d = st + (uint32_t)(row * ARS + su * 16);
                const size_t srcK = hb + (size_t)(kn + row) * HD + su * 8;
                const size_t srcV = hb + (size_t)row * Nn + kn + su * 8;
                CP16(d + A_KH, &kh[srcK]);
                CP16(d + A_KL, &kl[srcK]);
                CP16(d + A_VH, &vh[srcV]);
            }
            CP_COMMIT();
            if (tid < 64) tks2[(it + 1) & 1][tid] = t_idx[bn0 + kn + tid];
        }

        int myMask;
        {
            const int row = tid >> 1, half = tid & 1;
            const uint4* mp = reinterpret_cast<const uint4*>(
                &mask[(bn0 + q0 + row) * Nn + k0 + half * 32]);
            uint4 mA = mp[0], mB = mp[1];
            myMask = (mA.x | mA.y | mA.z | mA.w | mB.x | mB.y | mB.z | mB.w) != 0;
        }

        if (it + 1 < Nn / 64) { CP_WAIT(1); } else { CP_WAIT(0); }
        const int tileMasked = __syncthreads_or(myMask);

        const uint32_t bKh = sbase + A_KV + kvOff + A_KH + offB;
        const uint32_t bKl = sbase + A_KV + kvOff + A_KL + offB;
        const uint32_t bVh = sbase + A_KV + kvOff + A_VH + offB;
        const int* tks = tks2[it & 1];

        // ---- S = Qh.Kh + Qh.Kl ----
        float sacc[8][4];
#pragma unroll
        for (int j = 0; j < 8; j++)
#pragma unroll
            for (int e = 0; e < 4; e++) sacc[j][e] = 0.0f;

#pragma unroll
        for (int pass = 0; pass < 2; pass++) {
            const uint32_t bBase = (pass == 1) ? bKl : bKh;
#pragma unroll
            for (int kc = 0; kc < 4; kc++) {
                uint32_t aq[4];
                LDSM_X4(aq[0], aq[1], aq[2], aq[3], aQh + (uint32_t)(kc * 32));
#pragma unroll
                for (int g = 0; g < 4; g++) {
                    uint32_t t0, t1, t2, t3;
                    LDSM_X4(t0, t1, t2, t3, bBase + (uint32_t)(g * 16 * ARS + kc * 32));
                    MMA_FP16(sacc[2 * g], aq, t0, t1);
                    MMA_FP16(sacc[2 * g + 1], aq, t2, t3);
                }
            }
        }

        // ---- bias + tile max ----
        float tmax0 = -1e30f, tmax1 = -1e30f;
#pragma unroll
        for (int j = 0; j < 8; j++) {
            const int c0 = 8 * j + 2 * (lane & 3);
            const float tk0 = (float)tks[c0];
            const float tk1 = (float)tks[c0 + 1];
            sacc[j][0] -= a_h * fmaxf(tq0 - tk0, 0.0f);
            sacc[j][1] -= a_h * fmaxf(tq0 - tk1, 0.0f);
            sacc[j][2] -= a_h * fmaxf(tq1 - tk0, 0.0f);
            sacc[j][3] -= a_h * fmaxf(tq1 - tk1, 0.0f);
            tmax0 = fmaxf(tmax0, fmaxf(sacc[j][0], sacc[j][1]));
            tmax1 = fmaxf(tmax1, fmaxf(sacc[j][2], sacc[j][3]));
        }
        tmax0 = fmaxf(tmax0, __shfl_xor_sync(0xFFFFFFFF, tmax0, 1));
        tmax0 = fmaxf(tmax0, __shfl_xor_sync(0xFFFFFFFF, tmax0, 2));
        tmax1 = fmaxf(tmax1, __shfl_xor_sync(0xFFFFFFFF, tmax1, 1));
        tmax1 = fmaxf(tmax1, __shfl_xor_sync(0xFFFFFFFF, tmax1, 2));

        const float mn0 = fmaxf(m0, tmax0);
        const float mn1 = fmaxf(m1, tmax1);
        const float sc0 = __expf(m0 - mn0);
        const float sc1 = __expf(m1 - mn1);
        m0 = mn0; m1 = mn1;
        lsum0 *= sc0; lsum1 *= sc1;
#pragma unroll
        for (int j = 0; j < 8; j++) {
            ctxacc[j][0] *= sc0; ctxacc[j][1] *= sc0;
            ctxacc[j][2] *= sc1; ctxacc[j][3] *= sc1;
        }

        // ---- exp + mask + pack P ----
        uint32_t pa[4][4];
#pragma unroll
        for (int j = 0; j < 8; j++) {
            const int c0 = 8 * j + 2 * (lane & 3);
            float p0 = __expf(sacc[j][0] - m0);
            float p1 = __expf(sacc[j][1] - m0);
            float p2 = __expf(sacc[j][2] - m1);
            float p3 = __expf(sacc[j][3] - m1);
            if (tileMasked) {
                const unsigned char* mr0 = &mask[(bn0 + row_lo) * Nn + k0 + c0];
                const unsigned char* mr1 = &mask[(bn0 + row_hi) * Nn + k0 + c0];
                p0 = mr0[0] ? 0.0f : p0;
                p1 = mr0[1] ? 0.0f : p1;
                p2 = mr1[0] ? 0.0f : p2;
                p3 = mr1[1] ? 0.0f : p3;
            }
            const __half2 lo_h = __float22half2_rn(make_float2(p0, p1));
            const __half2 hi_h = __float22half2_rn(make_float2(p2, p3));
            const float2 lo_r = __half22float2(lo_h);
            const float2 hi_r = __half22float2(hi_h);
            lsum0 += lo_r.x + lo_r.y;
            lsum1 += hi_r.x + hi_r.y;
            pa[j >> 1][(j & 1) * 2 + 0] = h2_as_u32(lo_h);
            pa[j >> 1][(j & 1) * 2 + 1] = h2_as_u32(hi_h);
        }

        // ---- ctx += P x Vh ----
#pragma unroll
        for (int kc = 0; kc < 4; kc++) {
#pragma unroll
            for (int g = 0; g < 4; g++) {
                uint32_t t0, t1, t2, t3;
                LDSM_X4(t0, t1, t2, t3, bVh + (uint32_t)(g * 16 * ARS + kc * 32));
                MMA_FP16(ctxacc[2 * g], pa[kc], t0, t1);
                MMA_FP16(ctxacc[2 * g + 1], pa[kc], t2, t3);
            }
        }
        __syncthreads();
    }

    lsum0 += __shfl_xor_sync(0xFFFFFFFF, lsum0, 1);
    lsum0 += __shfl_xor_sync(0xFFFFFFFF, lsum0, 2);
    lsum1 += __shfl_xor_sync(0xFFFFFFFF, lsum1, 1);
    lsum1 += __shfl_xor_sync(0xFFFFFFFF, lsum1, 2);
    const float inv0 = (lsum0 > 0.0f) ? (1.0f / lsum0) : 0.0f;
    const float inv1 = (lsum1 > 0.0f) ? (1.0f / lsum1) : 0.0f;

#pragma unroll
    for (int j = 0; j < 8; j++) {
        const int c0 = h * HD + 8 * j + 2 * (lane & 3);
        const float o0 = ctxacc[j][0] * inv0, o1 = ctxacc[j][1] * inv0;
        const float o2 = ctxacc[j][2] * inv1, o3 = ctxacc[j][3] * inv1;
        __nv_bfloat16 h0 = __float2bfloat16_rn(o0), h1 = __float2bfloat16_rn(o1);
        __nv_bfloat16 h2 = __float2bfloat16_rn(o2), h3 = __float2bfloat16_rn(o3);
        __nv_bfloat162 hl; hl.x = h0; hl.y = h1;
        __nv_bfloat162 hh; hh.x = h2; hh.y = h3;
        __nv_bfloat162 ll; ll.x = __float2bfloat16_rn(o0 - __bfloat162float(h0));
        ll.y = __float2bfloat16_rn(o1 - __bfloat162float(h1));
        __nv_bfloat162 lh; lh.x = __float2bfloat16_rn(o2 - __bfloat162float(h2));
        lh.y = __float2bfloat16_rn(o3 - __bfloat162float(h3));
        *reinterpret_cast<__nv_bfloat162*>(&ctxh[(bn0 + row_lo) * Dd + c0]) = hl;
        *reinterpret_cast<__nv_bfloat162*>(&ctxh[(bn0 + row_hi) * Dd + c0]) = hh;
        *reinterpret_cast<__nv_bfloat162*>(&ctxl[(bn0 + row_lo) * Dd + c0]) = ll;
        *reinterpret_cast<__nv_bfloat162*>(&ctxl[(bn0 + row_hi) * Dd + c0]) = lh;
    }
}

// ---------------------------------------------------------------------------
extern "C" void kernel_launch(void* const* d_in, const int* in_sizes, int n_in,
                              void* d_out, int out_size) {
    const float*         X     = (const float*)d_in[0];
    const int*           t_idx = (const int*)d_in[1];
    const unsigned char* mask  = (const unsigned char*)d_in[2];
    const float*         Wqkv  = (const float*)d_in[3];
    const float*         bqkv  = (const float*)d_in[4];
    const float*         Wo    = (const float*)d_in[5];
    const float*         bo    = (const float*)d_in[6];
    const float*         alpha = (const float*)d_in[7];
    float*               out   = (float*)d_out;

    void *qkv_p, *xh_p, *xl_p, *wqh_p, *wql_p, *woh_p, *wol_p, *ctxh_p, *ctxl_p;
    void *qh_p, *kh_p, *kl_p, *vh_p;
    cudaGetSymbolAddress(&qkv_p, g_qkv);
    cudaGetSymbolAddress(&xh_p, g_xh);   cudaGetSymbolAddress(&xl_p, g_xl);
    cudaGetSymbolAddress(&wqh_p, g_wqh); cudaGetSymbolAddress(&wql_p, g_wql);
    cudaGetSymbolAddress(&woh_p, g_woh); cudaGetSymbolAddress(&wol_p, g_wol);
    cudaGetSymbolAddress(&ctxh_p, g_ctxh); cudaGetSymbolAddress(&ctxl_p, g_ctxl);
    cudaGetSymbolAddress(&qh_p, g_q16h);
    cudaGetSymbolAddress(&kh_p, g_k16h); cudaGetSymbolAddress(&kl_p, g_k16l);
    cudaGetSymbolAddress(&vh_p, g_v16h);

    cudaFuncSetAttribute(gemm_sp, cudaFuncAttributeMaxDynamicSharedMemorySize, G_SMEM);
    cudaFuncSetAttribute(attn_tc, cudaFuncAttributeMaxDynamicSharedMemorySize, A_SMEM);

    // prep1: split X, Wqkv, Wo
    split_bf16<<<(BN_ROWS * Dd / 4 + 255) / 256, 256>>>(
        X, (__nv_bfloat16*)xh_p, (__nv_bfloat16*)xl_p, BN_ROWS * Dd / 4);
    split_bf16<<<(QKV_COLS * Dd / 4 + 255) / 256, 256>>>(
        Wqkv, (__nv_bfloat16*)wqh_p, (__nv_bfloat16*)wql_p, QKV_COLS * Dd / 4);
    split_bf16<<<(Dd * Dd / 4 + 255) / 256, 256>>>(
        Wo, (__nv_bfloat16*)woh_p, (__nv_bfloat16*)wol_p, Dd * Dd / 4);

    // 1) QKV projection
    {
        dim3 grid(QKV_COLS / 128, BN_ROWS / 128);
        gemm_sp<<<grid, 256, G_SMEM>>>((__nv_bfloat16*)xh_p, (__nv_bfloat16*)xl_p,
                                       (__nv_bfloat16*)wqh_p, (__nv_bfloat16*)wql_p,
                                       bqkv, (float*)qkv_p, QKV_COLS, Dd);
    }

    // prep2: per-head fp16 (Qh, Kh+Kl, Vh transposed)
    {
        dim3 grid(Nn / 64, NH);
        attn_prep<<<grid, 128>>>((const float*)qkv_p,
                                 (__half*)qh_p,
                                 (__half*)kh_p, (__half*)kl_p,
                                 (__half*)vh_p);
    }

    // 2) Tensor-core flash attention -> ctx (bf16 hi/lo)
    {
        dim3 grid(Nn / 64, Hh, Bb);
        attn_tc<<<grid, 128, A_SMEM>>>((const __half*)qh_p,
                                       (const __half*)kh_p, (const __half*)kl_p,
                                       (const __half*)vh_p,
                                       t_idx, mask, alpha,
                                       (__nv_bfloat16*)ctxh_p, (__nv_bfloat16*)ctxl_p);
    }

    // 3) Output projection
    {
        dim3 grid(Dd / 128, BN_ROWS / 128);
        gemm_sp<<<grid, 256, G_SMEM>>>((__nv_bfloat16*)ctxh_p, (__nv_bfloat16*)ctxl_p,
                                       (__nv_bfloat16*)woh_p, (__nv_bfloat16*)wol_p,
                                       bo, out, Dd, Dd);
    }
}

// round 14
// speedup vs baseline: 5.2586x; 1.0007x over previous
#include <cuda_runtime.h>
#include <cuda_bf16.h>
#include <cuda_fp16.h>
#include <cstdint>

// Fixed problem shapes
#define Bb 2
#define Nn 2048
#define Dd 1024
#define Hh 16
#define HD 64
#define BN_ROWS 4096
#define QKV_COLS 3072
#define NH (Bb * Hh)
#define HSZ (Nn * HD)

// Scratch (device globals: allocation-guard safe)
__device__ float g_qkv[BN_ROWS * QKV_COLS];
__device__ __nv_bfloat16 g_xh[BN_ROWS * Dd], g_xl[BN_ROWS * Dd];
__device__ __nv_bfloat16 g_wqh[QKV_COLS * Dd], g_wql[QKV_COLS * Dd];
__device__ __nv_bfloat16 g_woh[Dd * Dd], g_wol[Dd * Dd];
__device__ __nv_bfloat16 g_ctxh[BN_ROWS * Dd], g_ctxl[BN_ROWS * Dd];
__device__ __half g_q16h[NH * HSZ];
__device__ __half g_k16h[NH * HSZ], g_k16l[NH * HSZ];
__device__ __half g_v16h[NH * HSZ];                     // [bh][hd][n]

// ---------------------------------------------------------------------------
// helpers
// ---------------------------------------------------------------------------
__device__ __forceinline__ uint32_t smem_u32(const void* p) {
    uint32_t a;
    asm("{ .reg .u64 t; cvta.to.shared.u64 t, %1; cvt.u32.u64 %0, t; }" : "=r"(a) : "l"(p));
    return a;
}
__device__ __forceinline__ uint32_t h2_as_u32(__half2 h) {
    return *reinterpret_cast<uint32_t*>(&h);
}

#define CP16(dst, src) \
    asm volatile("cp.async.cg.shared.global [%0], [%1], 16;" :: "r"(dst), "l"(src))
#define CP_COMMIT() asm volatile("cp.async.commit_group;" ::: "memory")
#define CP_WAIT(n)  asm volatile("cp.async.wait_group %0;" :: "n"(n) : "memory")

#define LDSM_X4(r0, r1, r2, r3, addr) \
    asm volatile("ldmatrix.sync.aligned.m8n8.x4.shared.b16 {%0,%1,%2,%3}, [%4];" \
                 : "=r"(r0), "=r"(r1), "=r"(r2), "=r"(r3) : "r"(addr))

#define MMA_BF16(d, a, b0, b1) \
    asm volatile("mma.sync.aligned.m16n8k16.row.col.f32.bf16.bf16.f32 " \
                 "{%0,%1,%2,%3},{%4,%5,%6,%7},{%8,%9},{%0,%1,%2,%3};" \
                 : "+f"((d)[0]), "+f"((d)[1]), "+f"((d)[2]), "+f"((d)[3]) \
                 : "r"((a)[0]), "r"((a)[1]), "r"((a)[2]), "r"((a)[3]), \
                   "r"(b0), "r"(b1))

#define MMA_FP16(d, a, b0, b1) \
    asm volatile("mma.sync.aligned.m16n8k16.row.col.f32.f16.f16.f32 " \
                 "{%0,%1,%2,%3},{%4,%5,%6,%7},{%8,%9},{%0,%1,%2,%3};" \
                 : "+f"((d)[0]), "+f"((d)[1]), "+f"((d)[2]), "+f"((d)[3]) \
                 : "r"((a)[0]), "r"((a)[1]), "r"((a)[2]), "r"((a)[3]), \
                   "r"(b0), "r"(b1))

// ---------------------------------------------------------------------------
// prep1: elementwise fp32 -> bf16 hi/lo split
// ---------------------------------------------------------------------------
__global__ __launch_bounds__(256)
void split_bf16(const float* __restrict__ in, __nv_bfloat16* __restrict__ oh,
                __nv_bfloat16* __restrict__ ol, int n4) {
    const int i = blockIdx.x * 256 + threadIdx.x;
    if (i >= n4) return;
    const float4 v = reinterpret_cast<const float4*>(in)[i];
    float f[4] = {v.x, v.y, v.z, v.w};
    __nv_bfloat16 h[4], l[4];
#pragma unroll
    for (int e = 0; e < 4; e++) {
        h[e] = __float2bfloat16_rn(f[e]);
        l[e] = __float2bfloat16_rn(f[e] - __bfloat162float(h[e]));
    }
    __nv_bfloat162 h01; h01.x = h[0]; h01.y = h[1];
    __nv_bfloat162 h23; h23.x = h[2]; h23.y = h[3];
    __nv_bfloat162 l01; l01.x = l[0]; l01.y = l[1];
    __nv_bfloat162 l23; l23.x = l[2]; l23.y = l[3];
    reinterpret_cast<__nv_bfloat162*>(oh)[2 * i]     = h01;
    reinterpret_cast<__nv_bfloat162*>(oh)[2 * i + 1] = h23;
    reinterpret_cast<__nv_bfloat162*>(ol)[2 * i]     = l01;
    reinterpret_cast<__nv_bfloat162*>(ol)[2 * i + 1] = l23;
}

// ---------------------------------------------------------------------------
// prep2: qkv fp32 -> per-head fp16 (Qh scaled 1/8; Kh+Kl split; Vh transposed)
// ---------------------------------------------------------------------------
__global__ __launch_bounds__(128)
void attn_prep(const float* __restrict__ qkv,
               __half* __restrict__ qh,
               __half* __restrict__ kh, __half* __restrict__ kl,
               __half* __restrict__ vh) {
    __shared__ float sv[64][65];
    const int tid = threadIdx.x;
    const int nt = blockIdx.x, bh = blockIdx.y;
    const int b = bh >> 4, h = bh & 15;
    const int n0 = nt * 64;
    const size_t obase = (size_t)bh * HSZ;

#pragma unroll
    for (int p = 0; p < 8; p++) {
        const int idx = p * 128 + tid;
        const int row = idx >> 4, c4 = (idx & 15) * 4;
        const size_t src = (size_t)(b * Nn + n0 + row) * QKV_COLS + h * HD + c4;
        // Q (scaled 1/8, single fp16)
        {
            const float4 v = *reinterpret_cast<const float4*>(&qkv[src]);
            __half h0 = __float2half_rn(v.x * 0.125f);
            __half h1 = __float2half_rn(v.y * 0.125f);
            __half h2 = __float2half_rn(v.z * 0.125f);
            __half h3 = __float2half_rn(v.w * 0.125f);
            const size_t o = obase + (size_t)(n0 + row) * HD + c4;
            *reinterpret_cast<__half2*>(&qh[o])     = __halves2half2(h0, h1);
            *reinterpret_cast<__half2*>(&qh[o + 2]) = __halves2half2(h2, h3);
        }
        // K (fp16 hi/lo split)
        {
            const float4 v = *reinterpret_cast<const float4*>(&qkv[src + Dd]);
            float f[4] = {v.x, v.y, v.z, v.w};
            __half hh[4], ll[4];
#pragma unroll
            for (int e = 0; e < 4; e++) {
                hh[e] = __float2half_rn(f[e]);
                ll[e] = __float2half_rn(f[e] - __half2float(hh[e]));
            }
            const size_t o = obase + (size_t)(n0 + row) * HD + c4;
            *reinterpret_cast<__half2*>(&kh[o])     = __halves2half2(hh[0], hh[1]);
            *reinterpret_cast<__half2*>(&kh[o + 2]) = __halves2half2(hh[2], hh[3]);
            *reinterpret_cast<__half2*>(&kl[o])     = __halves2half2(ll[0], ll[1]);
            *reinterpret_cast<__half2*>(&kl[o + 2]) = __halves2half2(ll[2], ll[3]);
        }
        // V -> smem
        {
            const float4 v = *reinterpret_cast<const float4*>(&qkv[src + 2 * Dd]);
            sv[row][c4 + 0] = v.x; sv[row][c4 + 1] = v.y;
            sv[row][c4 + 2] = v.z; sv[row][c4 + 3] = v.w;
        }
    }
    __syncthreads();
    // V transposed write: [hd][n] (single fp16)
#pragma unroll
    for (int p = 0; p < 8; p++) {
        const int idx = p * 128 + tid;
        const int hd = idx >> 4, oc4 = (idx & 15) * 4;
        __half h0 = __float2half_rn(sv[oc4 + 0][hd]);
        __half h1 = __float2half_rn(sv[oc4 + 1][hd]);
        __half h2 = __float2half_rn(sv[oc4 + 2][hd]);
        __half h3 = __float2half_rn(sv[oc4 + 3][hd]);
        const size_t o = obase + (size_t)hd * Nn + n0 + oc4;
        *reinterpret_cast<__half2*>(&vh[o])     = __halves2half2(h0, h1);
        *reinterpret_cast<__half2*>(&vh[o + 2]) = __halves2half2(h2, h3);
    }
}

// ---------------------------------------------------------------------------
// bf16x3 GEMM, cp.async double-buffered (validated R12).
// ---------------------------------------------------------------------------
#define G_AH 0
#define G_AL 10240
#define G_BH 20480
#define G_BL 30720
#define G_SBUF 40960
#define G_SMEM (2 * G_SBUF)

__global__ __launch_bounds__(256, 2)
void gemm_sp(const __nv_bfloat16* __restrict__ Ah, const __nv_bfloat16* __restrict__ Al,
             const __nv_bfloat16* __restrict__ Bh, const __nv_bfloat16* __restrict__ Bl,
             const float* __restrict__ bias, float* __restrict__ C,
             int Nc, int K) {
    extern __shared__ char dsm[];
    const uint32_t sbase = smem_u32(dsm);

    const int tid = threadIdx.x;
    const int row0 = blockIdx.y * 128;
    const int col0 = blockIdx.x * 128;
    const int warp = tid >> 5, lane = tid & 31;
    const int wm = warp & 3, wn = warp >> 2;

    const int quad = lane >> 3, r8 = lane & 7;
    const uint32_t offA = (uint32_t)(((quad & 1) * 8 + r8) * 80 + ((quad >> 1) * 8) * 2);
    const uint32_t offB = (uint32_t)(((quad >> 1) * 8 + r8) * 80 + ((quad & 1) * 8) * 2);
    const uint32_t aHi0 = sbase + G_AH + (uint32_t)(wm * 32 * 80) + offA;
    const uint32_t aLo0 = sbase + G_AL + (uint32_t)(wm * 32 * 80) + offA;
    const uint32_t bHi0 = sbase + G_BH + (uint32_t)(wn * 64 * 80) + offB;
    const uint32_t bLo0 = sbase + G_BL + (uint32_t)(wn * 64 * 80) + offB;

    const int sr0 = tid >> 2, su = tid & 3;

    float acc[2][8][4];
#pragma unroll
    for (int mt = 0; mt < 2; mt++)
#pragma unroll
        for (int j = 0; j < 8; j++)
#pragma unroll
            for (int e = 0; e < 4; e++) acc[mt][j][e] = 0.0f;

    const int nk = K >> 5;

    {
        const uint32_t st = sbase;
#pragma unroll
        for (int p = 0; p < 2; p++) {
            const int row = sr0 + p * 64;
            const uint32_t d = st + (uint32_t)(row * 80 + su * 16);
            const size_t ra = (size_t)(row0 + row) * K + su * 8;
            const size_t rb = (size_t)(col0 + row) * K + su * 8;
            CP16(d + G_AH, &Ah[ra]);
            CP16(d + G_AL, &Al[ra]);
            CP16(d + G_BH, &Bh[rb]);
            CP16(d + G_BL, &Bl[rb]);
        }
        CP_COMMIT();
    }

    for (int ks = 0; ks < nk; ks++) {
        const uint32_t bufOff = (uint32_t)((ks & 1) * G_SBUF);
        if (ks + 1 < nk) {
            const uint32_t st = sbase + (uint32_t)(((ks + 1) & 1) * G_SBUF);
            const int k0 = (ks + 1) * 32;
#pragma unroll
            for (int p = 0; p < 2; p++) {
                const int row = sr0 + p * 64;
                const uint32_t d = st + (uint32_t)(row * 80 + su * 16);
                const size_t ra = (size_t)(row0 + row) * K + k0 + su * 8;
                const size_t rb = (size_t)(col0 + row) * K + k0 + su * 8;
                CP16(d + G_AH, &Ah[ra]);
                CP16(d + G_AL, &Al[ra]);
                CP16(d + G_BH, &Bh[rb]);
                CP16(d + G_BL, &Bl[rb]);
            }
            CP_COMMIT();
            CP_WAIT(1);
        } else {
            CP_WAIT(0);
        }
        __syncthreads();

#pragma unroll
        for (int kc = 0; kc < 2; kc++) {
            const uint32_t kadd = bufOff + (uint32_t)(kc * 32);
            uint32_t ah[2][4], al[2][4], bh[8][2], bl[8][2];
#pragma unroll
            for (int mt = 0; mt < 2; mt++) {
                LDSM_X4(ah[mt][0], ah[mt][1], ah[mt][2], ah[mt][3],
                        aHi0 + (uint32_t)(mt * 16 * 80) + kadd);
                LDSM_X4(al[mt][0], al[mt][1], al[mt][2], al[mt][3],
                        aLo0 + (uint32_t)(mt * 16 * 80) + kadd);
            }
#pragma unroll
            for (int g = 0; g < 4; g++) {
                uint32_t t0, t1, t2, t3;
                LDSM_X4(t0, t1, t2, t3, bHi0 + (uint32_t)(g * 16 * 80) + kadd);
                bh[2 * g][0] = t0; bh[2 * g][1] = t1;
                bh[2 * g + 1][0] = t2; bh[2 * g + 1][1] = t3;
                LDSM_X4(t0, t1, t2, t3, bLo0 + (uint32_t)(g * 16 * 80) + kadd);
                bl[2 * g][0] = t0; bl[2 * g][1] = t1;
                bl[2 * g + 1][0] = t2; bl[2 * g + 1][1] = t3;
            }
#pragma unroll
            for (int mt = 0; mt < 2; mt++)
#pragma unroll
                for (int j = 0; j < 8; j++)
                    MMA_BF16(acc[mt][j], ah[mt], bh[j][0], bh[j][1]);
#pragma unroll
            for (int mt = 0; mt < 2; mt++)
#pragma unroll
                for (int j = 0; j < 8; j++)
                    MMA_BF16(acc[mt][j], ah[mt], bl[j][0], bl[j][1]);
#pragma unroll
            for (int mt = 0; mt < 2; mt++)
#pragma unroll
                for (int j = 0; j < 8; j++)
                    MMA_BF16(acc[mt][j], al[mt], bh[j][0], bh[j][1]);
        }
        __syncthreads();
    }

    const int mrow = row0 + wm * 32 + (lane >> 2);
    const int ncol = col0 + wn * 64 + (lane & 3) * 2;
#pragma unroll
    for (int mt = 0; mt < 2; mt++) {
        const int r_up = mrow + mt * 16;
#pragma unroll
        for (int j = 0; j < 8; j++) {
            const int c = ncol + j * 8;
            const float b0 = bias[c], b1 = bias[c + 1];
            float2 v0 = make_float2(acc[mt][j][0] + b0, acc[mt][j][1] + b1);
            float2 v1 = make_float2(acc[mt][j][2] + b0, acc[mt][j][3] + b1);
            *reinterpret_cast<float2*>(&C[(size_t)r_up * Nc + c]) = v0;
            *reinterpret_cast<float2*>(&C[(size_t)(r_up + 8) * Nc + c]) = v1;
        }
    }
}

// ---------------------------------------------------------------------------
// Tensor-core flash attention.
// S = Qh.Kh + Qh.Kl (2 passes); PV = P x Vh (1 pass).
// Dynamic smem: Q (9216) + 2 bufs x (3 x 9216) = 64512B -> 3 CTAs/SM.
// ---------------------------------------------------------------------------
#define AROW 72
#define ARS  144
#define A_QH 0
#define A_KV 9216
#define A_KH 0
#define A_KL 9216
#define A_VH 18432
#define A_VBUF 27648
#define A_SMEM (A_KV + 2 * A_VBUF)   // 64512

__global__ __launch_bounds__(128)
void attn_tc(const __half* __restrict__ qh,
             const __half* __restrict__ kh, const __half* __restrict__ kl,
             const __half* __restrict__ vh,
             const int* __restrict__ t_idx,
             const unsigned char* __restrict__ mask,
             const float* __restrict__ alpha,
             __nv_bfloat16* __restrict__ ctxh, __nv_bfloat16* __restrict__ ctxl) {
    extern __shared__ char dsm[];
    __shared__ int tks2[2][64];
    const uint32_t sbase = smem_u32(dsm);

    const int qt = blockIdx.x, h = blockIdx.y, b = blockIdx.z;
    const int tid = threadIdx.x, warp = tid >> 5, lane = tid & 31;
    const int q0 = qt * 64;

    const float a_h = alpha[h];
    const size_t bn0 = (size_t)(b * Nn);
    const size_t hb = (size_t)(b * Hh + h) * HSZ;

    const int sr0 = tid >> 3, su = tid & 7;

    // ---- stage Q once ----
#pragma unroll
    for (int p = 0; p < 4; p++) {
        const int idx = p * 128 + tid;
        const int row = idx >> 3, u = idx & 7;
        const size_t src = hb + (size_t)(q0 + row) * HD + u * 8;
        *reinterpret_cast<uint4*>(dsm + A_QH + row * ARS + u * 16) =
            *reinterpret_cast<const uint4*>(&qh[src]);
    }

    const int g8 = lane >> 2;
    const int row_lo = q0 + warp * 16 + g8;
    const int row_hi = row_lo + 8;
    const float tq0 = (float)t_idx[bn0 + row_lo];
    const float tq1 = (float)t_idx[bn0 + row_hi];

    float ctxacc[8][4];
#pragma unroll
    for (int j = 0; j < 8; j++)
#pragma unroll
        for (int e = 0; e < 4; e++) ctxacc[j][e] = 0.0f;
    float lsum0 = 0.0f, lsum1 = 0.0f;
    float m0 = -1e30f, m1 = -1e30f;

    const int quad = lane >> 3, r8 = lane & 7;
    const uint32_t offA = (uint32_t)(((quad & 1) * 8 + r8) * ARS + ((quad >> 1) * 8) * 2);
    const uint32_t offB = (uint32_t)(((quad >> 1) * 8 + r8) * ARS + ((quad & 1) * 8) * 2);
    const uint32_t aQh = sbase + A_QH + (uint32_t)(warp * 16 * ARS) + offA;

    // ---- prologue: prefetch K/V tile 0; stage tks(0) ----
    {
        const uint32_t st = sbase + A_KV;
#pragma unroll
        for (int p = 0; p < 4; p++) {
            const int row = sr0 + p * 16;
            const uint32_t d = st + (uint32_t)(row * ARS + su * 16);
            const size_t srcK = hb + (size_t)row * HD + su * 8;
            const size_t srcV = hb + (size_t)row * Nn + su * 8;
            CP16(d + A_KH, &kh[srcK]);
            CP16(d + A_KL, &kl[srcK]);
            CP16(d + A_VH, &vh[srcV]);
        }
        CP_COMMIT();
        if (tid < 64) tks2[0][tid] = t_idx[bn0 + tid];
    }

    for (int it = 0; it < Nn / 64; it++) {
        const int k0 = it * 64;
        const uint32_t kvOff = (uint32_t)((it & 1) * A_VBUF);

        if (it + 1 < Nn / 64) {
            const int kn = (it + 1) * 64;
            const uint32_t st = sbase + A_KV + (uint32_t)(((it + 1) & 1) * A_VBUF);
#pragma unroll
            for (int p = 0; p < 4; p++) {
                const int row = sr0 + p * 16;
                const uint32_t d = st + (uint32_t)(row * ARS + su * 16);
                const size_t srcK = hb + (size_t)(kn + row) * HD + su * 8;
                const size_t srcV = hb + (size_t)row * Nn + kn + su * 8;
                CP16(d + A_KH, &kh[srcK]);
                CP16(d + A_KL, &kl[srcK]);
                CP16(d + A_VH, &vh[srcV]);
            }
            CP_COMMIT();
            if (tid < 64) tks2[(it + 1) & 1][tid] = t_idx[bn0 + kn + tid];
        }

        int myMask;
        {
            const int row = tid >> 1, half = tid & 1;
            const uint4* mp = reinterpret_cast<const uint4*>(
                &mask[(bn0 + q0 + row) * Nn + k0 + half * 32]);
            uint4 mA = mp[0], mB = mp[1];
            myMask = (mA.x | mA.y | mA.z | mA.w | mB.x | mB.y | mB.z | mB.w) != 0;
        }

        if (it + 1 < Nn / 64) { CP_WAIT(1); } else { CP_WAIT(0); }
        const int tileMasked = __syncthreads_or(myMask);

        const uint32_t bKh = sbase + A_KV + kvOff + A_KH + offB;
        const uint32_t bKl = sbase + A_KV + kvOff + A_KL + offB;
        const uint32_t bVh = sbase + A_KV + kvOff + A_VH + offB;
        const int* tks = tks2[it & 1];

        // ---- S = Qh.Kh + Qh.Kl ----
        float sacc[8][4];
#pragma unroll
        for (int j = 0; j < 8; j++)
#pragma unroll
            for (int e = 0; e < 4; e++) sacc[j][e] = 0.0f;

#pragma unroll
        for (int pass = 0; pass < 2; pass++) {
            const uint32_t bBase = (pass == 1) ? bKl : bKh;
#pragma unroll
            for (int kc = 0; kc < 4; kc++) {
                uint32_t aq[4];
                LDSM_X4(aq[0], aq[1], aq[2], aq[3], aQh + (uint32_t)(kc * 32));
#pragma unroll
                for (int g = 0; g < 4; g++) {
                    uint32_t t0, t1, t2, t3;
                    LDSM_X4(t0, t1, t2, t3, bBase + (uint32_t)(g * 16 * ARS + kc * 32));
                    MMA_FP16(sacc[2 * g], aq, t0, t1);
                    MMA_FP16(sacc[2 * g + 1], aq, t2, t3);
                }
            }
        }

        // ---- bias + tile max ----
        float tmax0 = -1e30f, tmax1 = -1e30f;
#pragma unroll
        for (int j = 0; j < 8; j++) {
            const int c0 = 8 * j + 2 * (lane & 3);
            const float tk0 = (float)tks[c0];
            const float tk1 = (float)tks[c0 + 1];
            sacc[j][0] -= a_h * fmaxf(tq0 - tk0, 0.0f);
            sacc[j][1] -= a_h * fmaxf(tq0 - tk1, 0.0f);
            sacc[j][2] -= a_h * fmaxf(tq1 - tk0, 0.0f);
            sacc[j][3] -= a_h * fmaxf(tq1 - tk1, 0.0f);
            tmax0 = fmaxf(tmax0, fmaxf(sacc[j][0], sacc[j][1]));
            tmax1 = fmaxf(tmax1, fmaxf(sacc[j][2], sacc[j][3]));
        }
        tmax0 = fmaxf(tmax0, __shfl_xor_sync(0xFFFFFFFF, tmax0, 1));
        tmax0 = fmaxf(tmax0, __shfl_xor_sync(0xFFFFFFFF, tmax0, 2));
        tmax1 = fmaxf(tmax1, __shfl_xor_sync(0xFFFFFFFF, tmax1, 1));
        tmax1 = fmaxf(tmax1, __shfl_xor_sync(0xFFFFFFFF, tmax1, 2));

        const float mn0 = fmaxf(m0, tmax0);
        const float mn1 = fmaxf(m1, tmax1);
        const float sc0 = __expf(m0 - mn0);
        const float sc1 = __expf(m1 - mn1);
        m0 = mn0; m1 = mn1;
        lsum0 *= sc0; lsum1 *= sc1;
#pragma unroll
        for (int j = 0; j < 8; j++) {
            ctxacc[j][0] *= sc0; ctxacc[j][1] *= sc0;
            ctxacc[j][2] *= sc1; ctxacc[j][3] *= sc1;
        }

        // ---- exp + mask + pack P ----
        uint32_t pa[4][4];
#pragma unroll
        for (int j = 0; j < 8; j++) {
            const int c0 = 8 * j + 2 * (lane & 3);
            float p0 = __expf(sacc[j][0] - m0);
            float p1 = __expf(sacc[j][1] - m0);
            float p2 = __expf(sacc[j][2] - m1);
            float p3 = __expf(sacc[j][3] - m1);
            if (tileMasked) {
                const unsigned char* mr0 = &mask[(bn0 + row_lo) * Nn + k0 + c0];
                const unsigned char* mr1 = &mask[(bn0 + row_hi) * Nn + k0 + c0];
                p0 = mr0[0] ? 0.0f : p0;
                p1 = mr0[1] ? 0.0f : p1;
                p2 = mr1[0] ? 0.0f : p2;
                p3 = mr1[1] ? 0.0f : p3;
            }
            const __half2 lo_h = __float22half2_rn(make_float2(p0, p1));
            const __half2 hi_h = __float22half2_rn(make_float2(p2, p3));
            const float2 lo_r = __half22float2(lo_h);
            const float2 hi_r = __half22float2(hi_h);
            lsum0 += lo_r.x + lo_r.y;
            lsum1 += hi_r.x + hi_r.y;
            pa[j >> 1][(j & 1) * 2 + 0] = h2_as_u32(lo_h);
            pa[j >> 1][(j & 1) * 2 + 1] = h2_as_u32(hi_h);
        }

        // ---- ctx += P x Vh ----
#pragma unroll
        for (int kc = 0; kc < 4; kc++) {
#pragma unroll
            for (int g = 0; g < 4; g++) {
                uint32_t t0, t1, t2, t3;
                LDSM_X4(t0, t1, t2, t3, bVh + (uint32_t)(g * 16 * ARS + kc * 32));
                MMA_FP16(ctxacc[2 * g], pa[kc], t0, t1);
                MMA_FP16(ctxacc[2 * g + 1], pa[kc], t2, t3);
            }
        }
        __syncthreads();
    }

    lsum0 += __shfl_xor_sync(0xFFFFFFFF, lsum0, 1);
    lsum0 += __shfl_xor_sync(0xFFFFFFFF, lsum0, 2);
    lsum1 += __shfl_xor_sync(0xFFFFFFFF, lsum1, 1);
    lsum1 += __shfl_xor_sync(0xFFFFFFFF, lsum1, 2);
    const float inv0 = (lsum0 > 0.0f) ? (1.0f / lsum0) : 0.0f;
    const float inv1 = (lsum1 > 0.0f) ? (1.0f / lsum1) : 0.0f;

#pragma unroll
    for (int j = 0; j < 8; j++) {
        const int c0 = h * HD + 8 * j + 2 * (lane & 3);
        const float o0 = ctxacc[j][0] * inv0, o1 = ctxacc[j][1] * inv0;
        const float o2 = ctxacc[j][2] * inv1, o3 = ctxacc[j][3] * inv1;
        __nv_bfloat16 h0 = __float2bfloat16_rn(o0), h1 = __float2bfloat16_rn(o1);
        __nv_bfloat16 h2 = __float2bfloat16_rn(o2), h3 = __float2bfloat16_rn(o3);
        __nv_bfloat162 hl; hl.x = h0; hl.y = h1;
        __nv_bfloat162 hh; hh.x = h2; hh.y = h3;
        __nv_bfloat162 ll; ll.x = __float2bfloat16_rn(o0 - __bfloat162float(h0));
        ll.y = __float2bfloat16_rn(o1 - __bfloat162float(h1));
        __nv_bfloat162 lh; lh.x = __float2bfloat16_rn(o2 - __bfloat162float(h2));
        lh.y = __float2bfloat16_rn(o3 - __bfloat162float(h3));
        *reinterpret_cast<__nv_bfloat162*>(&ctxh[(bn0 + row_lo) * Dd + c0]) = hl;
        *reinterpret_cast<__nv_bfloat162*>(&ctxh[(bn0 + row_hi) * Dd + c0]) = hh;
        *reinterpret_cast<__nv_bfloat162*>(&ctxl[(bn0 + row_lo) * Dd + c0]) = ll;
        *reinterpret_cast<__nv_bfloat162*>(&ctxl[(bn0 + row_hi) * Dd + c0]) = lh;
    }
}

// ---------------------------------------------------------------------------
extern "C" void kernel_launch(void* const* d_in, const int* in_sizes, int n_in,
                              void* d_out, int out_size) {
    const float*         X     = (const float*)d_in[0];
    const int*           t_idx = (const int*)d_in[1];
    const unsigned char* mask  = (const unsigned char*)d_in[2];
    const float*         Wqkv  = (const float*)d_in[3];
    const float*         bqkv  = (const float*)d_in[4];
    const float*         Wo    = (const float*)d_in[5];
    const float*         bo    = (const float*)d_in[6];
    const float*         alpha = (const float*)d_in[7];
    float*               out   = (float*)d_out;

    void *qkv_p, *xh_p, *xl_p, *wqh_p, *wql_p, *woh_p, *wol_p, *ctxh_p, *ctxl_p;
    void *qh_p, *kh_p, *kl_p, *vh_p;
    cudaGetSymbolAddress(&qkv_p, g_qkv);
    cudaGetSymbolAddress(&xh_p, g_xh);   cudaGetSymbolAddress(&xl_p, g_xl);
    cudaGetSymbolAddress(&wqh_p, g_wqh); cudaGetSymbolAddress(&wql_p, g_wql);
    cudaGetSymbolAddress(&woh_p, g_woh); cudaGetSymbolAddress(&wol_p, g_wol);
    cudaGetSymbolAddress(&ctxh_p, g_ctxh); cudaGetSymbolAddress(&ctxl_p, g_ctxl);
    cudaGetSymbolAddress(&qh_p, g_q16h);
    cudaGetSymbolAddress(&kh_p, g_k16h); cudaGetSymbolAddress(&kl_p, g_k16l);
    cudaGetSymbolAddress(&vh_p, g_v16h);

    cudaFuncSetAttribute(gemm_sp, cudaFuncAttributeMaxDynamicSharedMemorySize, G_SMEM);
    cudaFuncSetAttribute(attn_tc, cudaFuncAttributeMaxDynamicSharedMemorySize, A_SMEM);

    // prep1: split X, Wqkv, Wo
    split_bf16<<<(BN_ROWS * Dd / 4 + 255) / 256, 256>>>(
        X, (__nv_bfloat16*)xh_p, (__nv_bfloat16*)xl_p, BN_ROWS * Dd / 4);
    split_bf16<<<(QKV_COLS * Dd / 4 + 255) / 256, 256>>>(
        Wqkv, (__nv_bfloat16*)wqh_p, (__nv_bfloat16*)wql_p, QKV_COLS * Dd / 4);
    split_bf16<<<(Dd * Dd / 4 + 255) / 256, 256>>>(
        Wo, (__nv_bfloat16*)woh_p, (__nv_bfloat16*)wol_p, Dd * Dd / 4);

    // 1) QKV projection
    {
        dim3 grid(QKV_COLS / 128, BN_ROWS / 128);
        gemm_sp<<<grid, 256, G_SMEM>>>((__nv_bfloat16*)xh_p, (__nv_bfloat16*)xl_p,
                                       (__nv_bfloat16*)wqh_p, (__nv_bfloat16*)wql_p,
                                       bqkv, (float*)qkv_p, QKV_COLS, Dd);
    }

    // prep2: per-head fp16 (Qh, Kh+Kl, Vh transposed)
    {
        dim3 grid(Nn / 64, NH);
        attn_prep<<<grid, 128>>>((const float*)qkv_p,
                                 (__half*)qh_p,
                                 (__half*)kh_p, (__half*)kl_p,
                                 (__half*)vh_p);
    }

    // 2) Tensor-core flash attention -> ctx (bf16 hi/lo)
    {
        dim3 grid(Nn / 64, Hh, Bb);
        attn_tc<<<grid, 128, A_SMEM>>>((const __half*)qh_p,
                                       (const __half*)kh_p, (const __half*)kl_p,
                                       (const __half*)vh_p,
                                       t_idx, mask, alpha,
                                       (__nv_bfloat16*)ctxh_p, (__nv_bfloat16*)ctxl_p);
    }

    // 3) Output projection
    {
        dim3 grid(Dd / 128, BN_ROWS / 128);
        gemm_sp<<<grid, 256, G_SMEM>>>((__nv_bfloat16*)ctxh_p, (__nv_bfloat16*)ctxl_p,
                                       (__nv_bfloat16*)woh_p, (__nv_bfloat16*)wol_p,
                                       bo, out, Dd, Dd);
    }
}